// round 10
// baseline (speedup 1.0000x reference)
#include <cuda_runtime.h>
#include <cuda_bf16.h>
#include <cstdint>

#define NNODES 20000
#define NEDGES 320000
#define FNODE  64
#define FEDGE  16
#define HIDN   300
#define NGRAPH 128

typedef unsigned long long ull;

// ---------------- scratch (device globals) ----------------
__device__ float g_h0[NEDGES * HIDN];
__device__ float g_hA[NEDGES * HIDN];          // t ping
__device__ float g_hB[NEDGES * HIDN];          // t pong
__device__ __nv_bfloat16 g_Ah[NEDGES * 320];   // A operand hi (current layer)
__device__ __nv_bfloat16 g_Al[NEDGES * 320];   // A operand lo
__device__ float g_a [NNODES * HIDN];          // u2
__device__ float g_s [NNODES * HIDN];          // final node message
__device__ float g_pool[NGRAPH * HIDN];
__device__ __nv_bfloat16 g_Wh [3 * 384 * 320]; // conv W^T hi [l][n][k], zero-pad
__device__ __nv_bfloat16 g_Wl [3 * 384 * 320];
__device__ __nv_bfloat16 g_WIh[384 * 320];     // init W^T hi
__device__ __nv_bfloat16 g_WIl[384 * 320];
__device__ __nv_bfloat16 g_WNh[384 * 384];     // e2n W^T hi [n][k]
__device__ __nv_bfloat16 g_WNl[384 * 384];
__device__ int g_cnt [NNODES];
__device__ int g_ptr [NNODES + 1];
__device__ int g_fill[NNODES];
__device__ int g_eid [NEDGES];

__device__ __forceinline__ float* hbuf(int s) {
    return (s == 0) ? g_h0 : ((s == 1) ? g_hA : g_hB);
}

// ---------------- helpers ----------------
__device__ __forceinline__ float4 ld4(const float* p) { return *reinterpret_cast<const float4*>(p); }
__device__ __forceinline__ void   st4(float* p, float4 v) { *reinterpret_cast<float4*>(p) = v; }
__device__ __forceinline__ float  frelu(float x) { return x > 0.f ? x : 0.f; }

__device__ __forceinline__ uint32_t smem_u32(const void* p) {
    uint32_t a;
    asm("{ .reg .u64 t; cvta.to.shared.u64 t, %1; cvt.u32.u64 %0, t; }" : "=r"(a) : "l"(p));
    return a;
}
__device__ __forceinline__ uint32_t sw128(uint32_t o) { return o ^ ((o >> 3) & 0x70); }

__device__ __forceinline__ void ldsm4(uint32_t* r, uint32_t a) {
    asm volatile("ldmatrix.sync.aligned.m8n8.x4.shared.b16 {%0,%1,%2,%3}, [%4];"
                 : "=r"(r[0]), "=r"(r[1]), "=r"(r[2]), "=r"(r[3]) : "r"(a));
}
__device__ __forceinline__ void mma_bf(float* d, const uint32_t* a, const uint32_t* b) {
    asm volatile("mma.sync.aligned.m16n8k16.row.col.f32.bf16.bf16.f32 "
                 "{%0,%1,%2,%3}, {%4,%5,%6,%7}, {%8,%9}, {%0,%1,%2,%3};"
                 : "+f"(d[0]), "+f"(d[1]), "+f"(d[2]), "+f"(d[3])
                 : "r"(a[0]), "r"(a[1]), "r"(a[2]), "r"(a[3]), "r"(b[0]), "r"(b[1]));
}
#define CPA16(dst, src) asm volatile("cp.async.cg.shared.global [%0], [%1], 16;" :: "r"(dst), "l"(src))
#define CPA_COMMIT()    asm volatile("cp.async.commit_group;" ::: "memory")
#define CPA_WAIT0()     asm volatile("cp.async.wait_group 0;" ::: "memory")
#define CPA_WAIT1()     asm volatile("cp.async.wait_group 1;" ::: "memory")

__device__ __forceinline__ void split_pack(float v0, float v1, uint32_t& hi, uint32_t& lo) {
    __nv_bfloat162 h, l;
    h.x = __float2bfloat16(v0); h.y = __float2bfloat16(v1);
    l.x = __float2bfloat16(v0 - __bfloat162float(h.x));
    l.y = __float2bfloat16(v1 - __bfloat162float(h.y));
    hi = *reinterpret_cast<uint32_t*>(&h);
    lo = *reinterpret_cast<uint32_t*>(&l);
}

// ---------------- preprocessing ----------------
__global__ void k_pre(const float* __restrict__ Wc, const float* __restrict__ Wi,
                      const float* __restrict__ We) {
    int t = blockIdx.x * blockDim.x + threadIdx.x;
    if (t < NNODES) g_cnt[t] = 0;
    if (t < NGRAPH * HIDN) g_pool[t] = 0.f;
    if (t < 122880) {
        int n = t / 320, k = t % 320;
        float v = (n < HIDN && k < 80) ? Wi[k * HIDN + n] : 0.f;
        __nv_bfloat16 bh = __float2bfloat16(v);
        g_WIh[t] = bh;
        g_WIl[t] = __float2bfloat16(v - __bfloat162float(bh));
    }
    if (t < 3 * 122880) {
        int l = t / 122880, r2 = t % 122880;
        int n = r2 / 320, k = r2 % 320;
        float v = (n < HIDN && k < HIDN) ? Wc[l * HIDN * HIDN + k * HIDN + n] : 0.f;
        __nv_bfloat16 bh = __float2bfloat16(v);
        g_Wh[t] = bh;
        g_Wl[t] = __float2bfloat16(v - __bfloat162float(bh));
    }
    if (t < 384 * 384) {
        int n = t / 384, k = t % 384;
        float v = (n < HIDN && k < FNODE + HIDN) ? We[k * HIDN + n] : 0.f;
        __nv_bfloat16 bh = __float2bfloat16(v);
        g_WNh[t] = bh;
        g_WNl[t] = __float2bfloat16(v - __bfloat162float(bh));
    }
}

__global__ void k_hist(const int* __restrict__ coli) {
    int e = blockIdx.x * blockDim.x + threadIdx.x;
    if (e < NEDGES) atomicAdd(&g_cnt[coli[e]], 1);
}

__global__ void k_scan() {
    __shared__ int sh[1024];
    int tid = threadIdx.x;
    int carry = 0;
    const int CH = (NNODES + 1023) / 1024;
    for (int c = 0; c < CH; ++c) {
        int i = c * 1024 + tid;
        int v = (i < NNODES) ? g_cnt[i] : 0;
        sh[tid] = v;
        __syncthreads();
        for (int off = 1; off < 1024; off <<= 1) {
            int t = (tid >= off) ? sh[tid - off] : 0;
            __syncthreads();
            sh[tid] += t;
            __syncthreads();
        }
        int inc = sh[tid];
        int total = sh[1023];
        if (i < NNODES) {
            int ex = carry + inc - v;
            g_ptr[i]  = ex;
            g_fill[i] = ex;
        }
        carry += total;
        __syncthreads();
    }
    if (tid == 0) g_ptr[NNODES] = carry;
}

__global__ void k_scatter(const int* __restrict__ coli) {
    int e = blockIdx.x * blockDim.x + threadIdx.x;
    if (e < NEDGES) {
        int pos = atomicAdd(&g_fill[coli[e]], 1);
        g_eid[pos] = e;
    }
}

// ---------------- segment sum: g_a[n] = sum t[e] (u2 only) ----------------
__global__ void k_segsum(int src_sel) {
    const float* h = hbuf(src_sel);
    int t = blockIdx.x * blockDim.x + threadIdx.x;
    if (t >= NNODES * 75) return;
    int n = t / 75;
    int c = (t - n * 75) * 4;
    int beg = g_ptr[n], end = g_ptr[n + 1];
    float4 acc = make_float4(0.f, 0.f, 0.f, 0.f);
#pragma unroll 2
    for (int i = beg; i < end; ++i) {
        int e = g_eid[i];
        float4 vv = ld4(h + e * HIDN + c);
        acc.x += vv.x; acc.y += vv.y; acc.z += vv.z; acc.w += vv.w;
    }
    st4(g_a + n * HIDN + c, acc);
}

// ------ fused segsum + next-h materialize (paired-edge identity) --------
__global__ void k_seghm(int t_sel, const float* __restrict__ bc) {
    const float* tp = hbuf(t_sel);
    int t = blockIdx.x * blockDim.x + threadIdx.x;
    if (t >= NNODES * 75) return;
    int n = t / 75;
    int c = (t - n * 75) * 4;
    float4 bv = ld4(bc + c);
    int beg = g_ptr[n], end = g_ptr[n + 1];
    float4 u = make_float4(0.f, 0.f, 0.f, 0.f);
#pragma unroll 2
    for (int i = beg; i < end; ++i) {
        int e = g_eid[i];
        float4 vv = ld4(tp + e * HIDN + c);
        u.x += vv.x; u.y += vv.y; u.z += vv.z; u.w += vv.w;
    }
    for (int i = beg; i < end; ++i) {
        int e = g_eid[i];
        int er = e ^ 1;
        float4 tv  = ld4(tp + e * HIDN + c);
        float4 h0v = ld4(g_h0 + er * HIDN + c);
        float4 v;
        v.x = frelu(h0v.x + bv.x + u.x - tv.x);
        v.y = frelu(h0v.y + bv.y + u.y - tv.y);
        v.z = frelu(h0v.z + bv.z + u.z - tv.z);
        v.w = frelu(h0v.w + bv.w + u.w - tv.w);
        uint32_t h0w, l0w, h1w, l1w;
        split_pack(v.x, v.y, h0w, l0w);
        split_pack(v.z, v.w, h1w, l1w);
        *reinterpret_cast<uint2*>(g_Ah + (size_t)er * 320 + c) = make_uint2(h0w, h1w);
        *reinterpret_cast<uint2*>(g_Al + (size_t)er * 320 + c) = make_uint2(l0w, l1w);
    }
}

// --------- fused final: g_s[n] = sum_e relu(h0[e]+bc2+u2[row[e]]-rev(t2)) ----
__global__ void k_segsum_h3(int t2_sel, const float* __restrict__ bc2,
                            const int* __restrict__ rowi) {
    const float* t2 = hbuf(t2_sel);
    int t = blockIdx.x * blockDim.x + threadIdx.x;
    if (t >= NNODES * 75) return;
    int n = t / 75;
    int c = (t - n * 75) * 4;
    float4 bv = ld4(bc2 + c);
    int beg = g_ptr[n], end = g_ptr[n + 1];
    float4 acc = make_float4(0.f, 0.f, 0.f, 0.f);
#pragma unroll 2
    for (int i = beg; i < end; ++i) {
        int e = g_eid[i];
        float4 h0v = ld4(g_h0 + e * HIDN + c);
        float4 uv  = ld4(g_a + rowi[e] * HIDN + c);
        float4 tv  = ld4(t2 + (e ^ 1) * HIDN + c);
        acc.x += frelu(h0v.x + bv.x + uv.x - tv.x);
        acc.y += frelu(h0v.y + bv.y + uv.y - tv.y);
        acc.z += frelu(h0v.z + bv.z + uv.z - tv.z);
        acc.w += frelu(h0v.w + bv.w + uv.w - tv.w);
    }
    st4(g_s + n * HIDN + c, acc);
}

// =====================================================================
// Conv GEMM, 1 CTA/SM: full-B preload (5 chunks, 160KB) + A 2-stage
// double buffer (64KB). CTA 128m x 128n, 8 warps (4m x 2n), K=320.
// 3-pass bf16 split, fp32 acc. wait_group sees A groups only.
// =====================================================================
#define CB_AH 0                 // 2 stages x 16384
#define CB_AL 32768             // 2 stages x 16384
#define CB_BH 65536             // 5 chunks x 16384 = 81920
#define CB_BL 147456            // 81920
#define CB_TOTAL 229376

__global__ void __launch_bounds__(256, 1) k_cgemm(int layer, int out_sel) {
    extern __shared__ char smem[];
    uint32_t sb = smem_u32(smem);
    int tid = threadIdx.x;
    int lane = tid & 31;
    int wid = tid >> 5;
    int m0 = blockIdx.y * 128;
    int n0 = blockIdx.x * 128;

    const __nv_bfloat16* Wh = g_Wh + layer * 122880;
    const __nv_bfloat16* Wl = g_Wl + layer * 122880;
    float* tout = hbuf(out_sel);

    int wm = wid >> 1, wn = wid & 1;
    int mat = lane >> 3, l7 = lane & 7;
    int a_row = wm * 32 + (mat & 1) * 8 + l7;
    int a_kof = (mat >> 1) * 8;
    int b_base = wn * 64 + (mat >> 1) * 8 + l7;
    int b_kof = (mat & 1) * 8;
    bool nact = (n0 + wn * 64) < HIDN;

    // precomputed ldsm swizzle offsets (loop-invariant)
    uint32_t a_soff[2][4], b_soff[4][4];
#pragma unroll
    for (int mt = 0; mt < 2; ++mt)
#pragma unroll
        for (int ks = 0; ks < 4; ++ks)
            a_soff[mt][ks] = sw128((uint32_t)(((a_row + mt * 16) << 7) +
                                              ((ks * 16 + a_kof) << 1)));
#pragma unroll
    for (int np = 0; np < 4; ++np)
#pragma unroll
        for (int ks = 0; ks < 4; ++ks)
            b_soff[np][ks] = sw128((uint32_t)(((b_base + np * 16) << 7) +
                                              ((ks * 16 + b_kof) << 1)));

    // ---- group 0: full B preload (5 chunks, hi+lo) ----
    for (int j = tid; j < 5120; j += 256) {
        int c = j >> 10, r2 = (j >> 3) & 127, i = j & 7;
        uint32_t off = c * 16384 + sw128((uint32_t)(r2 * 128 + i * 16));
        CPA16(sb + CB_BH + off, Wh + (size_t)(n0 + r2) * 320 + c * 64 + i * 8);
        CPA16(sb + CB_BL + off, Wl + (size_t)(n0 + r2) * 320 + c * 64 + i * 8);
    }
    CPA_COMMIT();

#define CA_LOAD(KC)                                                            \
    {                                                                          \
        uint32_t stg = ((KC) & 1) * 16384;                                     \
        _Pragma("unroll")                                                      \
        for (int s = 0; s < 4; s++) {                                          \
            int j = tid + s * 256;                                             \
            int r2 = j >> 3, i = j & 7;                                        \
            uint32_t off = stg + sw128((uint32_t)(r2 * 128 + i * 16));         \
            CPA16(sb + CB_AH + off, g_Ah + (size_t)(m0 + r2) * 320 + (KC) * 64 + i * 8); \
            CPA16(sb + CB_AL + off, g_Al + (size_t)(m0 + r2) * 320 + (KC) * 64 + i * 8); \
        }                                                                      \
        CPA_COMMIT();                                                          \
    }

    CA_LOAD(0)
    CA_LOAD(1)

    float acc[2][8][4];
#pragma unroll
    for (int i = 0; i < 2; i++)
#pragma unroll
        for (int j = 0; j < 8; j++)
#pragma unroll
            for (int q = 0; q < 4; q++) acc[i][j][q] = 0.f;

    for (int kc = 0; kc < 5; ++kc) {
        if (kc < 4) { CPA_WAIT1(); } else { CPA_WAIT0(); }
        __syncthreads();
        uint32_t ast = ((uint32_t)kc & 1) * 16384;
        uint32_t bst = (uint32_t)kc * 16384;
#pragma unroll
        for (int ks = 0; ks < 4; ++ks) {
            uint32_t ah[2][4], al[2][4];
#pragma unroll
            for (int mt = 0; mt < 2; ++mt) {
                ldsm4(ah[mt], sb + CB_AH + ast + a_soff[mt][ks]);
                ldsm4(al[mt], sb + CB_AL + ast + a_soff[mt][ks]);
            }
            if (nact) {
#pragma unroll
                for (int np = 0; np < 4; ++np) {
                    uint32_t bh[4], bl[4];
                    ldsm4(bh, sb + CB_BH + bst + b_soff[np][ks]);
                    ldsm4(bl, sb + CB_BL + bst + b_soff[np][ks]);
#pragma unroll
                    for (int mt = 0; mt < 2; ++mt)
#pragma unroll
                        for (int h = 0; h < 2; ++h) {
                            float* d = acc[mt][np * 2 + h];
                            mma_bf(d, ah[mt], bh + h * 2);
                            mma_bf(d, ah[mt], bl + h * 2);
                            mma_bf(d, al[mt], bh + h * 2);
                        }
                }
            }
        }
        __syncthreads();
        if (kc + 2 < 5) CA_LOAD(kc + 2)
    }
#undef CA_LOAD

    int orow = m0 + wm * 32 + (lane >> 2);
    int oc0  = n0 + wn * 64 + (lane & 3) * 2;
#pragma unroll
    for (int mt = 0; mt < 2; ++mt)
#pragma unroll
        for (int nt = 0; nt < 8; ++nt) {
            int col = oc0 + nt * 8;
            if (col >= HIDN) continue;
#pragma unroll
            for (int h = 0; h < 2; ++h) {
                int row = orow + mt * 16 + h * 8;
                *reinterpret_cast<float2*>(tout + row * HIDN + col) =
                    make_float2(acc[mt][nt][h * 2], acc[mt][nt][h * 2 + 1]);
            }
        }
}

// =====================================================================
// Init GEMM: A = [x[row]|ea] (K=80 -> 2 chunks), epilogue h0 fp32 + bf16 split
// =====================================================================
#define TG_A_HI 0
#define TG_A_LO 16384
#define TG_B_HI 32768
#define TG_B_LO 49152
#define TG_TOTAL 65536

__global__ void __launch_bounds__(256, 2) k_tginit(
    const int* __restrict__ rowi, const float* __restrict__ bvec,
    const float* __restrict__ x, const float* __restrict__ ea)
{
    extern __shared__ char smem[];
    uint32_t sb = smem_u32(smem);
    int tid = threadIdx.x;
    int lane = tid & 31;
    int wid = tid >> 5;
    int m0 = blockIdx.y * 128;
    int n0 = blockIdx.x * 128;

    int r = tid >> 1;
    int e = m0 + r;
    int cc0 = (tid & 1) * 32;
    int rv = rowi[e];

    int wm = wid >> 1, wn = wid & 1;
    int mat = lane >> 3, l7 = lane & 7;
    int a_row = wm * 32 + (mat & 1) * 8 + l7;
    int a_kof = (mat >> 1) * 8;
    int b_base = wn * 64 + (mat >> 1) * 8 + l7;
    int b_kof = (mat & 1) * 8;
    bool nact = (n0 + wn * 64) < HIDN;

    float acc[2][8][4];
#pragma unroll
    for (int i = 0; i < 2; i++)
#pragma unroll
        for (int j = 0; j < 8; j++)
#pragma unroll
            for (int q = 0; q < 4; q++) acc[i][j][q] = 0.f;

    for (int kc = 0; kc < 2; ++kc) {
        int k0 = kc * 64;
        if (kc) __syncthreads();
#pragma unroll
        for (int s = 0; s < 4; s++) {
            int j = tid + s * 256;
            int n = j >> 3, i = j & 7;
            uint32_t off = sw128((uint32_t)(n * 128 + i * 16));
            CPA16(sb + TG_B_HI + off, g_WIh + (n0 + n) * 320 + k0 + i * 8);
            CPA16(sb + TG_B_LO + off, g_WIl + (n0 + n) * 320 + k0 + i * 8);
        }
        CPA_COMMIT();
#pragma unroll
        for (int i = 0; i < 8; i++) {
            int cc = cc0 + i * 4;
            int k = k0 + cc;
            float4 v = make_float4(0.f, 0.f, 0.f, 0.f);
            if (k < FNODE)    v = ld4(x + rv * FNODE + k);
            else if (k < 80)  v = ld4(ea + e * FEDGE + (k - FNODE));
            uint32_t h0w, l0w, h1w, l1w;
            split_pack(v.x, v.y, h0w, l0w);
            split_pack(v.z, v.w, h1w, l1w);
            uint32_t off = sw128((uint32_t)(r * 128 + cc * 2));
            *reinterpret_cast<uint2*>(smem + TG_A_HI + off) = make_uint2(h0w, h1w);
            *reinterpret_cast<uint2*>(smem + TG_A_LO + off) = make_uint2(l0w, l1w);
        }
        CPA_WAIT0();
        __syncthreads();
#pragma unroll
        for (int ks = 0; ks < 4; ++ks) {
            uint32_t ah[2][4], al[2][4];
#pragma unroll
            for (int mt = 0; mt < 2; ++mt) {
                uint32_t off = sw128((uint32_t)(((a_row + mt * 16) << 7) +
                                                ((ks * 16 + a_kof) << 1)));
                ldsm4(ah[mt], sb + TG_A_HI + off);
                ldsm4(al[mt], sb + TG_A_LO + off);
            }
            if (nact) {
#pragma unroll
                for (int np = 0; np < 4; ++np) {
                    uint32_t boff = sw128((uint32_t)(((b_base + np * 16) << 7) +
                                                     ((ks * 16 + b_kof) << 1)));
                    uint32_t bh[4], bl[4];
                    ldsm4(bh, sb + TG_B_HI + boff);
                    ldsm4(bl, sb + TG_B_LO + boff);
#pragma unroll
                    for (int mt = 0; mt < 2; ++mt)
#pragma unroll
                        for (int h = 0; h < 2; ++h) {
                            float* d = acc[mt][np * 2 + h];
                            mma_bf(d, ah[mt], bh + h * 2);
                            mma_bf(d, ah[mt], bl + h * 2);
                            mma_bf(d, al[mt], bh + h * 2);
                        }
                }
            }
        }
    }

    int orow = m0 + wm * 32 + (lane >> 2);
    int oc0  = n0 + wn * 64 + (lane & 3) * 2;
#pragma unroll
    for (int mt = 0; mt < 2; ++mt)
#pragma unroll
        for (int nt = 0; nt < 8; ++nt) {
            int col = oc0 + nt * 8;
            if (col >= 320) continue;
            bool live = col < HIDN;
            float b0 = live ? bvec[col] : 0.f;
            float b1 = live ? bvec[col + 1] : 0.f;
#pragma unroll
            for (int h = 0; h < 2; ++h) {
                int row = orow + mt * 16 + h * 8;
                float v0 = live ? frelu(acc[mt][nt][h * 2] + b0) : 0.f;
                float v1 = live ? frelu(acc[mt][nt][h * 2 + 1] + b1) : 0.f;
                if (live)
                    *reinterpret_cast<float2*>(g_h0 + row * HIDN + col) = make_float2(v0, v1);
                uint32_t hw, lw;
                split_pack(v0, v1, hw, lw);
                *reinterpret_cast<uint32_t*>(g_Ah + (size_t)row * 320 + col) = hw;
                *reinterpret_cast<uint32_t*>(g_Al + (size_t)row * 320 + col) = lw;
            }
        }
}

// =====================================================================
// Node GEMM (tensor): hn = relu([x|s] @ W_e2n + be); pool += hn
// =====================================================================
__global__ void __launch_bounds__(256, 2) k_tgnode(
    const int* __restrict__ batch, const float* __restrict__ bvec,
    const float* __restrict__ x)
{
    extern __shared__ char smem[];
    uint32_t sb = smem_u32(smem);
    int tid = threadIdx.x;
    int lane = tid & 31;
    int wid = tid >> 5;
    int m0 = blockIdx.y * 128;
    int n0 = blockIdx.x * 128;

    int r = tid >> 1;
    int e = m0 + r;
    bool eok = (e < NNODES);
    int es = eok ? e : 0;
    int cc0 = (tid & 1) * 32;

    int wm = wid >> 1, wn = wid & 1;
    int mat = lane >> 3, l7 = lane & 7;
    int a_row = wm * 32 + (mat & 1) * 8 + l7;
    int a_kof = (mat >> 1) * 8;
    int b_base = wn * 64 + (mat >> 1) * 8 + l7;
    int b_kof = (mat & 1) * 8;
    bool nact = (n0 + wn * 64) < HIDN;

    const int KTOT = FNODE + HIDN;  // 364

    float acc[2][8][4];
#pragma unroll
    for (int i = 0; i < 2; i++)
#pragma unroll
        for (int j = 0; j < 8; j++)
#pragma unroll
            for (int q = 0; q < 4; q++) acc[i][j][q] = 0.f;

    for (int kc = 0; kc < 6; ++kc) {
        int k0 = kc * 64;
        if (kc) __syncthreads();
#pragma unroll
        for (int s = 0; s < 4; s++) {
            int j = tid + s * 256;
            int n = j >> 3, i = j & 7;
            uint32_t off = sw128((uint32_t)(n * 128 + i * 16));
            CPA16(sb + TG_B_HI + off, g_WNh + (n0 + n) * 384 + k0 + i * 8);
            CPA16(sb + TG_B_LO + off, g_WNl + (n0 + n) * 384 + k0 + i * 8);
        }
        CPA_COMMIT();
#pragma unroll
        for (int i = 0; i < 8; i++) {
            int cc = cc0 + i * 4;
            int k = k0 + cc;
            float4 v = make_float4(0.f, 0.f, 0.f, 0.f);
            if (eok && k < KTOT)
                v = (k < FNODE) ? ld4(x + es * FNODE + k)
                                : ld4(g_s + es * HIDN + (k - FNODE));
            uint32_t h0w, l0w, h1w, l1w;
            split_pack(v.x, v.y, h0w, l0w);
            split_pack(v.z, v.w, h1w, l1w);
            uint32_t off = sw128((uint32_t)(r * 128 + cc * 2));
            *reinterpret_cast<uint2*>(smem + TG_A_HI + off) = make_uint2(h0w, h1w);
            *reinterpret_cast<uint2*>(smem + TG_A_LO + off) = make_uint2(l0w, l1w);
        }
        CPA_WAIT0();
        __syncthreads();
#pragma unroll
        for (int ks = 0; ks < 4; ++ks) {
            uint32_t ah[2][4], al[2][4];
#pragma unroll
            for (int mt = 0; mt < 2; ++mt) {
                uint32_t off = sw128((uint32_t)(((a_row + mt * 16) << 7) +
                                                ((ks * 16 + a_kof) << 1)));
                ldsm4(ah[mt], sb + TG_A_HI + off);
                ldsm4(al[mt], sb + TG_A_LO + off);
            }
            if (nact) {
#pragma unroll
                for (int np = 0; np < 4; ++np) {
                    uint32_t boff = sw128((uint32_t)(((b_base + np * 16) << 7) +
                                                     ((ks * 16 + b_kof) << 1)));
                    uint32_t bh[4], bl[4];
                    ldsm4(bh, sb + TG_B_HI + boff);
                    ldsm4(bl, sb + TG_B_LO + boff);
#pragma unroll
                    for (int mt = 0; mt < 2; ++mt)
#pragma unroll
                        for (int h = 0; h < 2; ++h) {
                            float* d = acc[mt][np * 2 + h];
                            mma_bf(d, ah[mt], bh + h * 2);
                            mma_bf(d, ah[mt], bl + h * 2);
                            mma_bf(d, al[mt], bh + h * 2);
                        }
                }
            }
        }
    }

    int orow = m0 + wm * 32 + (lane >> 2);
    int oc0  = n0 + wn * 64 + (lane & 3) * 2;
#pragma unroll
    for (int mt = 0; mt < 2; ++mt)
#pragma unroll
        for (int nt = 0; nt < 8; ++nt) {
            int col = oc0 + nt * 8;
            if (col >= HIDN) continue;
            float b0 = bvec[col], b1 = bvec[col + 1];
#pragma unroll
            for (int h = 0; h < 2; ++h) {
                int row = orow + mt * 16 + h * 8;
                if (row >= NNODES) continue;
                float* p = g_pool + batch[row] * HIDN + col;
                atomicAdd(p + 0, frelu(acc[mt][nt][h * 2] + b0));
                atomicAdd(p + 1, frelu(acc[mt][nt][h * 2 + 1] + b1));
            }
        }
}

// ---------------- FFN ----------------
__global__ void k_ffn(const float* __restrict__ Wf, const float* __restrict__ bf,
                      float* __restrict__ out) {
    int g = blockIdx.x;
    int lane = threadIdx.x;
    float s = 0.f;
    for (int k = lane; k < HIDN; k += 32) s += g_pool[g * HIDN + k] * Wf[k];
#pragma unroll
    for (int o = 16; o; o >>= 1) s += __shfl_xor_sync(0xffffffffu, s, o);
    if (lane == 0) out[g] = s + bf[0];
}

// ---------------- entry ----------------
extern "C" void kernel_launch(void* const* d_in, const int* in_sizes, int n_in,
                              void* d_out, int out_size) {
    const float* x     = (const float*)d_in[0];
    const float* ea    = (const float*)d_in[1];
    const int*   ei    = (const int*)d_in[2];
    const int*   rowi  = ei;
    const int*   coli  = ei + NEDGES;
    const int*   batch = (const int*)d_in[3];
    const float* Wi    = (const float*)d_in[4];
    const float* bi    = (const float*)d_in[5];
    const float* Wc    = (const float*)d_in[6];
    const float* bc    = (const float*)d_in[7];
    const float* We    = (const float*)d_in[8];
    const float* be    = (const float*)d_in[9];
    const float* Wf    = (const float*)d_in[10];
    const float* bf    = (const float*)d_in[11];
    float* out = (float*)d_out;

    cudaFuncSetAttribute(k_cgemm,  cudaFuncAttributeMaxDynamicSharedMemorySize, CB_TOTAL);
    cudaFuncSetAttribute(k_tginit, cudaFuncAttributeMaxDynamicSharedMemorySize, TG_TOTAL);
    cudaFuncSetAttribute(k_tgnode, cudaFuncAttributeMaxDynamicSharedMemorySize, TG_TOTAL);

    dim3 gT(3, NEDGES / 128);
    dim3 gN(3, (NNODES + 127) / 128);
    int ssB = (NNODES * 75 + 255) / 256;

    k_pre<<<1440, 256>>>(Wc, Wi, We);                   // 1
    k_hist<<<NEDGES / 256, 256>>>(coli);                // 2
    k_tginit<<<gT, 256, TG_TOTAL>>>(rowi, bi, x, ea);   // 3: h0 + A bf16
    k_cgemm<<<gT, 256, CB_TOTAL>>>(0, 1);               // 4: t0  <- profiled
    k_scan<<<1, 1024>>>();                              // 5
    k_scatter<<<NEDGES / 256, 256>>>(coli);             // 6

    k_seghm<<<ssB, 256>>>(1, bc);                       // u0 (regs) + A = h1 bf16
    k_cgemm<<<gT, 256, CB_TOTAL>>>(1, 2);               // t1
    k_seghm<<<ssB, 256>>>(2, bc + HIDN);                // u1 (regs) + A = h2 bf16
    k_cgemm<<<gT, 256, CB_TOTAL>>>(2, 1);               // t2
    k_segsum<<<ssB, 256>>>(1);                          // u2 -> g_a
    k_segsum_h3<<<ssB, 256>>>(1, bc + 2 * HIDN, rowi);  // s (fused h3+segsum)

    k_tgnode<<<gN, 256, TG_TOTAL>>>(batch, be, x);      // node GEMM + pool
    k_ffn<<<NGRAPH, 32>>>(Wf, bf, out);
}

// round 12
// speedup vs baseline: 1.1210x; 1.1210x over previous
#include <cuda_runtime.h>
#include <cuda_bf16.h>
#include <cstdint>

#define NNODES 20000
#define NEDGES 320000
#define FNODE  64
#define FEDGE  16
#define HIDN   300
#define NGRAPH 128

typedef unsigned long long ull;

// ---------------- scratch (device globals) ----------------
__device__ float g_h0[NEDGES * HIDN];
__device__ float g_hA[NEDGES * HIDN];          // t ping
__device__ float g_hB[NEDGES * HIDN];          // t pong
__device__ __nv_bfloat16 g_Ah[NEDGES * 320];   // A operand hi (current layer)
__device__ __nv_bfloat16 g_Al[NEDGES * 320];   // A operand lo
__device__ float g_a [NNODES * HIDN];          // u2
__device__ float g_s [NNODES * HIDN];          // final node message
__device__ float g_pool[NGRAPH * HIDN];
__device__ __nv_bfloat16 g_Wh [3 * 384 * 320]; // conv W^T hi [l][n][k], zero-pad
__device__ __nv_bfloat16 g_Wl [3 * 384 * 320];
__device__ __nv_bfloat16 g_WIh[384 * 320];     // init W^T hi
__device__ __nv_bfloat16 g_WIl[384 * 320];
__device__ __nv_bfloat16 g_WNh[384 * 384];     // e2n W^T hi [n][k]
__device__ __nv_bfloat16 g_WNl[384 * 384];
__device__ int g_cnt [NNODES];
__device__ int g_ptr [NNODES + 1];
__device__ int g_fill[NNODES];
__device__ int g_eid [NEDGES];

__device__ __forceinline__ float* hbuf(int s) {
    return (s == 0) ? g_h0 : ((s == 1) ? g_hA : g_hB);
}

// ---------------- helpers ----------------
__device__ __forceinline__ float4 ld4(const float* p) { return *reinterpret_cast<const float4*>(p); }
__device__ __forceinline__ void   st4(float* p, float4 v) { *reinterpret_cast<float4*>(p) = v; }
__device__ __forceinline__ float  frelu(float x) { return x > 0.f ? x : 0.f; }

__device__ __forceinline__ uint32_t smem_u32(const void* p) {
    uint32_t a;
    asm("{ .reg .u64 t; cvta.to.shared.u64 t, %1; cvt.u32.u64 %0, t; }" : "=r"(a) : "l"(p));
    return a;
}
__device__ __forceinline__ uint32_t sw128(uint32_t o) { return o ^ ((o >> 3) & 0x70); }

__device__ __forceinline__ void ldsm4(uint32_t* r, uint32_t a) {
    asm volatile("ldmatrix.sync.aligned.m8n8.x4.shared.b16 {%0,%1,%2,%3}, [%4];"
                 : "=r"(r[0]), "=r"(r[1]), "=r"(r[2]), "=r"(r[3]) : "r"(a));
}
__device__ __forceinline__ void mma_bf(float* d, const uint32_t* a, const uint32_t* b) {
    asm volatile("mma.sync.aligned.m16n8k16.row.col.f32.bf16.bf16.f32 "
                 "{%0,%1,%2,%3}, {%4,%5,%6,%7}, {%8,%9}, {%0,%1,%2,%3};"
                 : "+f"(d[0]), "+f"(d[1]), "+f"(d[2]), "+f"(d[3])
                 : "r"(a[0]), "r"(a[1]), "r"(a[2]), "r"(a[3]), "r"(b[0]), "r"(b[1]));
}
#define CPA16(dst, src) asm volatile("cp.async.cg.shared.global [%0], [%1], 16;" :: "r"(dst), "l"(src))
#define CPA_COMMIT()    asm volatile("cp.async.commit_group;" ::: "memory")
#define CPA_WAIT0()     asm volatile("cp.async.wait_group 0;" ::: "memory")
#define MBAR_INIT(a, c) asm volatile("mbarrier.init.shared.b64 [%0], %1;" :: "r"(a), "r"(c) : "memory")
// .noinc: do NOT bump pending count (init count already equals arriving threads)
#define CPA_MBAR_ARRIVE(a) asm volatile("cp.async.mbarrier.arrive.noinc.shared.b64 [%0];" :: "r"(a) : "memory")

__device__ __forceinline__ void mbar_wait(uint32_t mbar, uint32_t parity) {
    uint32_t done;
    asm volatile("{\n\t.reg .pred p;\n\t"
                 "mbarrier.try_wait.parity.acquire.cta.shared::cta.b64 p, [%1], %2;\n\t"
                 "selp.b32 %0, 1, 0, p;\n\t}"
                 : "=r"(done) : "r"(mbar), "r"(parity) : "memory");
    if (!done) {
        asm volatile("{\n\t.reg .pred P1;\n\t"
                     "WL_%=:\n\t"
                     "mbarrier.try_wait.parity.acquire.cta.shared::cta.b64 P1, [%0], %1, 0x989680;\n\t"
                     "@P1 bra.uni WD_%=;\n\t"
                     "bra.uni WL_%=;\n\t"
                     "WD_%=:\n\t}"
                     :: "r"(mbar), "r"(parity) : "memory");
    }
}

__device__ __forceinline__ void split_pack(float v0, float v1, uint32_t& hi, uint32_t& lo) {
    __nv_bfloat162 h, l;
    h.x = __float2bfloat16(v0); h.y = __float2bfloat16(v1);
    l.x = __float2bfloat16(v0 - __bfloat162float(h.x));
    l.y = __float2bfloat16(v1 - __bfloat162float(h.y));
    hi = *reinterpret_cast<uint32_t*>(&h);
    lo = *reinterpret_cast<uint32_t*>(&l);
}

// ---------------- preprocessing ----------------
__global__ void k_pre(const float* __restrict__ Wc, const float* __restrict__ Wi,
                      const float* __restrict__ We) {
    int t = blockIdx.x * blockDim.x + threadIdx.x;
    if (t < NNODES) g_cnt[t] = 0;
    if (t < NGRAPH * HIDN) g_pool[t] = 0.f;
    if (t < 122880) {
        int n = t / 320, k = t % 320;
        float v = (n < HIDN && k < 80) ? Wi[k * HIDN + n] : 0.f;
        __nv_bfloat16 bh = __float2bfloat16(v);
        g_WIh[t] = bh;
        g_WIl[t] = __float2bfloat16(v - __bfloat162float(bh));
    }
    if (t < 3 * 122880) {
        int l = t / 122880, r2 = t % 122880;
        int n = r2 / 320, k = r2 % 320;
        float v = (n < HIDN && k < HIDN) ? Wc[l * HIDN * HIDN + k * HIDN + n] : 0.f;
        __nv_bfloat16 bh = __float2bfloat16(v);
        g_Wh[t] = bh;
        g_Wl[t] = __float2bfloat16(v - __bfloat162float(bh));
    }
    if (t < 384 * 384) {
        int n = t / 384, k = t % 384;
        float v = (n < HIDN && k < FNODE + HIDN) ? We[k * HIDN + n] : 0.f;
        __nv_bfloat16 bh = __float2bfloat16(v);
        g_WNh[t] = bh;
        g_WNl[t] = __float2bfloat16(v - __bfloat162float(bh));
    }
}

__global__ void k_hist(const int* __restrict__ coli) {
    int e = blockIdx.x * blockDim.x + threadIdx.x;
    if (e < NEDGES) atomicAdd(&g_cnt[coli[e]], 1);
}

// fast single-block scan: 1024 threads x 20 elems, shuffle-based (3 syncs)
__global__ void k_scan() {
    __shared__ int wsum[32];
    int tid = threadIdx.x;
    int lane = tid & 31, wid = tid >> 5;
    const int PER = 20;
    int base = tid * PER;
    int v[PER];
    int s = 0;
#pragma unroll
    for (int i = 0; i < PER; ++i) {
        int idx = base + i;
        v[i] = (idx < NNODES) ? g_cnt[idx] : 0;
        s += v[i];
    }
    int ws = s;
#pragma unroll
    for (int off = 1; off < 32; off <<= 1) {
        int t = __shfl_up_sync(0xffffffffu, ws, off);
        if (lane >= off) ws += t;
    }
    if (lane == 31) wsum[wid] = ws;
    __syncthreads();
    if (wid == 0) {
        int w = wsum[lane];
#pragma unroll
        for (int off = 1; off < 32; off <<= 1) {
            int t = __shfl_up_sync(0xffffffffu, w, off);
            if (lane >= off) w += t;
        }
        wsum[lane] = w;
    }
    __syncthreads();
    int warp_off = (wid > 0) ? wsum[wid - 1] : 0;
    int run = warp_off + ws - s;   // exclusive prefix at this thread's base
#pragma unroll
    for (int i = 0; i < PER; ++i) {
        int idx = base + i;
        if (idx < NNODES) { g_ptr[idx] = run; g_fill[idx] = run; }
        run += v[i];
    }
    if (tid == 0) g_ptr[NNODES] = wsum[31];
}

__global__ void k_scatter(const int* __restrict__ coli) {
    int e = blockIdx.x * blockDim.x + threadIdx.x;
    if (e < NEDGES) {
        int pos = atomicAdd(&g_fill[coli[e]], 1);
        g_eid[pos] = e;
    }
}

// ---------------- segment sum: g_a[n] = sum t[e] (u2 only) ----------------
__global__ void k_segsum(int src_sel) {
    const float* h = hbuf(src_sel);
    int t = blockIdx.x * blockDim.x + threadIdx.x;
    if (t >= NNODES * 75) return;
    int n = t / 75;
    int c = (t - n * 75) * 4;
    int beg = g_ptr[n], end = g_ptr[n + 1];
    float4 acc = make_float4(0.f, 0.f, 0.f, 0.f);
#pragma unroll 2
    for (int i = beg; i < end; ++i) {
        int e = g_eid[i];
        float4 vv = ld4(h + e * HIDN + c);
        acc.x += vv.x; acc.y += vv.y; acc.z += vv.z; acc.w += vv.w;
    }
    st4(g_a + n * HIDN + c, acc);
}

// ------ fused segsum + next-h materialize (paired-edge identity) --------
__global__ void k_seghm(int t_sel, const float* __restrict__ bc) {
    const float* tp = hbuf(t_sel);
    int t = blockIdx.x * blockDim.x + threadIdx.x;
    if (t >= NNODES * 75) return;
    int n = t / 75;
    int c = (t - n * 75) * 4;
    float4 bv = ld4(bc + c);
    int beg = g_ptr[n], end = g_ptr[n + 1];
    float4 u = make_float4(0.f, 0.f, 0.f, 0.f);
#pragma unroll 2
    for (int i = beg; i < end; ++i) {
        int e = g_eid[i];
        float4 vv = ld4(tp + e * HIDN + c);
        u.x += vv.x; u.y += vv.y; u.z += vv.z; u.w += vv.w;
    }
#pragma unroll 2
    for (int i = beg; i < end; ++i) {
        int e = g_eid[i];
        int er = e ^ 1;
        float4 tv  = ld4(tp + e * HIDN + c);
        float4 h0v = ld4(g_h0 + er * HIDN + c);
        float4 v;
        v.x = frelu(h0v.x + bv.x + u.x - tv.x);
        v.y = frelu(h0v.y + bv.y + u.y - tv.y);
        v.z = frelu(h0v.z + bv.z + u.z - tv.z);
        v.w = frelu(h0v.w + bv.w + u.w - tv.w);
        uint32_t h0w, l0w, h1w, l1w;
        split_pack(v.x, v.y, h0w, l0w);
        split_pack(v.z, v.w, h1w, l1w);
        *reinterpret_cast<uint2*>(g_Ah + (size_t)er * 320 + c) = make_uint2(h0w, h1w);
        *reinterpret_cast<uint2*>(g_Al + (size_t)er * 320 + c) = make_uint2(l0w, l1w);
    }
}

// --------- fused final: g_s[n] = sum_e relu(h0[e]+bc2+u2[row[e]]-rev(t2)) ----
__global__ void k_segsum_h3(int t2_sel, const float* __restrict__ bc2,
                            const int* __restrict__ rowi) {
    const float* t2 = hbuf(t2_sel);
    int t = blockIdx.x * blockDim.x + threadIdx.x;
    if (t >= NNODES * 75) return;
    int n = t / 75;
    int c = (t - n * 75) * 4;
    float4 bv = ld4(bc2 + c);
    int beg = g_ptr[n], end = g_ptr[n + 1];
    float4 acc = make_float4(0.f, 0.f, 0.f, 0.f);
#pragma unroll 2
    for (int i = beg; i < end; ++i) {
        int e = g_eid[i];
        float4 h0v = ld4(g_h0 + e * HIDN + c);
        float4 uv  = ld4(g_a + rowi[e] * HIDN + c);
        float4 tv  = ld4(t2 + (e ^ 1) * HIDN + c);
        acc.x += frelu(h0v.x + bv.x + uv.x - tv.x);
        acc.y += frelu(h0v.y + bv.y + uv.y - tv.y);
        acc.z += frelu(h0v.z + bv.z + uv.z - tv.z);
        acc.w += frelu(h0v.w + bv.w + uv.w - tv.w);
    }
    st4(g_s + n * HIDN + c, acc);
}

// =====================================================================
// Conv GEMM, 2 CTA/SM, mbarrier cp.async pipeline (.noinc arrives):
//   warps 0-3 load A (2-stage, prefetch distance 2, DRAM stream hidden),
//   warps 4-7 load B (single stage, L2-resident, same-iter wait).
// CTA 128m x 128n, K=320 in 5 chunks of 64, 3-pass bf16 split, fp32 acc.
// smem: A 2x32KB + B 32KB + mbars = 96.1KB -> 2 CTAs/SM.
// =====================================================================
#define C2_STAGE 32768          // one A stage: AH 16K + AL 16K
#define C2_BH 65536
#define C2_BL 81920
#define C2_MBAR 98304           // 4 mbars
#define C2_TOTAL 98368

__global__ void __launch_bounds__(256, 2) k_cgemm(int layer, int out_sel) {
    extern __shared__ char smem[];
    uint32_t sb = smem_u32(smem);
    int tid = threadIdx.x;
    int lane = tid & 31;
    int wid = tid >> 5;
    int m0 = blockIdx.y * 128;
    int n0 = blockIdx.x * 128;

    const __nv_bfloat16* Wh = g_Wh + layer * 122880;
    const __nv_bfloat16* Wl = g_Wl + layer * 122880;
    float* tout = hbuf(out_sel);

    uint32_t mbA0 = sb + C2_MBAR, mbA1 = sb + C2_MBAR + 8;
    uint32_t mbB0 = sb + C2_MBAR + 16, mbB1 = sb + C2_MBAR + 24;

    if (tid == 0) {
        MBAR_INIT(mbA0, 128); MBAR_INIT(mbA1, 128);
        MBAR_INIT(mbB0, 128); MBAR_INIT(mbB1, 128);
    }
    __syncthreads();

    bool isA = (tid < 128);
    int lt = tid & 127;

    int wm = wid >> 1, wn = wid & 1;
    int mat = lane >> 3, l7 = lane & 7;
    int a_row = wm * 32 + (mat & 1) * 8 + l7;
    int a_kof = (mat >> 1) * 8;
    int b_base = wn * 64 + (mat >> 1) * 8 + l7;
    int b_kof = (mat & 1) * 8;
    bool nact = (n0 + wn * 64) < HIDN;

    uint32_t a_soff[2][4], b_soff[4][4];
#pragma unroll
    for (int mt = 0; mt < 2; ++mt)
#pragma unroll
        for (int ks = 0; ks < 4; ++ks)
            a_soff[mt][ks] = sw128((uint32_t)(((a_row + mt * 16) << 7) +
                                              ((ks * 16 + a_kof) << 1)));
#pragma unroll
    for (int np = 0; np < 4; ++np)
#pragma unroll
        for (int ks = 0; ks < 4; ++ks)
            b_soff[np][ks] = sw128((uint32_t)(((b_base + np * 16) << 7) +
                                              ((ks * 16 + b_kof) << 1)));

#define A_ISSUE(KC)                                                            \
    {                                                                          \
        uint32_t stg = sb + ((KC) & 1) * C2_STAGE;                             \
        _Pragma("unroll")                                                      \
        for (int s = 0; s < 8; s++) {                                          \
            int j = lt + s * 128;                                              \
            int r2 = j >> 3, i = j & 7;                                        \
            uint32_t off = sw128((uint32_t)(r2 * 128 + i * 16));               \
            CPA16(stg + off,         g_Ah + (size_t)(m0 + r2) * 320 + (KC) * 64 + i * 8); \
            CPA16(stg + 16384 + off, g_Al + (size_t)(m0 + r2) * 320 + (KC) * 64 + i * 8); \
        }                                                                      \
    }
#define B_ISSUE(KC)                                                            \
    {                                                                          \
        _Pragma("unroll")                                                      \
        for (int s = 0; s < 8; s++) {                                          \
            int j = lt + s * 128;                                              \
            int r2 = j >> 3, i = j & 7;                                        \
            uint32_t off = sw128((uint32_t)(r2 * 128 + i * 16));               \
            CPA16(sb + C2_BH + off, Wh + (size_t)(n0 + r2) * 320 + (KC) * 64 + i * 8); \
            CPA16(sb + C2_BL + off, Wl + (size_t)(n0 + r2) * 320 + (KC) * 64 + i * 8); \
        }                                                                      \
    }

    if (isA) {
        A_ISSUE(0) CPA_MBAR_ARRIVE(mbA0);
        A_ISSUE(1) CPA_MBAR_ARRIVE(mbA1);
    }

    float acc[2][8][4];
#pragma unroll
    for (int i = 0; i < 2; i++)
#pragma unroll
        for (int j = 0; j < 8; j++)
#pragma unroll
            for (int q = 0; q < 4; q++) acc[i][j][q] = 0.f;

    for (int kc = 0; kc < 5; ++kc) {
        uint32_t mbA = (kc & 1) ? mbA1 : mbA0;
        uint32_t mbB = (kc & 1) ? mbB1 : mbB0;
        uint32_t par = (uint32_t)((kc >> 1) & 1);
        if (!isA) { B_ISSUE(kc) CPA_MBAR_ARRIVE(mbB); }
        mbar_wait(mbA, par);
        mbar_wait(mbB, par);
        __syncthreads();

        uint32_t ast = sb + ((uint32_t)kc & 1) * C2_STAGE;
#pragma unroll
        for (int ks = 0; ks < 4; ++ks) {
            uint32_t ah[2][4], al[2][4];
#pragma unroll
            for (int mt = 0; mt < 2; ++mt) {
                ldsm4(ah[mt], ast + a_soff[mt][ks]);
                ldsm4(al[mt], ast + 16384 + a_soff[mt][ks]);
            }
            if (nact) {
#pragma unroll
                for (int np = 0; np < 4; ++np) {
                    uint32_t bh[4], bl[4];
                    ldsm4(bh, sb + C2_BH + b_soff[np][ks]);
                    ldsm4(bl, sb + C2_BL + b_soff[np][ks]);
#pragma unroll
                    for (int mt = 0; mt < 2; ++mt)
#pragma unroll
                        for (int h = 0; h < 2; ++h) {
                            float* d = acc[mt][np * 2 + h];
                            mma_bf(d, ah[mt], bh + h * 2);
                            mma_bf(d, ah[mt], bl + h * 2);
                            mma_bf(d, al[mt], bh + h * 2);
                        }
                }
            }
        }
        __syncthreads();
        if (kc + 2 < 5 && isA) { A_ISSUE(kc + 2) CPA_MBAR_ARRIVE(mbA); }
    }
#undef A_ISSUE
#undef B_ISSUE

    int orow = m0 + wm * 32 + (lane >> 2);
    int oc0  = n0 + wn * 64 + (lane & 3) * 2;
#pragma unroll
    for (int mt = 0; mt < 2; ++mt)
#pragma unroll
        for (int nt = 0; nt < 8; ++nt) {
            int col = oc0 + nt * 8;
            if (col >= HIDN) continue;
#pragma unroll
            for (int h = 0; h < 2; ++h) {
                int row = orow + mt * 16 + h * 8;
                *reinterpret_cast<float2*>(tout + row * HIDN + col) =
                    make_float2(acc[mt][nt][h * 2], acc[mt][nt][h * 2 + 1]);
            }
        }
}

// =====================================================================
// Init GEMM: A = [x[row]|ea] (K=80 -> 2 chunks), epilogue h0 fp32 + bf16 split
// =====================================================================
#define TG_A_HI 0
#define TG_A_LO 16384
#define TG_B_HI 32768
#define TG_B_LO 49152
#define TG_TOTAL 65536

__global__ void __launch_bounds__(256, 2) k_tginit(
    const int* __restrict__ rowi, const float* __restrict__ bvec,
    const float* __restrict__ x, const float* __restrict__ ea)
{
    extern __shared__ char smem[];
    uint32_t sb = smem_u32(smem);
    int tid = threadIdx.x;
    int lane = tid & 31;
    int wid = tid >> 5;
    int m0 = blockIdx.y * 128;
    int n0 = blockIdx.x * 128;

    int r = tid >> 1;
    int e = m0 + r;
    int cc0 = (tid & 1) * 32;
    int rv = rowi[e];

    int wm = wid >> 1, wn = wid & 1;
    int mat = lane >> 3, l7 = lane & 7;
    int a_row = wm * 32 + (mat & 1) * 8 + l7;
    int a_kof = (mat >> 1) * 8;
    int b_base = wn * 64 + (mat >> 1) * 8 + l7;
    int b_kof = (mat & 1) * 8;
    bool nact = (n0 + wn * 64) < HIDN;

    float acc[2][8][4];
#pragma unroll
    for (int i = 0; i < 2; i++)
#pragma unroll
        for (int j = 0; j < 8; j++)
#pragma unroll
            for (int q = 0; q < 4; q++) acc[i][j][q] = 0.f;

    for (int kc = 0; kc < 2; ++kc) {
        int k0 = kc * 64;
        if (kc) __syncthreads();
#pragma unroll
        for (int s = 0; s < 4; s++) {
            int j = tid + s * 256;
            int n = j >> 3, i = j & 7;
            uint32_t off = sw128((uint32_t)(n * 128 + i * 16));
            CPA16(sb + TG_B_HI + off, g_WIh + (n0 + n) * 320 + k0 + i * 8);
            CPA16(sb + TG_B_LO + off, g_WIl + (n0 + n) * 320 + k0 + i * 8);
        }
        CPA_COMMIT();
#pragma unroll
        for (int i = 0; i < 8; i++) {
            int cc = cc0 + i * 4;
            int k = k0 + cc;
            float4 v = make_float4(0.f, 0.f, 0.f, 0.f);
            if (k < FNODE)    v = ld4(x + rv * FNODE + k);
            else if (k < 80)  v = ld4(ea + e * FEDGE + (k - FNODE));
            uint32_t h0w, l0w, h1w, l1w;
            split_pack(v.x, v.y, h0w, l0w);
            split_pack(v.z, v.w, h1w, l1w);
            uint32_t off = sw128((uint32_t)(r * 128 + cc * 2));
            *reinterpret_cast<uint2*>(smem + TG_A_HI + off) = make_uint2(h0w, h1w);
            *reinterpret_cast<uint2*>(smem + TG_A_LO + off) = make_uint2(l0w, l1w);
        }
        CPA_WAIT0();
        __syncthreads();
#pragma unroll
        for (int ks = 0; ks < 4; ++ks) {
            uint32_t ah[2][4], al[2][4];
#pragma unroll
            for (int mt = 0; mt < 2; ++mt) {
                uint32_t off = sw128((uint32_t)(((a_row + mt * 16) << 7) +
                                                ((ks * 16 + a_kof) << 1)));
                ldsm4(ah[mt], sb + TG_A_HI + off);
                ldsm4(al[mt], sb + TG_A_LO + off);
            }
            if (nact) {
#pragma unroll
                for (int np = 0; np < 4; ++np) {
                    uint32_t boff = sw128((uint32_t)(((b_base + np * 16) << 7) +
                                                     ((ks * 16 + b_kof) << 1)));
                    uint32_t bh[4], bl[4];
                    ldsm4(bh, sb + TG_B_HI + boff);
                    ldsm4(bl, sb + TG_B_LO + boff);
#pragma unroll
                    for (int mt = 0; mt < 2; ++mt)
#pragma unroll
                        for (int h = 0; h < 2; ++h) {
                            float* d = acc[mt][np * 2 + h];
                            mma_bf(d, ah[mt], bh + h * 2);
                            mma_bf(d, ah[mt], bl + h * 2);
                            mma_bf(d, al[mt], bh + h * 2);
                        }
                }
            }
        }
    }

    int orow = m0 + wm * 32 + (lane >> 2);
    int oc0  = n0 + wn * 64 + (lane & 3) * 2;
#pragma unroll
    for (int mt = 0; mt < 2; ++mt)
#pragma unroll
        for (int nt = 0; nt < 8; ++nt) {
            int col = oc0 + nt * 8;
            if (col >= 320) continue;
            bool live = col < HIDN;
            float b0 = live ? bvec[col] : 0.f;
            float b1 = live ? bvec[col + 1] : 0.f;
#pragma unroll
            for (int h = 0; h < 2; ++h) {
                int row = orow + mt * 16 + h * 8;
                float v0 = live ? frelu(acc[mt][nt][h * 2] + b0) : 0.f;
                float v1 = live ? frelu(acc[mt][nt][h * 2 + 1] + b1) : 0.f;
                if (live)
                    *reinterpret_cast<float2*>(g_h0 + row * HIDN + col) = make_float2(v0, v1);
                uint32_t hw, lw;
                split_pack(v0, v1, hw, lw);
                *reinterpret_cast<uint32_t*>(g_Ah + (size_t)row * 320 + col) = hw;
                *reinterpret_cast<uint32_t*>(g_Al + (size_t)row * 320 + col) = lw;
            }
        }
}

// =====================================================================
// Node GEMM (tensor): hn = relu([x|s] @ W_e2n + be); pool += hn
// =====================================================================
__global__ void __launch_bounds__(256, 2) k_tgnode(
    const int* __restrict__ batch, const float* __restrict__ bvec,
    const float* __restrict__ x)
{
    extern __shared__ char smem[];
    uint32_t sb = smem_u32(smem);
    int tid = threadIdx.x;
    int lane = tid & 31;
    int wid = tid >> 5;
    int m0 = blockIdx.y * 128;
    int n0 = blockIdx.x * 128;

    int r = tid >> 1;
    int e = m0 + r;
    bool eok = (e < NNODES);
    int es = eok ? e : 0;
    int cc0 = (tid & 1) * 32;

    int wm = wid >> 1, wn = wid & 1;
    int mat = lane >> 3, l7 = lane & 7;
    int a_row = wm * 32 + (mat & 1) * 8 + l7;
    int a_kof = (mat >> 1) * 8;
    int b_base = wn * 64 + (mat >> 1) * 8 + l7;
    int b_kof = (mat & 1) * 8;
    bool nact = (n0 + wn * 64) < HIDN;

    const int KTOT = FNODE + HIDN;  // 364

    float acc[2][8][4];
#pragma unroll
    for (int i = 0; i < 2; i++)
#pragma unroll
        for (int j = 0; j < 8; j++)
#pragma unroll
            for (int q = 0; q < 4; q++) acc[i][j][q] = 0.f;

    for (int kc = 0; kc < 6; ++kc) {
        int k0 = kc * 64;
        if (kc) __syncthreads();
#pragma unroll
        for (int s = 0; s < 4; s++) {
            int j = tid + s * 256;
            int n = j >> 3, i = j & 7;
            uint32_t off = sw128((uint32_t)(n * 128 + i * 16));
            CPA16(sb + TG_B_HI + off, g_WNh + (n0 + n) * 384 + k0 + i * 8);
            CPA16(sb + TG_B_LO + off, g_WNl + (n0 + n) * 384 + k0 + i * 8);
        }
        CPA_COMMIT();
#pragma unroll
        for (int i = 0; i < 8; i++) {
            int cc = cc0 + i * 4;
            int k = k0 + cc;
            float4 v = make_float4(0.f, 0.f, 0.f, 0.f);
            if (eok && k < KTOT)
                v = (k < FNODE) ? ld4(x + es * FNODE + k)
                                : ld4(g_s + es * HIDN + (k - FNODE));
            uint32_t h0w, l0w, h1w, l1w;
            split_pack(v.x, v.y, h0w, l0w);
            split_pack(v.z, v.w, h1w, l1w);
            uint32_t off = sw128((uint32_t)(r * 128 + cc * 2));
            *reinterpret_cast<uint2*>(smem + TG_A_HI + off) = make_uint2(h0w, h1w);
            *reinterpret_cast<uint2*>(smem + TG_A_LO + off) = make_uint2(l0w, l1w);
        }
        CPA_WAIT0();
        __syncthreads();
#pragma unroll
        for (int ks = 0; ks < 4; ++ks) {
            uint32_t ah[2][4], al[2][4];
#pragma unroll
            for (int mt = 0; mt < 2; ++mt) {
                uint32_t off = sw128((uint32_t)(((a_row + mt * 16) << 7) +
                                                ((ks * 16 + a_kof) << 1)));
                ldsm4(ah[mt], sb + TG_A_HI + off);
                ldsm4(al[mt], sb + TG_A_LO + off);
            }
            if (nact) {
#pragma unroll
                for (int np = 0; np < 4; ++np) {
                    uint32_t boff = sw128((uint32_t)(((b_base + np * 16) << 7) +
                                                     ((ks * 16 + b_kof) << 1)));
                    uint32_t bh[4], bl[4];
                    ldsm4(bh, sb + TG_B_HI + boff);
                    ldsm4(bl, sb + TG_B_LO + boff);
#pragma unroll
                    for (int mt = 0; mt < 2; ++mt)
#pragma unroll
                        for (int h = 0; h < 2; ++h) {
                            float* d = acc[mt][np * 2 + h];
                            mma_bf(d, ah[mt], bh + h * 2);
                            mma_bf(d, ah[mt], bl + h * 2);
                            mma_bf(d, al[mt], bh + h * 2);
                        }
                }
            }
        }
    }

    int orow = m0 + wm * 32 + (lane >> 2);
    int oc0  = n0 + wn * 64 + (lane & 3) * 2;
#pragma unroll
    for (int mt = 0; mt < 2; ++mt)
#pragma unroll
        for (int nt = 0; nt < 8; ++nt) {
            int col = oc0 + nt * 8;
            if (col >= HIDN) continue;
            float b0 = bvec[col], b1 = bvec[col + 1];
#pragma unroll
            for (int h = 0; h < 2; ++h) {
                int row = orow + mt * 16 + h * 8;
                if (row >= NNODES) continue;
                float* p = g_pool + batch[row] * HIDN + col;
                atomicAdd(p + 0, frelu(acc[mt][nt][h * 2] + b0));
                atomicAdd(p + 1, frelu(acc[mt][nt][h * 2 + 1] + b1));
            }
        }
}

// ---------------- FFN ----------------
__global__ void k_ffn(const float* __restrict__ Wf, const float* __restrict__ bf,
                      float* __restrict__ out) {
    int g = blockIdx.x;
    int lane = threadIdx.x;
    float s = 0.f;
    for (int k = lane; k < HIDN; k += 32) s += g_pool[g * HIDN + k] * Wf[k];
#pragma unroll
    for (int o = 16; o; o >>= 1) s += __shfl_xor_sync(0xffffffffu, s, o);
    if (lane == 0) out[g] = s + bf[0];
}

// ---------------- entry ----------------
extern "C" void kernel_launch(void* const* d_in, const int* in_sizes, int n_in,
                              void* d_out, int out_size) {
    const float* x     = (const float*)d_in[0];
    const float* ea    = (const float*)d_in[1];
    const int*   ei    = (const int*)d_in[2];
    const int*   rowi  = ei;
    const int*   coli  = ei + NEDGES;
    const int*   batch = (const int*)d_in[3];
    const float* Wi    = (const float*)d_in[4];
    const float* bi    = (const float*)d_in[5];
    const float* Wc    = (const float*)d_in[6];
    const float* bc    = (const float*)d_in[7];
    const float* We    = (const float*)d_in[8];
    const float* be    = (const float*)d_in[9];
    const float* Wf    = (const float*)d_in[10];
    const float* bf    = (const float*)d_in[11];
    float* out = (float*)d_out;

    cudaFuncSetAttribute(k_cgemm,  cudaFuncAttributeMaxDynamicSharedMemorySize, C2_TOTAL);
    cudaFuncSetAttribute(k_tginit, cudaFuncAttributeMaxDynamicSharedMemorySize, TG_TOTAL);
    cudaFuncSetAttribute(k_tgnode, cudaFuncAttributeMaxDynamicSharedMemorySize, TG_TOTAL);

    dim3 gT(3, NEDGES / 128);
    dim3 gN(3, (NNODES + 127) / 128);
    int ssB = (NNODES * 75 + 255) / 256;

    k_pre<<<1440, 256>>>(Wc, Wi, We);                   // 1
    k_hist<<<NEDGES / 256, 256>>>(coli);                // 2
    k_tginit<<<gT, 256, TG_TOTAL>>>(rowi, bi, x, ea);   // 3: h0 + A bf16
    k_cgemm<<<gT, 256, C2_TOTAL>>>(0, 1);               // 4: t0  <- profiled
    k_scan<<<1, 1024>>>();                              // 5
    k_scatter<<<NEDGES / 256, 256>>>(coli);             // 6

    k_seghm<<<ssB, 256>>>(1, bc);                       // u0 (regs) + A = h1 bf16
    k_cgemm<<<gT, 256, C2_TOTAL>>>(1, 2);               // t1
    k_seghm<<<ssB, 256>>>(2, bc + HIDN);                // u1 (regs) + A = h2 bf16
    k_cgemm<<<gT, 256, C2_TOTAL>>>(2, 1);               // t2
    k_segsum<<<ssB, 256>>>(1);                          // u2 -> g_a
    k_segsum_h3<<<ssB, 256>>>(1, bc + 2 * HIDN, rowi);  // s (fused h3+segsum)

    k_tgnode<<<gN, 256, TG_TOTAL>>>(batch, be, x);      // node GEMM + pool
    k_ffn<<<NGRAPH, 32>>>(Wf, bf, out);
}

// round 13
// speedup vs baseline: 1.1357x; 1.0131x over previous
#include <cuda_runtime.h>
#include <cuda_bf16.h>
#include <cstdint>

#define NNODES 20000
#define NEDGES 320000
#define FNODE  64
#define FEDGE  16
#define HIDN   300
#define NGRAPH 128

typedef unsigned long long ull;

// ---------------- scratch (device globals) ----------------
__device__ float g_h0[NEDGES * HIDN];
__device__ float g_hA[NEDGES * HIDN];          // t ping
__device__ float g_hB[NEDGES * HIDN];          // t pong
__device__ __nv_bfloat16 g_Ah[NEDGES * 320];   // A operand hi (current layer)
__device__ __nv_bfloat16 g_Al[NEDGES * 320];   // A operand lo
__device__ float g_a [NNODES * HIDN];          // u2
__device__ float g_s [NNODES * HIDN];          // final node message
__device__ float g_pool[NGRAPH * HIDN];
__device__ __nv_bfloat16 g_Wh [3 * 384 * 320]; // conv W^T hi [l][n][k], zero-pad
__device__ __nv_bfloat16 g_Wl [3 * 384 * 320];
__device__ __nv_bfloat16 g_WIh[384 * 320];     // init W^T hi
__device__ __nv_bfloat16 g_WIl[384 * 320];
__device__ __nv_bfloat16 g_WNh[384 * 384];     // e2n W^T hi [n][k]
__device__ __nv_bfloat16 g_WNl[384 * 384];
__device__ int g_cnt [NNODES];
__device__ int g_ptr [NNODES + 1];
__device__ int g_fill[NNODES];
__device__ int g_eid [NEDGES];

__device__ __forceinline__ float* hbuf(int s) {
    return (s == 0) ? g_h0 : ((s == 1) ? g_hA : g_hB);
}

// ---------------- helpers ----------------
__device__ __forceinline__ float4 ld4(const float* p) { return *reinterpret_cast<const float4*>(p); }
__device__ __forceinline__ void   st4(float* p, float4 v) { *reinterpret_cast<float4*>(p) = v; }
__device__ __forceinline__ float  frelu(float x) { return x > 0.f ? x : 0.f; }

__device__ __forceinline__ uint32_t smem_u32(const void* p) {
    uint32_t a;
    asm("{ .reg .u64 t; cvta.to.shared.u64 t, %1; cvt.u32.u64 %0, t; }" : "=r"(a) : "l"(p));
    return a;
}
__device__ __forceinline__ uint32_t sw128(uint32_t o) { return o ^ ((o >> 3) & 0x70); }

__device__ __forceinline__ void ldsm4(uint32_t* r, uint32_t a) {
    asm volatile("ldmatrix.sync.aligned.m8n8.x4.shared.b16 {%0,%1,%2,%3}, [%4];"
                 : "=r"(r[0]), "=r"(r[1]), "=r"(r[2]), "=r"(r[3]) : "r"(a));
}
__device__ __forceinline__ void mma_bf(float* d, const uint32_t* a, const uint32_t* b) {
    asm volatile("mma.sync.aligned.m16n8k16.row.col.f32.bf16.bf16.f32 "
                 "{%0,%1,%2,%3}, {%4,%5,%6,%7}, {%8,%9}, {%0,%1,%2,%3};"
                 : "+f"(d[0]), "+f"(d[1]), "+f"(d[2]), "+f"(d[3])
                 : "r"(a[0]), "r"(a[1]), "r"(a[2]), "r"(a[3]), "r"(b[0]), "r"(b[1]));
}
#define CPA16(dst, src) asm volatile("cp.async.cg.shared.global [%0], [%1], 16;" :: "r"(dst), "l"(src))
#define CPA_COMMIT()    asm volatile("cp.async.commit_group;" ::: "memory")
#define CPA_WAIT0()     asm volatile("cp.async.wait_group 0;" ::: "memory")

__device__ __forceinline__ void split_pack(float v0, float v1, uint32_t& hi, uint32_t& lo) {
    __nv_bfloat162 h, l;
    h.x = __float2bfloat16(v0); h.y = __float2bfloat16(v1);
    l.x = __float2bfloat16(v0 - __bfloat162float(h.x));
    l.y = __float2bfloat16(v1 - __bfloat162float(h.y));
    hi = *reinterpret_cast<uint32_t*>(&h);
    lo = *reinterpret_cast<uint32_t*>(&l);
}

// ---------------- preprocessing ----------------
__global__ void k_pre(const float* __restrict__ Wc, const float* __restrict__ Wi,
                      const float* __restrict__ We) {
    int t = blockIdx.x * blockDim.x + threadIdx.x;
    if (t < NNODES) g_cnt[t] = 0;
    if (t < NGRAPH * HIDN) g_pool[t] = 0.f;
    if (t < 122880) {
        int n = t / 320, k = t % 320;
        float v = (n < HIDN && k < 80) ? Wi[k * HIDN + n] : 0.f;
        __nv_bfloat16 bh = __float2bfloat16(v);
        g_WIh[t] = bh;
        g_WIl[t] = __float2bfloat16(v - __bfloat162float(bh));
    }
    if (t < 3 * 122880) {
        int l = t / 122880, r2 = t % 122880;
        int n = r2 / 320, k = r2 % 320;
        float v = (n < HIDN && k < HIDN) ? Wc[l * HIDN * HIDN + k * HIDN + n] : 0.f;
        __nv_bfloat16 bh = __float2bfloat16(v);
        g_Wh[t] = bh;
        g_Wl[t] = __float2bfloat16(v - __bfloat162float(bh));
    }
    if (t < 384 * 384) {
        int n = t / 384, k = t % 384;
        float v = (n < HIDN && k < FNODE + HIDN) ? We[k * HIDN + n] : 0.f;
        __nv_bfloat16 bh = __float2bfloat16(v);
        g_WNh[t] = bh;
        g_WNl[t] = __float2bfloat16(v - __bfloat162float(bh));
    }
}

__global__ void k_hist(const int* __restrict__ coli) {
    int e = blockIdx.x * blockDim.x + threadIdx.x;
    if (e < NEDGES) atomicAdd(&g_cnt[coli[e]], 1);
}

// fast single-block scan: 1024 threads x 20 elems, shuffle-based (3 syncs)
__global__ void k_scan() {
    __shared__ int wsum[32];
    int tid = threadIdx.x;
    int lane = tid & 31, wid = tid >> 5;
    const int PER = 20;
    int base = tid * PER;
    int v[PER];
    int s = 0;
#pragma unroll
    for (int i = 0; i < PER; ++i) {
        int idx = base + i;
        v[i] = (idx < NNODES) ? g_cnt[idx] : 0;
        s += v[i];
    }
    int ws = s;
#pragma unroll
    for (int off = 1; off < 32; off <<= 1) {
        int t = __shfl_up_sync(0xffffffffu, ws, off);
        if (lane >= off) ws += t;
    }
    if (lane == 31) wsum[wid] = ws;
    __syncthreads();
    if (wid == 0) {
        int w = wsum[lane];
#pragma unroll
        for (int off = 1; off < 32; off <<= 1) {
            int t = __shfl_up_sync(0xffffffffu, w, off);
            if (lane >= off) w += t;
        }
        wsum[lane] = w;
    }
    __syncthreads();
    int warp_off = (wid > 0) ? wsum[wid - 1] : 0;
    int run = warp_off + ws - s;
#pragma unroll
    for (int i = 0; i < PER; ++i) {
        int idx = base + i;
        if (idx < NNODES) { g_ptr[idx] = run; g_fill[idx] = run; }
        run += v[i];
    }
    if (tid == 0) g_ptr[NNODES] = wsum[31];
}

__global__ void k_scatter(const int* __restrict__ coli) {
    int e = blockIdx.x * blockDim.x + threadIdx.x;
    if (e < NEDGES) {
        int pos = atomicAdd(&g_fill[coli[e]], 1);
        g_eid[pos] = e;
    }
}

// ---------------- segment sum: g_a[n] = sum t[e] (u2 only) ----------------
__global__ void k_segsum(int src_sel) {
    const float* h = hbuf(src_sel);
    int t = blockIdx.x * blockDim.x + threadIdx.x;
    if (t >= NNODES * 75) return;
    int n = t / 75;
    int c = (t - n * 75) * 4;
    int beg = g_ptr[n], end = g_ptr[n + 1];
    float4 acc = make_float4(0.f, 0.f, 0.f, 0.f);
#pragma unroll 2
    for (int i = beg; i < end; ++i) {
        int e = g_eid[i];
        float4 vv = ld4(h + e * HIDN + c);
        acc.x += vv.x; acc.y += vv.y; acc.z += vv.z; acc.w += vv.w;
    }
    st4(g_a + n * HIDN + c, acc);
}

// ------ fused segsum + next-h materialize (paired-edge identity) --------
__global__ void k_seghm(int t_sel, const float* __restrict__ bc) {
    const float* tp = hbuf(t_sel);
    int t = blockIdx.x * blockDim.x + threadIdx.x;
    if (t >= NNODES * 75) return;
    int n = t / 75;
    int c = (t - n * 75) * 4;
    float4 bv = ld4(bc + c);
    int beg = g_ptr[n], end = g_ptr[n + 1];
    float4 u = make_float4(0.f, 0.f, 0.f, 0.f);
#pragma unroll 2
    for (int i = beg; i < end; ++i) {
        int e = g_eid[i];
        float4 vv = ld4(tp + e * HIDN + c);
        u.x += vv.x; u.y += vv.y; u.z += vv.z; u.w += vv.w;
    }
#pragma unroll 2
    for (int i = beg; i < end; ++i) {
        int e = g_eid[i];
        int er = e ^ 1;
        float4 tv  = ld4(tp + e * HIDN + c);
        float4 h0v = ld4(g_h0 + er * HIDN + c);
        float4 v;
        v.x = frelu(h0v.x + bv.x + u.x - tv.x);
        v.y = frelu(h0v.y + bv.y + u.y - tv.y);
        v.z = frelu(h0v.z + bv.z + u.z - tv.z);
        v.w = frelu(h0v.w + bv.w + u.w - tv.w);
        uint32_t h0w, l0w, h1w, l1w;
        split_pack(v.x, v.y, h0w, l0w);
        split_pack(v.z, v.w, h1w, l1w);
        *reinterpret_cast<uint2*>(g_Ah + (size_t)er * 320 + c) = make_uint2(h0w, h1w);
        *reinterpret_cast<uint2*>(g_Al + (size_t)er * 320 + c) = make_uint2(l0w, l1w);
    }
}

// --------- fused final: g_s[n] = sum_e relu(h0[e]+bc2+u2[row[e]]-rev(t2)) ----
__global__ void k_segsum_h3(int t2_sel, const float* __restrict__ bc2,
                            const int* __restrict__ rowi) {
    const float* t2 = hbuf(t2_sel);
    int t = blockIdx.x * blockDim.x + threadIdx.x;
    if (t >= NNODES * 75) return;
    int n = t / 75;
    int c = (t - n * 75) * 4;
    float4 bv = ld4(bc2 + c);
    int beg = g_ptr[n], end = g_ptr[n + 1];
    float4 acc = make_float4(0.f, 0.f, 0.f, 0.f);
#pragma unroll 2
    for (int i = beg; i < end; ++i) {
        int e = g_eid[i];
        float4 h0v = ld4(g_h0 + e * HIDN + c);
        float4 uv  = ld4(g_a + rowi[e] * HIDN + c);
        float4 tv  = ld4(t2 + (e ^ 1) * HIDN + c);
        acc.x += frelu(h0v.x + bv.x + uv.x - tv.x);
        acc.y += frelu(h0v.y + bv.y + uv.y - tv.y);
        acc.z += frelu(h0v.z + bv.z + uv.z - tv.z);
        acc.w += frelu(h0v.w + bv.w + uv.w - tv.w);
    }
    st4(g_s + n * HIDN + c, acc);
}

// =====================================================================
// Conv GEMM (R9-proven): t_out = A @ W_layer, K=320 in 5 chunks of 64.
// CTA 128m x 128n, 8 warps (4m x 2n), SW128, cp.async commit+wait0,
// 2 CTAs/SM, 3-pass bf16 split, fp32 acc. Precomputed ldsm offsets.
// =====================================================================
#define TG_A_HI 0
#define TG_A_LO 16384
#define TG_B_HI 32768
#define TG_B_LO 49152
#define TG_TOTAL 65536

__global__ void __launch_bounds__(256, 2) k_cgemm(int layer, int out_sel) {
    extern __shared__ char smem[];
    uint32_t sb = smem_u32(smem);
    int tid = threadIdx.x;
    int lane = tid & 31;
    int wid = tid >> 5;
    int m0 = blockIdx.y * 128;
    int n0 = blockIdx.x * 128;

    const __nv_bfloat16* Wh = g_Wh + layer * 122880;
    const __nv_bfloat16* Wl = g_Wl + layer * 122880;
    float* tout = hbuf(out_sel);

    int wm = wid >> 1, wn = wid & 1;
    int mat = lane >> 3, l7 = lane & 7;
    int a_row = wm * 32 + (mat & 1) * 8 + l7;
    int a_kof = (mat >> 1) * 8;
    int b_base = wn * 64 + (mat >> 1) * 8 + l7;
    int b_kof = (mat & 1) * 8;
    bool nact = (n0 + wn * 64) < HIDN;

    uint32_t a_soff[2][4], b_soff[4][4];
#pragma unroll
    for (int mt = 0; mt < 2; ++mt)
#pragma unroll
        for (int ks = 0; ks < 4; ++ks)
            a_soff[mt][ks] = sw128((uint32_t)(((a_row + mt * 16) << 7) +
                                              ((ks * 16 + a_kof) << 1)));
#pragma unroll
    for (int np = 0; np < 4; ++np)
#pragma unroll
        for (int ks = 0; ks < 4; ++ks)
            b_soff[np][ks] = sw128((uint32_t)(((b_base + np * 16) << 7) +
                                              ((ks * 16 + b_kof) << 1)));

    float acc[2][8][4];
#pragma unroll
    for (int i = 0; i < 2; i++)
#pragma unroll
        for (int j = 0; j < 8; j++)
#pragma unroll
            for (int q = 0; q < 4; q++) acc[i][j][q] = 0.f;

    for (int kc = 0; kc < 5; ++kc) {
        int k0 = kc * 64;
        if (kc) __syncthreads();
#pragma unroll
        for (int s = 0; s < 4; s++) {
            int j = tid + s * 256;
            int r2 = j >> 3, i = j & 7;
            uint32_t off = sw128((uint32_t)(r2 * 128 + i * 16));
            CPA16(sb + TG_A_HI + off, g_Ah + (size_t)(m0 + r2) * 320 + k0 + i * 8);
            CPA16(sb + TG_A_LO + off, g_Al + (size_t)(m0 + r2) * 320 + k0 + i * 8);
        }
#pragma unroll
        for (int s = 0; s < 4; s++) {
            int j = tid + s * 256;
            int n = j >> 3, i = j & 7;
            uint32_t off = sw128((uint32_t)(n * 128 + i * 16));
            CPA16(sb + TG_B_HI + off, Wh + (n0 + n) * 320 + k0 + i * 8);
            CPA16(sb + TG_B_LO + off, Wl + (n0 + n) * 320 + k0 + i * 8);
        }
        CPA_COMMIT();
        CPA_WAIT0();
        __syncthreads();

#pragma unroll
        for (int ks = 0; ks < 4; ++ks) {
            uint32_t ah[2][4], al[2][4];
#pragma unroll
            for (int mt = 0; mt < 2; ++mt) {
                ldsm4(ah[mt], sb + TG_A_HI + a_soff[mt][ks]);
                ldsm4(al[mt], sb + TG_A_LO + a_soff[mt][ks]);
            }
            if (nact) {
#pragma unroll
                for (int np = 0; np < 4; ++np) {
                    uint32_t bh[4], bl[4];
                    ldsm4(bh, sb + TG_B_HI + b_soff[np][ks]);
                    ldsm4(bl, sb + TG_B_LO + b_soff[np][ks]);
#pragma unroll
                    for (int mt = 0; mt < 2; ++mt)
#pragma unroll
                        for (int h = 0; h < 2; ++h) {
                            float* d = acc[mt][np * 2 + h];
                            mma_bf(d, ah[mt], bh + h * 2);
                            mma_bf(d, ah[mt], bl + h * 2);
                            mma_bf(d, al[mt], bh + h * 2);
                        }
                }
            }
        }
    }

    int orow = m0 + wm * 32 + (lane >> 2);
    int oc0  = n0 + wn * 64 + (lane & 3) * 2;
#pragma unroll
    for (int mt = 0; mt < 2; ++mt)
#pragma unroll
        for (int nt = 0; nt < 8; ++nt) {
            int col = oc0 + nt * 8;
            if (col >= HIDN) continue;
#pragma unroll
            for (int h = 0; h < 2; ++h) {
                int row = orow + mt * 16 + h * 8;
                *reinterpret_cast<float2*>(tout + row * HIDN + col) =
                    make_float2(acc[mt][nt][h * 2], acc[mt][nt][h * 2 + 1]);
            }
        }
}

// =====================================================================
// Init GEMM: A = [x[row]|ea] (K=80 -> 2 chunks), epilogue h0 fp32 + bf16 split
// =====================================================================
__global__ void __launch_bounds__(256, 2) k_tginit(
    const int* __restrict__ rowi, const float* __restrict__ bvec,
    const float* __restrict__ x, const float* __restrict__ ea)
{
    extern __shared__ char smem[];
    uint32_t sb = smem_u32(smem);
    int tid = threadIdx.x;
    int lane = tid & 31;
    int wid = tid >> 5;
    int m0 = blockIdx.y * 128;
    int n0 = blockIdx.x * 128;

    int r = tid >> 1;
    int e = m0 + r;
    int cc0 = (tid & 1) * 32;
    int rv = rowi[e];

    int wm = wid >> 1, wn = wid & 1;
    int mat = lane >> 3, l7 = lane & 7;
    int a_row = wm * 32 + (mat & 1) * 8 + l7;
    int a_kof = (mat >> 1) * 8;
    int b_base = wn * 64 + (mat >> 1) * 8 + l7;
    int b_kof = (mat & 1) * 8;
    bool nact = (n0 + wn * 64) < HIDN;

    float acc[2][8][4];
#pragma unroll
    for (int i = 0; i < 2; i++)
#pragma unroll
        for (int j = 0; j < 8; j++)
#pragma unroll
            for (int q = 0; q < 4; q++) acc[i][j][q] = 0.f;

    for (int kc = 0; kc < 2; ++kc) {
        int k0 = kc * 64;
        if (kc) __syncthreads();
#pragma unroll
        for (int s = 0; s < 4; s++) {
            int j = tid + s * 256;
            int n = j >> 3, i = j & 7;
            uint32_t off = sw128((uint32_t)(n * 128 + i * 16));
            CPA16(sb + TG_B_HI + off, g_WIh + (n0 + n) * 320 + k0 + i * 8);
            CPA16(sb + TG_B_LO + off, g_WIl + (n0 + n) * 320 + k0 + i * 8);
        }
        CPA_COMMIT();
#pragma unroll
        for (int i = 0; i < 8; i++) {
            int cc = cc0 + i * 4;
            int k = k0 + cc;
            float4 v = make_float4(0.f, 0.f, 0.f, 0.f);
            if (k < FNODE)    v = ld4(x + rv * FNODE + k);
            else if (k < 80)  v = ld4(ea + e * FEDGE + (k - FNODE));
            uint32_t h0w, l0w, h1w, l1w;
            split_pack(v.x, v.y, h0w, l0w);
            split_pack(v.z, v.w, h1w, l1w);
            uint32_t off = sw128((uint32_t)(r * 128 + cc * 2));
            *reinterpret_cast<uint2*>(smem + TG_A_HI + off) = make_uint2(h0w, h1w);
            *reinterpret_cast<uint2*>(smem + TG_A_LO + off) = make_uint2(l0w, l1w);
        }
        CPA_WAIT0();
        __syncthreads();
#pragma unroll
        for (int ks = 0; ks < 4; ++ks) {
            uint32_t ah[2][4], al[2][4];
#pragma unroll
            for (int mt = 0; mt < 2; ++mt) {
                uint32_t off = sw128((uint32_t)(((a_row + mt * 16) << 7) +
                                                ((ks * 16 + a_kof) << 1)));
                ldsm4(ah[mt], sb + TG_A_HI + off);
                ldsm4(al[mt], sb + TG_A_LO + off);
            }
            if (nact) {
#pragma unroll
                for (int np = 0; np < 4; ++np) {
                    uint32_t boff = sw128((uint32_t)(((b_base + np * 16) << 7) +
                                                     ((ks * 16 + b_kof) << 1)));
                    uint32_t bh[4], bl[4];
                    ldsm4(bh, sb + TG_B_HI + boff);
                    ldsm4(bl, sb + TG_B_LO + boff);
#pragma unroll
                    for (int mt = 0; mt < 2; ++mt)
#pragma unroll
                        for (int h = 0; h < 2; ++h) {
                            float* d = acc[mt][np * 2 + h];
                            mma_bf(d, ah[mt], bh + h * 2);
                            mma_bf(d, ah[mt], bl + h * 2);
                            mma_bf(d, al[mt], bh + h * 2);
                        }
                }
            }
        }
    }

    int orow = m0 + wm * 32 + (lane >> 2);
    int oc0  = n0 + wn * 64 + (lane & 3) * 2;
#pragma unroll
    for (int mt = 0; mt < 2; ++mt)
#pragma unroll
        for (int nt = 0; nt < 8; ++nt) {
            int col = oc0 + nt * 8;
            if (col >= 320) continue;
            bool live = col < HIDN;
            float b0 = live ? bvec[col] : 0.f;
            float b1 = live ? bvec[col + 1] : 0.f;
#pragma unroll
            for (int h = 0; h < 2; ++h) {
                int row = orow + mt * 16 + h * 8;
                float v0 = live ? frelu(acc[mt][nt][h * 2] + b0) : 0.f;
                float v1 = live ? frelu(acc[mt][nt][h * 2 + 1] + b1) : 0.f;
                if (live)
                    *reinterpret_cast<float2*>(g_h0 + row * HIDN + col) = make_float2(v0, v1);
                uint32_t hw, lw;
                split_pack(v0, v1, hw, lw);
                *reinterpret_cast<uint32_t*>(g_Ah + (size_t)row * 320 + col) = hw;
                *reinterpret_cast<uint32_t*>(g_Al + (size_t)row * 320 + col) = lw;
            }
        }
}

// =====================================================================
// Node GEMM (tensor): hn = relu([x|s] @ W_e2n + be); pool += hn
// =====================================================================
__global__ void __launch_bounds__(256, 2) k_tgnode(
    const int* __restrict__ batch, const float* __restrict__ bvec,
    const float* __restrict__ x)
{
    extern __shared__ char smem[];
    uint32_t sb = smem_u32(smem);
    int tid = threadIdx.x;
    int lane = tid & 31;
    int wid = tid >> 5;
    int m0 = blockIdx.y * 128;
    int n0 = blockIdx.x * 128;

    int r = tid >> 1;
    int e = m0 + r;
    bool eok = (e < NNODES);
    int es = eok ? e : 0;
    int cc0 = (tid & 1) * 32;

    int wm = wid >> 1, wn = wid & 1;
    int mat = lane >> 3, l7 = lane & 7;
    int a_row = wm * 32 + (mat & 1) * 8 + l7;
    int a_kof = (mat >> 1) * 8;
    int b_base = wn * 64 + (mat >> 1) * 8 + l7;
    int b_kof = (mat & 1) * 8;
    bool nact = (n0 + wn * 64) < HIDN;

    const int KTOT = FNODE + HIDN;  // 364

    float acc[2][8][4];
#pragma unroll
    for (int i = 0; i < 2; i++)
#pragma unroll
        for (int j = 0; j < 8; j++)
#pragma unroll
            for (int q = 0; q < 4; q++) acc[i][j][q] = 0.f;

    for (int kc = 0; kc < 6; ++kc) {
        int k0 = kc * 64;
        if (kc) __syncthreads();
#pragma unroll
        for (int s = 0; s < 4; s++) {
            int j = tid + s * 256;
            int n = j >> 3, i = j & 7;
            uint32_t off = sw128((uint32_t)(n * 128 + i * 16));
            CPA16(sb + TG_B_HI + off, g_WNh + (n0 + n) * 384 + k0 + i * 8);
            CPA16(sb + TG_B_LO + off, g_WNl + (n0 + n) * 384 + k0 + i * 8);
        }
        CPA_COMMIT();
#pragma unroll
        for (int i = 0; i < 8; i++) {
            int cc = cc0 + i * 4;
            int k = k0 + cc;
            float4 v = make_float4(0.f, 0.f, 0.f, 0.f);
            if (eok && k < KTOT)
                v = (k < FNODE) ? ld4(x + es * FNODE + k)
                                : ld4(g_s + es * HIDN + (k - FNODE));
            uint32_t h0w, l0w, h1w, l1w;
            split_pack(v.x, v.y, h0w, l0w);
            split_pack(v.z, v.w, h1w, l1w);
            uint32_t off = sw128((uint32_t)(r * 128 + cc * 2));
            *reinterpret_cast<uint2*>(smem + TG_A_HI + off) = make_uint2(h0w, h1w);
            *reinterpret_cast<uint2*>(smem + TG_A_LO + off) = make_uint2(l0w, l1w);
        }
        CPA_WAIT0();
        __syncthreads();
#pragma unroll
        for (int ks = 0; ks < 4; ++ks) {
            uint32_t ah[2][4], al[2][4];
#pragma unroll
            for (int mt = 0; mt < 2; ++mt) {
                uint32_t off = sw128((uint32_t)(((a_row + mt * 16) << 7) +
                                                ((ks * 16 + a_kof) << 1)));
                ldsm4(ah[mt], sb + TG_A_HI + off);
                ldsm4(al[mt], sb + TG_A_LO + off);
            }
            if (nact) {
#pragma unroll
                for (int np = 0; np < 4; ++np) {
                    uint32_t boff = sw128((uint32_t)(((b_base + np * 16) << 7) +
                                                     ((ks * 16 + b_kof) << 1)));
                    uint32_t bh[4], bl[4];
                    ldsm4(bh, sb + TG_B_HI + boff);
                    ldsm4(bl, sb + TG_B_LO + boff);
#pragma unroll
                    for (int mt = 0; mt < 2; ++mt)
#pragma unroll
                        for (int h = 0; h < 2; ++h) {
                            float* d = acc[mt][np * 2 + h];
                            mma_bf(d, ah[mt], bh + h * 2);
                            mma_bf(d, ah[mt], bl + h * 2);
                            mma_bf(d, al[mt], bh + h * 2);
                        }
                }
            }
        }
    }

    int orow = m0 + wm * 32 + (lane >> 2);
    int oc0  = n0 + wn * 64 + (lane & 3) * 2;
#pragma unroll
    for (int mt = 0; mt < 2; ++mt)
#pragma unroll
        for (int nt = 0; nt < 8; ++nt) {
            int col = oc0 + nt * 8;
            if (col >= HIDN) continue;
            float b0 = bvec[col], b1 = bvec[col + 1];
#pragma unroll
            for (int h = 0; h < 2; ++h) {
                int row = orow + mt * 16 + h * 8;
                if (row >= NNODES) continue;
                float* p = g_pool + batch[row] * HIDN + col;
                atomicAdd(p + 0, frelu(acc[mt][nt][h * 2] + b0));
                atomicAdd(p + 1, frelu(acc[mt][nt][h * 2 + 1] + b1));
            }
        }
}

// ---------------- FFN ----------------
__global__ void k_ffn(const float* __restrict__ Wf, const float* __restrict__ bf,
                      float* __restrict__ out) {
    int g = blockIdx.x;
    int lane = threadIdx.x;
    float s = 0.f;
    for (int k = lane; k < HIDN; k += 32) s += g_pool[g * HIDN + k] * Wf[k];
#pragma unroll
    for (int o = 16; o; o >>= 1) s += __shfl_xor_sync(0xffffffffu, s, o);
    if (lane == 0) out[g] = s + bf[0];
}

// ---------------- entry ----------------
extern "C" void kernel_launch(void* const* d_in, const int* in_sizes, int n_in,
                              void* d_out, int out_size) {
    const float* x     = (const float*)d_in[0];
    const float* ea    = (const float*)d_in[1];
    const int*   ei    = (const int*)d_in[2];
    const int*   rowi  = ei;
    const int*   coli  = ei + NEDGES;
    const int*   batch = (const int*)d_in[3];
    const float* Wi    = (const float*)d_in[4];
    const float* bi    = (const float*)d_in[5];
    const float* Wc    = (const float*)d_in[6];
    const float* bc    = (const float*)d_in[7];
    const float* We    = (const float*)d_in[8];
    const float* be    = (const float*)d_in[9];
    const float* Wf    = (const float*)d_in[10];
    const float* bf    = (const float*)d_in[11];
    float* out = (float*)d_out;

    cudaFuncSetAttribute(k_cgemm,  cudaFuncAttributeMaxDynamicSharedMemorySize, TG_TOTAL);
    cudaFuncSetAttribute(k_tginit, cudaFuncAttributeMaxDynamicSharedMemorySize, TG_TOTAL);
    cudaFuncSetAttribute(k_tgnode, cudaFuncAttributeMaxDynamicSharedMemorySize, TG_TOTAL);

    dim3 gT(3, NEDGES / 128);
    dim3 gN(3, (NNODES + 127) / 128);
    int ssB = (NNODES * 75 + 255) / 256;

    k_pre<<<1440, 256>>>(Wc, Wi, We);                   // 1
    k_hist<<<NEDGES / 256, 256>>>(coli);                // 2
    k_tginit<<<gT, 256, TG_TOTAL>>>(rowi, bi, x, ea);   // 3: h0 + A bf16
    k_cgemm<<<gT, 256, TG_TOTAL>>>(0, 1);               // 4: t0  <- profiled
    k_scan<<<1, 1024>>>();                              // 5
    k_scatter<<<NEDGES / 256, 256>>>(coli);             // 6

    k_seghm<<<ssB, 256>>>(1, bc);                       // u0 (regs) + A = h1 bf16
    k_cgemm<<<gT, 256, TG_TOTAL>>>(1, 2);               // t1
    k_seghm<<<ssB, 256>>>(2, bc + HIDN);                // u1 (regs) + A = h2 bf16
    k_cgemm<<<gT, 256, TG_TOTAL>>>(2, 1);               // t2
    k_segsum<<<ssB, 256>>>(1);                          // u2 -> g_a
    k_segsum_h3<<<ssB, 256>>>(1, bc + 2 * HIDN, rowi);  // s (fused h3+segsum)

    k_tgnode<<<gN, 256, TG_TOTAL>>>(batch, be, x);      // node GEMM + pool
    k_ffn<<<NGRAPH, 32>>>(Wf, bf, out);
}

// round 14
// speedup vs baseline: 1.4307x; 1.2598x over previous
#include <cuda_runtime.h>
#include <cuda_bf16.h>
#include <cuda_fp16.h>
#include <cstdint>

#define NNODES 20000
#define NEDGES 320000
#define FNODE  64
#define FEDGE  16
#define HIDN   300
#define NGRAPH 128

typedef unsigned long long ull;

// ---------------- scratch (device globals) ----------------
__device__ float g_h0[NEDGES * HIDN];
__device__ float g_hA[NEDGES * HIDN];          // t ping
__device__ float g_hB[NEDGES * HIDN];          // t pong
__device__ __half g_Af[NEDGES * 320];          // A operand fp16 (current layer)
__device__ float g_a [NNODES * HIDN];          // u2
__device__ float g_s [NNODES * HIDN];          // final node message
__device__ float g_pool[NGRAPH * HIDN];
__device__ __half g_Wh [3 * 384 * 320];        // conv W^T fp16 hi [l][n][k]
__device__ __half g_Wl [3 * 384 * 320];        // conv W^T fp16 lo
__device__ __half g_WIh[384 * 320];            // init W^T hi
__device__ __half g_WIl[384 * 320];
__device__ __half g_WNh[384 * 384];            // e2n W^T hi [n][k]
__device__ __half g_WNl[384 * 384];
__device__ int g_cnt [NNODES];
__device__ int g_ptr [NNODES + 1];
__device__ int g_fill[NNODES];
__device__ int g_eid [NEDGES];

__device__ __forceinline__ float* hbuf(int s) {
    return (s == 0) ? g_h0 : ((s == 1) ? g_hA : g_hB);
}

// ---------------- helpers ----------------
__device__ __forceinline__ float4 ld4(const float* p) { return *reinterpret_cast<const float4*>(p); }
__device__ __forceinline__ void   st4(float* p, float4 v) { *reinterpret_cast<float4*>(p) = v; }
__device__ __forceinline__ float  frelu(float x) { return x > 0.f ? x : 0.f; }

__device__ __forceinline__ uint32_t smem_u32(const void* p) {
    uint32_t a;
    asm("{ .reg .u64 t; cvta.to.shared.u64 t, %1; cvt.u32.u64 %0, t; }" : "=r"(a) : "l"(p));
    return a;
}
__device__ __forceinline__ uint32_t sw128(uint32_t o) { return o ^ ((o >> 3) & 0x70); }

__device__ __forceinline__ void ldsm4(uint32_t* r, uint32_t a) {
    asm volatile("ldmatrix.sync.aligned.m8n8.x4.shared.b16 {%0,%1,%2,%3}, [%4];"
                 : "=r"(r[0]), "=r"(r[1]), "=r"(r[2]), "=r"(r[3]) : "r"(a));
}
__device__ __forceinline__ void mma_f16(float* d, const uint32_t* a, const uint32_t* b) {
    asm volatile("mma.sync.aligned.m16n8k16.row.col.f32.f16.f16.f32 "
                 "{%0,%1,%2,%3}, {%4,%5,%6,%7}, {%8,%9}, {%0,%1,%2,%3};"
                 : "+f"(d[0]), "+f"(d[1]), "+f"(d[2]), "+f"(d[3])
                 : "r"(a[0]), "r"(a[1]), "r"(a[2]), "r"(a[3]), "r"(b[0]), "r"(b[1]));
}
#define CPA16(dst, src) asm volatile("cp.async.cg.shared.global [%0], [%1], 16;" :: "r"(dst), "l"(src))
#define CPA_COMMIT()    asm volatile("cp.async.commit_group;" ::: "memory")
#define CPA_WAIT0()     asm volatile("cp.async.wait_group 0;" ::: "memory")

__device__ __forceinline__ uint2 pack4h(float4 v) {
    __half2 a = __floats2half2_rn(v.x, v.y);
    __half2 b = __floats2half2_rn(v.z, v.w);
    return make_uint2(*reinterpret_cast<uint32_t*>(&a), *reinterpret_cast<uint32_t*>(&b));
}

// ---------------- preprocessing ----------------
__global__ void k_pre(const float* __restrict__ Wc, const float* __restrict__ Wi,
                      const float* __restrict__ We) {
    int t = blockIdx.x * blockDim.x + threadIdx.x;
    if (t < NNODES) g_cnt[t] = 0;
    if (t < NGRAPH * HIDN) g_pool[t] = 0.f;
    if (t < 122880) {
        int n = t / 320, k = t % 320;
        float v = (n < HIDN && k < 80) ? Wi[k * HIDN + n] : 0.f;
        __half hh = __float2half(v);
        g_WIh[t] = hh;
        g_WIl[t] = __float2half(v - __half2float(hh));
    }
    if (t < 3 * 122880) {
        int l = t / 122880, r2 = t % 122880;
        int n = r2 / 320, k = r2 % 320;
        float v = (n < HIDN && k < HIDN) ? Wc[l * HIDN * HIDN + k * HIDN + n] : 0.f;
        __half hh = __float2half(v);
        g_Wh[t] = hh;
        g_Wl[t] = __float2half(v - __half2float(hh));
    }
    if (t < 384 * 384) {
        int n = t / 384, k = t % 384;
        float v = (n < HIDN && k < FNODE + HIDN) ? We[k * HIDN + n] : 0.f;
        __half hh = __float2half(v);
        g_WNh[t] = hh;
        g_WNl[t] = __float2half(v - __half2float(hh));
    }
}

__global__ void k_hist(const int* __restrict__ coli) {
    int e = blockIdx.x * blockDim.x + threadIdx.x;
    if (e < NEDGES) atomicAdd(&g_cnt[coli[e]], 1);
}

// fast single-block scan: 1024 threads x 20 elems, shuffle-based
__global__ void k_scan() {
    __shared__ int wsum[32];
    int tid = threadIdx.x;
    int lane = tid & 31, wid = tid >> 5;
    const int PER = 20;
    int base = tid * PER;
    int v[PER];
    int s = 0;
#pragma unroll
    for (int i = 0; i < PER; ++i) {
        int idx = base + i;
        v[i] = (idx < NNODES) ? g_cnt[idx] : 0;
        s += v[i];
    }
    int ws = s;
#pragma unroll
    for (int off = 1; off < 32; off <<= 1) {
        int t = __shfl_up_sync(0xffffffffu, ws, off);
        if (lane >= off) ws += t;
    }
    if (lane == 31) wsum[wid] = ws;
    __syncthreads();
    if (wid == 0) {
        int w = wsum[lane];
#pragma unroll
        for (int off = 1; off < 32; off <<= 1) {
            int t = __shfl_up_sync(0xffffffffu, w, off);
            if (lane >= off) w += t;
        }
        wsum[lane] = w;
    }
    __syncthreads();
    int warp_off = (wid > 0) ? wsum[wid - 1] : 0;
    int run = warp_off + ws - s;
#pragma unroll
    for (int i = 0; i < PER; ++i) {
        int idx = base + i;
        if (idx < NNODES) { g_ptr[idx] = run; g_fill[idx] = run; }
        run += v[i];
    }
    if (tid == 0) g_ptr[NNODES] = wsum[31];
}

__global__ void k_scatter(const int* __restrict__ coli) {
    int e = blockIdx.x * blockDim.x + threadIdx.x;
    if (e < NEDGES) {
        int pos = atomicAdd(&g_fill[coli[e]], 1);
        g_eid[pos] = e;
    }
}

// ---------------- segment sum: g_a[n] = sum t[e] (u2 only) ----------------
__global__ void k_segsum(int src_sel) {
    const float* h = hbuf(src_sel);
    int t = blockIdx.x * blockDim.x + threadIdx.x;
    if (t >= NNODES * 75) return;
    int n = t / 75;
    int c = (t - n * 75) * 4;
    int beg = g_ptr[n], end = g_ptr[n + 1];
    float4 acc = make_float4(0.f, 0.f, 0.f, 0.f);
#pragma unroll 2
    for (int i = beg; i < end; ++i) {
        int e = g_eid[i];
        float4 vv = ld4(h + e * HIDN + c);
        acc.x += vv.x; acc.y += vv.y; acc.z += vv.z; acc.w += vv.w;
    }
    st4(g_a + n * HIDN + c, acc);
}

// ------ fused segsum + next-h materialize (paired-edge identity) --------
__global__ void k_seghm(int t_sel, const float* __restrict__ bc) {
    const float* tp = hbuf(t_sel);
    int t = blockIdx.x * blockDim.x + threadIdx.x;
    if (t >= NNODES * 75) return;
    int n = t / 75;
    int c = (t - n * 75) * 4;
    float4 bv = ld4(bc + c);
    int beg = g_ptr[n], end = g_ptr[n + 1];
    float4 u = make_float4(0.f, 0.f, 0.f, 0.f);
#pragma unroll 2
    for (int i = beg; i < end; ++i) {
        int e = g_eid[i];
        float4 vv = ld4(tp + e * HIDN + c);
        u.x += vv.x; u.y += vv.y; u.z += vv.z; u.w += vv.w;
    }
#pragma unroll 2
    for (int i = beg; i < end; ++i) {
        int e = g_eid[i];
        int er = e ^ 1;
        float4 tv  = ld4(tp + e * HIDN + c);
        float4 h0v = ld4(g_h0 + er * HIDN + c);
        float4 v;
        v.x = frelu(h0v.x + bv.x + u.x - tv.x);
        v.y = frelu(h0v.y + bv.y + u.y - tv.y);
        v.z = frelu(h0v.z + bv.z + u.z - tv.z);
        v.w = frelu(h0v.w + bv.w + u.w - tv.w);
        *reinterpret_cast<uint2*>(g_Af + (size_t)er * 320 + c) = pack4h(v);
    }
}

// --------- fused final: g_s[n] = sum_e relu(h0[e]+bc2+u2[row[e]]-rev(t2)) ----
__global__ void k_segsum_h3(int t2_sel, const float* __restrict__ bc2,
                            const int* __restrict__ rowi) {
    const float* t2 = hbuf(t2_sel);
    int t = blockIdx.x * blockDim.x + threadIdx.x;
    if (t >= NNODES * 75) return;
    int n = t / 75;
    int c = (t - n * 75) * 4;
    float4 bv = ld4(bc2 + c);
    int beg = g_ptr[n], end = g_ptr[n + 1];
    float4 acc = make_float4(0.f, 0.f, 0.f, 0.f);
#pragma unroll 2
    for (int i = beg; i < end; ++i) {
        int e = g_eid[i];
        float4 h0v = ld4(g_h0 + e * HIDN + c);
        float4 uv  = ld4(g_a + rowi[e] * HIDN + c);
        float4 tv  = ld4(t2 + (e ^ 1) * HIDN + c);
        acc.x += frelu(h0v.x + bv.x + uv.x - tv.x);
        acc.y += frelu(h0v.y + bv.y + uv.y - tv.y);
        acc.z += frelu(h0v.z + bv.z + uv.z - tv.z);
        acc.w += frelu(h0v.w + bv.w + uv.w - tv.w);
    }
    st4(g_s + n * HIDN + c, acc);
}

// =====================================================================
// Conv GEMM (fp16 2-pass): t_out = A @ (Wh + Wl), A fp16 single.
// CTA 128m x 128n, 8 warps (4m x 2n), K=320 in 5 chunks of 64, SW128,
// cp.async commit+wait0, 2 CTAs/SM. smem: A 16K + Bh 16K + Bl 16K = 48K.
// =====================================================================
#define TG_A   0
#define TG_BH  16384
#define TG_BL  32768
#define TG_TOTAL 49152

__global__ void __launch_bounds__(256, 2) k_cgemm(int layer, int out_sel) {
    extern __shared__ char smem[];
    uint32_t sb = smem_u32(smem);
    int tid = threadIdx.x;
    int lane = tid & 31;
    int wid = tid >> 5;
    int m0 = blockIdx.y * 128;
    int n0 = blockIdx.x * 128;

    const __half* Wh = g_Wh + layer * 122880;
    const __half* Wl = g_Wl + layer * 122880;
    float* tout = hbuf(out_sel);

    int wm = wid >> 1, wn = wid & 1;
    int mat = lane >> 3, l7 = lane & 7;
    int a_row = wm * 32 + (mat & 1) * 8 + l7;
    int a_kof = (mat >> 1) * 8;
    int b_base = wn * 64 + (mat >> 1) * 8 + l7;
    int b_kof = (mat & 1) * 8;
    bool nact = (n0 + wn * 64) < HIDN;

    uint32_t a_soff[2][4], b_soff[4][4];
#pragma unroll
    for (int mt = 0; mt < 2; ++mt)
#pragma unroll
        for (int ks = 0; ks < 4; ++ks)
            a_soff[mt][ks] = sw128((uint32_t)(((a_row + mt * 16) << 7) +
                                              ((ks * 16 + a_kof) << 1)));
#pragma unroll
    for (int np = 0; np < 4; ++np)
#pragma unroll
        for (int ks = 0; ks < 4; ++ks)
            b_soff[np][ks] = sw128((uint32_t)(((b_base + np * 16) << 7) +
                                              ((ks * 16 + b_kof) << 1)));

    float acc[2][8][4];
#pragma unroll
    for (int i = 0; i < 2; i++)
#pragma unroll
        for (int j = 0; j < 8; j++)
#pragma unroll
            for (int q = 0; q < 4; q++) acc[i][j][q] = 0.f;

    for (int kc = 0; kc < 5; ++kc) {
        int k0 = kc * 64;
        if (kc) __syncthreads();
        // A: 128 rows x 64 k fp16 = 16KB -> 1024 x 16B, 4 iters
#pragma unroll
        for (int s = 0; s < 4; s++) {
            int j = tid + s * 256;
            int r2 = j >> 3, i = j & 7;
            uint32_t off = sw128((uint32_t)(r2 * 128 + i * 16));
            CPA16(sb + TG_A + off, g_Af + (size_t)(m0 + r2) * 320 + k0 + i * 8);
        }
        // B hi + lo
#pragma unroll
        for (int s = 0; s < 4; s++) {
            int j = tid + s * 256;
            int n = j >> 3, i = j & 7;
            uint32_t off = sw128((uint32_t)(n * 128 + i * 16));
            CPA16(sb + TG_BH + off, Wh + (n0 + n) * 320 + k0 + i * 8);
            CPA16(sb + TG_BL + off, Wl + (n0 + n) * 320 + k0 + i * 8);
        }
        CPA_COMMIT();
        CPA_WAIT0();
        __syncthreads();

#pragma unroll
        for (int ks = 0; ks < 4; ++ks) {
            uint32_t af[2][4];
#pragma unroll
            for (int mt = 0; mt < 2; ++mt)
                ldsm4(af[mt], sb + TG_A + a_soff[mt][ks]);
            if (nact) {
#pragma unroll
                for (int np = 0; np < 4; ++np) {
                    uint32_t bh[4], bl[4];
                    ldsm4(bh, sb + TG_BH + b_soff[np][ks]);
                    ldsm4(bl, sb + TG_BL + b_soff[np][ks]);
#pragma unroll
                    for (int mt = 0; mt < 2; ++mt)
#pragma unroll
                        for (int h = 0; h < 2; ++h) {
                            float* d = acc[mt][np * 2 + h];
                            mma_f16(d, af[mt], bh + h * 2);
                            mma_f16(d, af[mt], bl + h * 2);
                        }
                }
            }
        }
    }

    int orow = m0 + wm * 32 + (lane >> 2);
    int oc0  = n0 + wn * 64 + (lane & 3) * 2;
#pragma unroll
    for (int mt = 0; mt < 2; ++mt)
#pragma unroll
        for (int nt = 0; nt < 8; ++nt) {
            int col = oc0 + nt * 8;
            if (col >= HIDN) continue;
#pragma unroll
            for (int h = 0; h < 2; ++h) {
                int row = orow + mt * 16 + h * 8;
                *reinterpret_cast<float2*>(tout + row * HIDN + col) =
                    make_float2(acc[mt][nt][h * 2], acc[mt][nt][h * 2 + 1]);
            }
        }
}

// =====================================================================
// Init GEMM (fp16 2-pass): A = [x[row]|ea], K=80 -> 2 chunks.
// Epilogue: h0 = relu(acc+bias) -> g_h0 fp32 AND g_Af fp16.
// =====================================================================
__global__ void __launch_bounds__(256, 2) k_tginit(
    const int* __restrict__ rowi, const float* __restrict__ bvec,
    const float* __restrict__ x, const float* __restrict__ ea)
{
    extern __shared__ char smem[];
    uint32_t sb = smem_u32(smem);
    int tid = threadIdx.x;
    int lane = tid & 31;
    int wid = tid >> 5;
    int m0 = blockIdx.y * 128;
    int n0 = blockIdx.x * 128;

    int r = tid >> 1;
    int e = m0 + r;
    int cc0 = (tid & 1) * 32;
    int rv = rowi[e];

    int wm = wid >> 1, wn = wid & 1;
    int mat = lane >> 3, l7 = lane & 7;
    int a_row = wm * 32 + (mat & 1) * 8 + l7;
    int a_kof = (mat >> 1) * 8;
    int b_base = wn * 64 + (mat >> 1) * 8 + l7;
    int b_kof = (mat & 1) * 8;
    bool nact = (n0 + wn * 64) < HIDN;

    float acc[2][8][4];
#pragma unroll
    for (int i = 0; i < 2; i++)
#pragma unroll
        for (int j = 0; j < 8; j++)
#pragma unroll
            for (int q = 0; q < 4; q++) acc[i][j][q] = 0.f;

    for (int kc = 0; kc < 2; ++kc) {
        int k0 = kc * 64;
        if (kc) __syncthreads();
#pragma unroll
        for (int s = 0; s < 4; s++) {
            int j = tid + s * 256;
            int n = j >> 3, i = j & 7;
            uint32_t off = sw128((uint32_t)(n * 128 + i * 16));
            CPA16(sb + TG_BH + off, g_WIh + (n0 + n) * 320 + k0 + i * 8);
            CPA16(sb + TG_BL + off, g_WIl + (n0 + n) * 320 + k0 + i * 8);
        }
        CPA_COMMIT();
#pragma unroll
        for (int i = 0; i < 8; i++) {
            int cc = cc0 + i * 4;
            int k = k0 + cc;
            float4 v = make_float4(0.f, 0.f, 0.f, 0.f);
            if (k < FNODE)    v = ld4(x + rv * FNODE + k);
            else if (k < 80)  v = ld4(ea + e * FEDGE + (k - FNODE));
            uint32_t off = sw128((uint32_t)(r * 128 + cc * 2));
            *reinterpret_cast<uint2*>(smem + TG_A + off) = pack4h(v);
        }
        CPA_WAIT0();
        __syncthreads();
#pragma unroll
        for (int ks = 0; ks < 4; ++ks) {
            uint32_t af[2][4];
#pragma unroll
            for (int mt = 0; mt < 2; ++mt) {
                uint32_t off = sw128((uint32_t)(((a_row + mt * 16) << 7) +
                                                ((ks * 16 + a_kof) << 1)));
                ldsm4(af[mt], sb + TG_A + off);
            }
            if (nact) {
#pragma unroll
                for (int np = 0; np < 4; ++np) {
                    uint32_t boff = sw128((uint32_t)(((b_base + np * 16) << 7) +
                                                     ((ks * 16 + b_kof) << 1)));
                    uint32_t bh[4], bl[4];
                    ldsm4(bh, sb + TG_BH + boff);
                    ldsm4(bl, sb + TG_BL + boff);
#pragma unroll
                    for (int mt = 0; mt < 2; ++mt)
#pragma unroll
                        for (int h = 0; h < 2; ++h) {
                            float* d = acc[mt][np * 2 + h];
                            mma_f16(d, af[mt], bh + h * 2);
                            mma_f16(d, af[mt], bl + h * 2);
                        }
                }
            }
        }
    }

    int orow = m0 + wm * 32 + (lane >> 2);
    int oc0  = n0 + wn * 64 + (lane & 3) * 2;
#pragma unroll
    for (int mt = 0; mt < 2; ++mt)
#pragma unroll
        for (int nt = 0; nt < 8; ++nt) {
            int col = oc0 + nt * 8;
            if (col >= 320) continue;
            bool live = col < HIDN;
            float b0 = live ? bvec[col] : 0.f;
            float b1 = live ? bvec[col + 1] : 0.f;
#pragma unroll
            for (int h = 0; h < 2; ++h) {
                int row = orow + mt * 16 + h * 8;
                float v0 = live ? frelu(acc[mt][nt][h * 2] + b0) : 0.f;
                float v1 = live ? frelu(acc[mt][nt][h * 2 + 1] + b1) : 0.f;
                if (live)
                    *reinterpret_cast<float2*>(g_h0 + row * HIDN + col) = make_float2(v0, v1);
                __half2 p = __floats2half2_rn(v0, v1);
                *reinterpret_cast<uint32_t*>(g_Af + (size_t)row * 320 + col) =
                    *reinterpret_cast<uint32_t*>(&p);
            }
        }
}

// =====================================================================
// Node GEMM (fp16 2-pass): hn = relu([x|s] @ W_e2n + be); pool += hn
// =====================================================================
__global__ void __launch_bounds__(256, 2) k_tgnode(
    const int* __restrict__ batch, const float* __restrict__ bvec,
    const float* __restrict__ x)
{
    extern __shared__ char smem[];
    uint32_t sb = smem_u32(smem);
    int tid = threadIdx.x;
    int lane = tid & 31;
    int wid = tid >> 5;
    int m0 = blockIdx.y * 128;
    int n0 = blockIdx.x * 128;

    int r = tid >> 1;
    int e = m0 + r;
    bool eok = (e < NNODES);
    int es = eok ? e : 0;
    int cc0 = (tid & 1) * 32;

    int wm = wid >> 1, wn = wid & 1;
    int mat = lane >> 3, l7 = lane & 7;
    int a_row = wm * 32 + (mat & 1) * 8 + l7;
    int a_kof = (mat >> 1) * 8;
    int b_base = wn * 64 + (mat >> 1) * 8 + l7;
    int b_kof = (mat & 1) * 8;
    bool nact = (n0 + wn * 64) < HIDN;

    const int KTOT = FNODE + HIDN;  // 364

    float acc[2][8][4];
#pragma unroll
    for (int i = 0; i < 2; i++)
#pragma unroll
        for (int j = 0; j < 8; j++)
#pragma unroll
            for (int q = 0; q < 4; q++) acc[i][j][q] = 0.f;

    for (int kc = 0; kc < 6; ++kc) {
        int k0 = kc * 64;
        if (kc) __syncthreads();
#pragma unroll
        for (int s = 0; s < 4; s++) {
            int j = tid + s * 256;
            int n = j >> 3, i = j & 7;
            uint32_t off = sw128((uint32_t)(n * 128 + i * 16));
            CPA16(sb + TG_BH + off, g_WNh + (n0 + n) * 384 + k0 + i * 8);
            CPA16(sb + TG_BL + off, g_WNl + (n0 + n) * 384 + k0 + i * 8);
        }
        CPA_COMMIT();
#pragma unroll
        for (int i = 0; i < 8; i++) {
            int cc = cc0 + i * 4;
            int k = k0 + cc;
            float4 v = make_float4(0.f, 0.f, 0.f, 0.f);
            if (eok && k < KTOT)
                v = (k < FNODE) ? ld4(x + es * FNODE + k)
                                : ld4(g_s + es * HIDN + (k - FNODE));
            uint32_t off = sw128((uint32_t)(r * 128 + cc * 2));
            *reinterpret_cast<uint2*>(smem + TG_A + off) = pack4h(v);
        }
        CPA_WAIT0();
        __syncthreads();
#pragma unroll
        for (int ks = 0; ks < 4; ++ks) {
            uint32_t af[2][4];
#pragma unroll
            for (int mt = 0; mt < 2; ++mt) {
                uint32_t off = sw128((uint32_t)(((a_row + mt * 16) << 7) +
                                                ((ks * 16 + a_kof) << 1)));
                ldsm4(af[mt], sb + TG_A + off);
            }
            if (nact) {
#pragma unroll
                for (int np = 0; np < 4; ++np) {
                    uint32_t boff = sw128((uint32_t)(((b_base + np * 16) << 7) +
                                                     ((ks * 16 + b_kof) << 1)));
                    uint32_t bh[4], bl[4];
                    ldsm4(bh, sb + TG_BH + boff);
                    ldsm4(bl, sb + TG_BL + boff);
#pragma unroll
                    for (int mt = 0; mt < 2; ++mt)
#pragma unroll
                        for (int h = 0; h < 2; ++h) {
                            float* d = acc[mt][np * 2 + h];
                            mma_f16(d, af[mt], bh + h * 2);
                            mma_f16(d, af[mt], bl + h * 2);
                        }
                }
            }
        }
    }

    int orow = m0 + wm * 32 + (lane >> 2);
    int oc0  = n0 + wn * 64 + (lane & 3) * 2;
#pragma unroll
    for (int mt = 0; mt < 2; ++mt)
#pragma unroll
        for (int nt = 0; nt < 8; ++nt) {
            int col = oc0 + nt * 8;
            if (col >= HIDN) continue;
            float b0 = bvec[col], b1 = bvec[col + 1];
#pragma unroll
            for (int h = 0; h < 2; ++h) {
                int row = orow + mt * 16 + h * 8;
                if (row >= NNODES) continue;
                float* p = g_pool + batch[row] * HIDN + col;
                atomicAdd(p + 0, frelu(acc[mt][nt][h * 2] + b0));
                atomicAdd(p + 1, frelu(acc[mt][nt][h * 2 + 1] + b1));
            }
        }
}

// ---------------- FFN ----------------
__global__ void k_ffn(const float* __restrict__ Wf, const float* __restrict__ bf,
                      float* __restrict__ out) {
    int g = blockIdx.x;
    int lane = threadIdx.x;
    float s = 0.f;
    for (int k = lane; k < HIDN; k += 32) s += g_pool[g * HIDN + k] * Wf[k];
#pragma unroll
    for (int o = 16; o; o >>= 1) s += __shfl_xor_sync(0xffffffffu, s, o);
    if (lane == 0) out[g] = s + bf[0];
}

// ---------------- entry ----------------
extern "C" void kernel_launch(void* const* d_in, const int* in_sizes, int n_in,
                              void* d_out, int out_size) {
    const float* x     = (const float*)d_in[0];
    const float* ea    = (const float*)d_in[1];
    const int*   ei    = (const int*)d_in[2];
    const int*   rowi  = ei;
    const int*   coli  = ei + NEDGES;
    const int*   batch = (const int*)d_in[3];
    const float* Wi    = (const float*)d_in[4];
    const float* bi    = (const float*)d_in[5];
    const float* Wc    = (const float*)d_in[6];
    const float* bc    = (const float*)d_in[7];
    const float* We    = (const float*)d_in[8];
    const float* be    = (const float*)d_in[9];
    const float* Wf    = (const float*)d_in[10];
    const float* bf    = (const float*)d_in[11];
    float* out = (float*)d_out;

    cudaFuncSetAttribute(k_cgemm,  cudaFuncAttributeMaxDynamicSharedMemorySize, TG_TOTAL);
    cudaFuncSetAttribute(k_tginit, cudaFuncAttributeMaxDynamicSharedMemorySize, TG_TOTAL);
    cudaFuncSetAttribute(k_tgnode, cudaFuncAttributeMaxDynamicSharedMemorySize, TG_TOTAL);

    dim3 gT(3, NEDGES / 128);
    dim3 gN(3, (NNODES + 127) / 128);
    int ssB = (NNODES * 75 + 255) / 256;

    k_pre<<<1440, 256>>>(Wc, Wi, We);                   // 1
    k_hist<<<NEDGES / 256, 256>>>(coli);                // 2
    k_tginit<<<gT, 256, TG_TOTAL>>>(rowi, bi, x, ea);   // 3: h0 + A fp16
    k_cgemm<<<gT, 256, TG_TOTAL>>>(0, 1);               // 4: t0  <- profiled
    k_scan<<<1, 1024>>>();                              // 5
    k_scatter<<<NEDGES / 256, 256>>>(coli);             // 6

    k_seghm<<<ssB, 256>>>(1, bc);                       // u0 (regs) + A = h1 fp16
    k_cgemm<<<gT, 256, TG_TOTAL>>>(1, 2);               // t1
    k_seghm<<<ssB, 256>>>(2, bc + HIDN);                // u1 (regs) + A = h2 fp16
    k_cgemm<<<gT, 256, TG_TOTAL>>>(2, 1);               // t2
    k_segsum<<<ssB, 256>>>(1);                          // u2 -> g_a
    k_segsum_h3<<<ssB, 256>>>(1, bc + 2 * HIDN, rowi);  // s (fused h3+segsum)

    k_tgnode<<<gN, 256, TG_TOTAL>>>(batch, be, x);      // node GEMM + pool
    k_ffn<<<NGRAPH, 32>>>(Wf, bf, out);
}

// round 15
// speedup vs baseline: 1.6992x; 1.1877x over previous
#include <cuda_runtime.h>
#include <cuda_bf16.h>
#include <cuda_fp16.h>
#include <cstdint>

#define NNODES 20000
#define NEDGES 320000
#define FNODE  64
#define FEDGE  16
#define HIDN   300
#define NGRAPH 128

typedef unsigned long long ull;

// ---------------- scratch (device globals) ----------------
__device__ float g_h0[NEDGES * HIDN];
__device__ float g_hA[NEDGES * HIDN];          // t ping
__device__ float g_hB[NEDGES * HIDN];          // t pong
__device__ __half g_Af[NEDGES * 320];          // A operand fp16 (current layer)
__device__ float g_a [NNODES * HIDN];          // u2
__device__ float g_s [NNODES * HIDN];          // final node message
__device__ float g_pool[NGRAPH * HIDN];
__device__ __half g_W [3 * 384 * 320];         // conv W^T fp16 [l][n][k]
__device__ __half g_WI[384 * 320];             // init W^T fp16
__device__ __half g_WN[384 * 384];             // e2n W^T fp16 [n][k]
__device__ int g_cnt [NNODES];
__device__ int g_ptr [NNODES + 1];
__device__ int g_fill[NNODES];
__device__ int g_eid [NEDGES];

__device__ __forceinline__ float* hbuf(int s) {
    return (s == 0) ? g_h0 : ((s == 1) ? g_hA : g_hB);
}

// ---------------- helpers ----------------
__device__ __forceinline__ float4 ld4(const float* p) { return *reinterpret_cast<const float4*>(p); }
__device__ __forceinline__ void   st4(float* p, float4 v) { *reinterpret_cast<float4*>(p) = v; }
__device__ __forceinline__ float  frelu(float x) { return x > 0.f ? x : 0.f; }

__device__ __forceinline__ uint32_t smem_u32(const void* p) {
    uint32_t a;
    asm("{ .reg .u64 t; cvta.to.shared.u64 t, %1; cvt.u32.u64 %0, t; }" : "=r"(a) : "l"(p));
    return a;
}
__device__ __forceinline__ uint32_t sw128(uint32_t o) { return o ^ ((o >> 3) & 0x70); }

__device__ __forceinline__ void ldsm4(uint32_t* r, uint32_t a) {
    asm volatile("ldmatrix.sync.aligned.m8n8.x4.shared.b16 {%0,%1,%2,%3}, [%4];"
                 : "=r"(r[0]), "=r"(r[1]), "=r"(r[2]), "=r"(r[3]) : "r"(a));
}
__device__ __forceinline__ void mma_f16(float* d, const uint32_t* a, const uint32_t* b) {
    asm volatile("mma.sync.aligned.m16n8k16.row.col.f32.f16.f16.f32 "
                 "{%0,%1,%2,%3}, {%4,%5,%6,%7}, {%8,%9}, {%0,%1,%2,%3};"
                 : "+f"(d[0]), "+f"(d[1]), "+f"(d[2]), "+f"(d[3])
                 : "r"(a[0]), "r"(a[1]), "r"(a[2]), "r"(a[3]), "r"(b[0]), "r"(b[1]));
}
#define CPA16(dst, src) asm volatile("cp.async.cg.shared.global [%0], [%1], 16;" :: "r"(dst), "l"(src))
#define CPA_COMMIT()    asm volatile("cp.async.commit_group;" ::: "memory")
#define CPA_WAIT0()     asm volatile("cp.async.wait_group 0;" ::: "memory")

__device__ __forceinline__ uint2 pack4h(float4 v) {
    __half2 a = __floats2half2_rn(v.x, v.y);
    __half2 b = __floats2half2_rn(v.z, v.w);
    return make_uint2(*reinterpret_cast<uint32_t*>(&a), *reinterpret_cast<uint32_t*>(&b));
}

// ---------------- preprocessing ----------------
__global__ void k_pre(const float* __restrict__ Wc, const float* __restrict__ Wi,
                      const float* __restrict__ We) {
    int t = blockIdx.x * blockDim.x + threadIdx.x;
    if (t < NNODES) g_cnt[t] = 0;
    if (t < NGRAPH * HIDN) g_pool[t] = 0.f;
    if (t < 122880) {
        int n = t / 320, k = t % 320;
        float v = (n < HIDN && k < 80) ? Wi[k * HIDN + n] : 0.f;
        g_WI[t] = __float2half(v);
    }
    if (t < 3 * 122880) {
        int l = t / 122880, r2 = t % 122880;
        int n = r2 / 320, k = r2 % 320;
        float v = (n < HIDN && k < HIDN) ? Wc[l * HIDN * HIDN + k * HIDN + n] : 0.f;
        g_W[t] = __float2half(v);
    }
    if (t < 384 * 384) {
        int n = t / 384, k = t % 384;
        float v = (n < HIDN && k < FNODE + HIDN) ? We[k * HIDN + n] : 0.f;
        g_WN[t] = __float2half(v);
    }
}

__global__ void k_hist(const int* __restrict__ coli) {
    int e = blockIdx.x * blockDim.x + threadIdx.x;
    if (e < NEDGES) atomicAdd(&g_cnt[coli[e]], 1);
}

// fast single-block scan: 1024 threads x 20 elems, shuffle-based
__global__ void k_scan() {
    __shared__ int wsum[32];
    int tid = threadIdx.x;
    int lane = tid & 31, wid = tid >> 5;
    const int PER = 20;
    int base = tid * PER;
    int v[PER];
    int s = 0;
#pragma unroll
    for (int i = 0; i < PER; ++i) {
        int idx = base + i;
        v[i] = (idx < NNODES) ? g_cnt[idx] : 0;
        s += v[i];
    }
    int ws = s;
#pragma unroll
    for (int off = 1; off < 32; off <<= 1) {
        int t = __shfl_up_sync(0xffffffffu, ws, off);
        if (lane >= off) ws += t;
    }
    if (lane == 31) wsum[wid] = ws;
    __syncthreads();
    if (wid == 0) {
        int w = wsum[lane];
#pragma unroll
        for (int off = 1; off < 32; off <<= 1) {
            int t = __shfl_up_sync(0xffffffffu, w, off);
            if (lane >= off) w += t;
        }
        wsum[lane] = w;
    }
    __syncthreads();
    int warp_off = (wid > 0) ? wsum[wid - 1] : 0;
    int run = warp_off + ws - s;
#pragma unroll
    for (int i = 0; i < PER; ++i) {
        int idx = base + i;
        if (idx < NNODES) { g_ptr[idx] = run; g_fill[idx] = run; }
        run += v[i];
    }
    if (tid == 0) g_ptr[NNODES] = wsum[31];
}

__global__ void k_scatter(const int* __restrict__ coli) {
    int e = blockIdx.x * blockDim.x + threadIdx.x;
    if (e < NEDGES) {
        int pos = atomicAdd(&g_fill[coli[e]], 1);
        g_eid[pos] = e;
    }
}

// ---------------- segment sum: g_a[n] = sum t[e] (u2 only) ----------------
__global__ void k_segsum(int src_sel) {
    const float* h = hbuf(src_sel);
    int t = blockIdx.x * blockDim.x + threadIdx.x;
    if (t >= NNODES * 75) return;
    int n = t / 75;
    int c = (t - n * 75) * 4;
    int beg = g_ptr[n], end = g_ptr[n + 1];
    float4 acc = make_float4(0.f, 0.f, 0.f, 0.f);
#pragma unroll 2
    for (int i = beg; i < end; ++i) {
        int e = g_eid[i];
        float4 vv = ld4(h + e * HIDN + c);
        acc.x += vv.x; acc.y += vv.y; acc.z += vv.z; acc.w += vv.w;
    }
    st4(g_a + n * HIDN + c, acc);
}

// ------ fused segsum + next-h materialize (paired-edge identity) --------
__global__ void k_seghm(int t_sel, const float* __restrict__ bc) {
    const float* tp = hbuf(t_sel);
    int t = blockIdx.x * blockDim.x + threadIdx.x;
    if (t >= NNODES * 75) return;
    int n = t / 75;
    int c = (t - n * 75) * 4;
    float4 bv = ld4(bc + c);
    int beg = g_ptr[n], end = g_ptr[n + 1];
    float4 u = make_float4(0.f, 0.f, 0.f, 0.f);
#pragma unroll 2
    for (int i = beg; i < end; ++i) {
        int e = g_eid[i];
        float4 vv = ld4(tp + e * HIDN + c);
        u.x += vv.x; u.y += vv.y; u.z += vv.z; u.w += vv.w;
    }
#pragma unroll 2
    for (int i = beg; i < end; ++i) {
        int e = g_eid[i];
        int er = e ^ 1;
        float4 tv  = ld4(tp + e * HIDN + c);
        float4 h0v = ld4(g_h0 + er * HIDN + c);
        float4 v;
        v.x = frelu(h0v.x + bv.x + u.x - tv.x);
        v.y = frelu(h0v.y + bv.y + u.y - tv.y);
        v.z = frelu(h0v.z + bv.z + u.z - tv.z);
        v.w = frelu(h0v.w + bv.w + u.w - tv.w);
        *reinterpret_cast<uint2*>(g_Af + (size_t)er * 320 + c) = pack4h(v);
    }
}

// --------- fused final: g_s[n] = sum_e relu(h0[e]+bc2+u2[row[e]]-rev(t2)) ----
__global__ void k_segsum_h3(int t2_sel, const float* __restrict__ bc2,
                            const int* __restrict__ rowi) {
    const float* t2 = hbuf(t2_sel);
    int t = blockIdx.x * blockDim.x + threadIdx.x;
    if (t >= NNODES * 75) return;
    int n = t / 75;
    int c = (t - n * 75) * 4;
    float4 bv = ld4(bc2 + c);
    int beg = g_ptr[n], end = g_ptr[n + 1];
    float4 acc = make_float4(0.f, 0.f, 0.f, 0.f);
#pragma unroll 2
    for (int i = beg; i < end; ++i) {
        int e = g_eid[i];
        float4 h0v = ld4(g_h0 + e * HIDN + c);
        float4 uv  = ld4(g_a + rowi[e] * HIDN + c);
        float4 tv  = ld4(t2 + (e ^ 1) * HIDN + c);
        acc.x += frelu(h0v.x + bv.x + uv.x - tv.x);
        acc.y += frelu(h0v.y + bv.y + uv.y - tv.y);
        acc.z += frelu(h0v.z + bv.z + uv.z - tv.z);
        acc.w += frelu(h0v.w + bv.w + uv.w - tv.w);
    }
    st4(g_s + n * HIDN + c, acc);
}

// =====================================================================
// Conv GEMM (fp16 single-pass): t_out = A @ W, all fp16 operands.
// CTA 128m x 128n, 8 warps (4m x 2n), K=320 in 5 chunks of 64, SW128,
// cp.async commit+wait0, 2 CTAs/SM. smem: A 16K + B 16K = 32K.
// =====================================================================
#define TG_A   0
#define TG_B   16384
#define TG_TOTAL 32768

__global__ void __launch_bounds__(256, 2) k_cgemm(int layer, int out_sel) {
    extern __shared__ char smem[];
    uint32_t sb = smem_u32(smem);
    int tid = threadIdx.x;
    int lane = tid & 31;
    int wid = tid >> 5;
    int m0 = blockIdx.y * 128;
    int n0 = blockIdx.x * 128;

    const __half* W = g_W + layer * 122880;
    float* tout = hbuf(out_sel);

    int wm = wid >> 1, wn = wid & 1;
    int mat = lane >> 3, l7 = lane & 7;
    int a_row = wm * 32 + (mat & 1) * 8 + l7;
    int a_kof = (mat >> 1) * 8;
    int b_base = wn * 64 + (mat >> 1) * 8 + l7;
    int b_kof = (mat & 1) * 8;
    bool nact = (n0 + wn * 64) < HIDN;

    uint32_t a_soff[2][4], b_soff[4][4];
#pragma unroll
    for (int mt = 0; mt < 2; ++mt)
#pragma unroll
        for (int ks = 0; ks < 4; ++ks)
            a_soff[mt][ks] = sw128((uint32_t)(((a_row + mt * 16) << 7) +
                                              ((ks * 16 + a_kof) << 1)));
#pragma unroll
    for (int np = 0; np < 4; ++np)
#pragma unroll
        for (int ks = 0; ks < 4; ++ks)
            b_soff[np][ks] = sw128((uint32_t)(((b_base + np * 16) << 7) +
                                              ((ks * 16 + b_kof) << 1)));

    float acc[2][8][4];
#pragma unroll
    for (int i = 0; i < 2; i++)
#pragma unroll
        for (int j = 0; j < 8; j++)
#pragma unroll
            for (int q = 0; q < 4; q++) acc[i][j][q] = 0.f;

    for (int kc = 0; kc < 5; ++kc) {
        int k0 = kc * 64;
        if (kc) __syncthreads();
#pragma unroll
        for (int s = 0; s < 4; s++) {
            int j = tid + s * 256;
            int r2 = j >> 3, i = j & 7;
            uint32_t off = sw128((uint32_t)(r2 * 128 + i * 16));
            CPA16(sb + TG_A + off, g_Af + (size_t)(m0 + r2) * 320 + k0 + i * 8);
            CPA16(sb + TG_B + off, W + (size_t)(n0 + r2) * 320 + k0 + i * 8);
        }
        CPA_COMMIT();
        CPA_WAIT0();
        __syncthreads();

#pragma unroll
        for (int ks = 0; ks < 4; ++ks) {
            uint32_t af[2][4];
#pragma unroll
            for (int mt = 0; mt < 2; ++mt)
                ldsm4(af[mt], sb + TG_A + a_soff[mt][ks]);
            if (nact) {
#pragma unroll
                for (int np = 0; np < 4; ++np) {
                    uint32_t bf4[4];
                    ldsm4(bf4, sb + TG_B + b_soff[np][ks]);
#pragma unroll
                    for (int mt = 0; mt < 2; ++mt)
#pragma unroll
                        for (int h = 0; h < 2; ++h)
                            mma_f16(acc[mt][np * 2 + h], af[mt], bf4 + h * 2);
                }
            }
        }
    }

    int orow = m0 + wm * 32 + (lane >> 2);
    int oc0  = n0 + wn * 64 + (lane & 3) * 2;
#pragma unroll
    for (int mt = 0; mt < 2; ++mt)
#pragma unroll
        for (int nt = 0; nt < 8; ++nt) {
            int col = oc0 + nt * 8;
            if (col >= HIDN) continue;
#pragma unroll
            for (int h = 0; h < 2; ++h) {
                int row = orow + mt * 16 + h * 8;
                *reinterpret_cast<float2*>(tout + row * HIDN + col) =
                    make_float2(acc[mt][nt][h * 2], acc[mt][nt][h * 2 + 1]);
            }
        }
}

// =====================================================================
// Init GEMM (fp16 single-pass): A = [x[row]|ea], K=80 -> 2 chunks.
// Epilogue: h0 = relu(acc+bias) -> g_h0 fp32 AND g_Af fp16.
// =====================================================================
__global__ void __launch_bounds__(256, 2) k_tginit(
    const int* __restrict__ rowi, const float* __restrict__ bvec,
    const float* __restrict__ x, const float* __restrict__ ea)
{
    extern __shared__ char smem[];
    uint32_t sb = smem_u32(smem);
    int tid = threadIdx.x;
    int lane = tid & 31;
    int wid = tid >> 5;
    int m0 = blockIdx.y * 128;
    int n0 = blockIdx.x * 128;

    int r = tid >> 1;
    int e = m0 + r;
    int cc0 = (tid & 1) * 32;
    int rv = rowi[e];

    int wm = wid >> 1, wn = wid & 1;
    int mat = lane >> 3, l7 = lane & 7;
    int a_row = wm * 32 + (mat & 1) * 8 + l7;
    int a_kof = (mat >> 1) * 8;
    int b_base = wn * 64 + (mat >> 1) * 8 + l7;
    int b_kof = (mat & 1) * 8;
    bool nact = (n0 + wn * 64) < HIDN;

    float acc[2][8][4];
#pragma unroll
    for (int i = 0; i < 2; i++)
#pragma unroll
        for (int j = 0; j < 8; j++)
#pragma unroll
            for (int q = 0; q < 4; q++) acc[i][j][q] = 0.f;

    for (int kc = 0; kc < 2; ++kc) {
        int k0 = kc * 64;
        if (kc) __syncthreads();
#pragma unroll
        for (int s = 0; s < 4; s++) {
            int j = tid + s * 256;
            int n = j >> 3, i = j & 7;
            uint32_t off = sw128((uint32_t)(n * 128 + i * 16));
            CPA16(sb + TG_B + off, g_WI + (n0 + n) * 320 + k0 + i * 8);
        }
        CPA_COMMIT();
#pragma unroll
        for (int i = 0; i < 8; i++) {
            int cc = cc0 + i * 4;
            int k = k0 + cc;
            float4 v = make_float4(0.f, 0.f, 0.f, 0.f);
            if (k < FNODE)    v = ld4(x + rv * FNODE + k);
            else if (k < 80)  v = ld4(ea + e * FEDGE + (k - FNODE));
            uint32_t off = sw128((uint32_t)(r * 128 + cc * 2));
            *reinterpret_cast<uint2*>(smem + TG_A + off) = pack4h(v);
        }
        CPA_WAIT0();
        __syncthreads();
#pragma unroll
        for (int ks = 0; ks < 4; ++ks) {
            uint32_t af[2][4];
#pragma unroll
            for (int mt = 0; mt < 2; ++mt) {
                uint32_t off = sw128((uint32_t)(((a_row + mt * 16) << 7) +
                                                ((ks * 16 + a_kof) << 1)));
                ldsm4(af[mt], sb + TG_A + off);
            }
            if (nact) {
#pragma unroll
                for (int np = 0; np < 4; ++np) {
                    uint32_t boff = sw128((uint32_t)(((b_base + np * 16) << 7) +
                                                     ((ks * 16 + b_kof) << 1)));
                    uint32_t bf4[4];
                    ldsm4(bf4, sb + TG_B + boff);
#pragma unroll
                    for (int mt = 0; mt < 2; ++mt)
#pragma unroll
                        for (int h = 0; h < 2; ++h)
                            mma_f16(acc[mt][np * 2 + h], af[mt], bf4 + h * 2);
                }
            }
        }
    }

    int orow = m0 + wm * 32 + (lane >> 2);
    int oc0  = n0 + wn * 64 + (lane & 3) * 2;
#pragma unroll
    for (int mt = 0; mt < 2; ++mt)
#pragma unroll
        for (int nt = 0; nt < 8; ++nt) {
            int col = oc0 + nt * 8;
            if (col >= 320) continue;
            bool live = col < HIDN;
            float b0 = live ? bvec[col] : 0.f;
            float b1 = live ? bvec[col + 1] : 0.f;
#pragma unroll
            for (int h = 0; h < 2; ++h) {
                int row = orow + mt * 16 + h * 8;
                float v0 = live ? frelu(acc[mt][nt][h * 2] + b0) : 0.f;
                float v1 = live ? frelu(acc[mt][nt][h * 2 + 1] + b1) : 0.f;
                if (live)
                    *reinterpret_cast<float2*>(g_h0 + row * HIDN + col) = make_float2(v0, v1);
                __half2 p = __floats2half2_rn(v0, v1);
                *reinterpret_cast<uint32_t*>(g_Af + (size_t)row * 320 + col) =
                    *reinterpret_cast<uint32_t*>(&p);
            }
        }
}

// =====================================================================
// Node GEMM (fp16 single-pass): hn = relu([x|s] @ W_e2n + be); pool += hn
// =====================================================================
__global__ void __launch_bounds__(256, 2) k_tgnode(
    const int* __restrict__ batch, const float* __restrict__ bvec,
    const float* __restrict__ x)
{
    extern __shared__ char smem[];
    uint32_t sb = smem_u32(smem);
    int tid = threadIdx.x;
    int lane = tid & 31;
    int wid = tid >> 5;
    int m0 = blockIdx.y * 128;
    int n0 = blockIdx.x * 128;

    int r = tid >> 1;
    int e = m0 + r;
    bool eok = (e < NNODES);
    int es = eok ? e : 0;
    int cc0 = (tid & 1) * 32;

    int wm = wid >> 1, wn = wid & 1;
    int mat = lane >> 3, l7 = lane & 7;
    int a_row = wm * 32 + (mat & 1) * 8 + l7;
    int a_kof = (mat >> 1) * 8;
    int b_base = wn * 64 + (mat >> 1) * 8 + l7;
    int b_kof = (mat & 1) * 8;
    bool nact = (n0 + wn * 64) < HIDN;

    const int KTOT = FNODE + HIDN;  // 364

    float acc[2][8][4];
#pragma unroll
    for (int i = 0; i < 2; i++)
#pragma unroll
        for (int j = 0; j < 8; j++)
#pragma unroll
            for (int q = 0; q < 4; q++) acc[i][j][q] = 0.f;

    for (int kc = 0; kc < 6; ++kc) {
        int k0 = kc * 64;
        if (kc) __syncthreads();
#pragma unroll
        for (int s = 0; s < 4; s++) {
            int j = tid + s * 256;
            int n = j >> 3, i = j & 7;
            uint32_t off = sw128((uint32_t)(n * 128 + i * 16));
            CPA16(sb + TG_B + off, g_WN + (n0 + n) * 384 + k0 + i * 8);
        }
        CPA_COMMIT();
#pragma unroll
        for (int i = 0; i < 8; i++) {
            int cc = cc0 + i * 4;
            int k = k0 + cc;
            float4 v = make_float4(0.f, 0.f, 0.f, 0.f);
            if (eok && k < KTOT)
                v = (k < FNODE) ? ld4(x + es * FNODE + k)
                                : ld4(g_s + es * HIDN + (k - FNODE));
            uint32_t off = sw128((uint32_t)(r * 128 + cc * 2));
            *reinterpret_cast<uint2*>(smem + TG_A + off) = pack4h(v);
        }
        CPA_WAIT0();
        __syncthreads();
#pragma unroll
        for (int ks = 0; ks < 4; ++ks) {
            uint32_t af[2][4];
#pragma unroll
            for (int mt = 0; mt < 2; ++mt) {
                uint32_t off = sw128((uint32_t)(((a_row + mt * 16) << 7) +
                                                ((ks * 16 + a_kof) << 1)));
                ldsm4(af[mt], sb + TG_A + off);
            }
            if (nact) {
#pragma unroll
                for (int np = 0; np < 4; ++np) {
                    uint32_t boff = sw128((uint32_t)(((b_base + np * 16) << 7) +
                                                     ((ks * 16 + b_kof) << 1)));
                    uint32_t bf4[4];
                    ldsm4(bf4, sb + TG_B + boff);
#pragma unroll
                    for (int mt = 0; mt < 2; ++mt)
#pragma unroll
                        for (int h = 0; h < 2; ++h)
                            mma_f16(acc[mt][np * 2 + h], af[mt], bf4 + h * 2);
                }
            }
        }
    }

    int orow = m0 + wm * 32 + (lane >> 2);
    int oc0  = n0 + wn * 64 + (lane & 3) * 2;
#pragma unroll
    for (int mt = 0; mt < 2; ++mt)
#pragma unroll
        for (int nt = 0; nt < 8; ++nt) {
            int col = oc0 + nt * 8;
            if (col >= HIDN) continue;
            float b0 = bvec[col], b1 = bvec[col + 1];
#pragma unroll
            for (int h = 0; h < 2; ++h) {
                int row = orow + mt * 16 + h * 8;
                if (row >= NNODES) continue;
                float* p = g_pool + batch[row] * HIDN + col;
                atomicAdd(p + 0, frelu(acc[mt][nt][h * 2] + b0));
                atomicAdd(p + 1, frelu(acc[mt][nt][h * 2 + 1] + b1));
            }
        }
}

// ---------------- FFN ----------------
__global__ void k_ffn(const float* __restrict__ Wf, const float* __restrict__ bf,
                      float* __restrict__ out) {
    int g = blockIdx.x;
    int lane = threadIdx.x;
    float s = 0.f;
    for (int k = lane; k < HIDN; k += 32) s += g_pool[g * HIDN + k] * Wf[k];
#pragma unroll
    for (int o = 16; o; o >>= 1) s += __shfl_xor_sync(0xffffffffu, s, o);
    if (lane == 0) out[g] = s + bf[0];
}

// ---------------- entry ----------------
extern "C" void kernel_launch(void* const* d_in, const int* in_sizes, int n_in,
                              void* d_out, int out_size) {
    const float* x     = (const float*)d_in[0];
    const float* ea    = (const float*)d_in[1];
    const int*   ei    = (const int*)d_in[2];
    const int*   rowi  = ei;
    const int*   coli  = ei + NEDGES;
    const int*   batch = (const int*)d_in[3];
    const float* Wi    = (const float*)d_in[4];
    const float* bi    = (const float*)d_in[5];
    const float* Wc    = (const float*)d_in[6];
    const float* bc    = (const float*)d_in[7];
    const float* We    = (const float*)d_in[8];
    const float* be    = (const float*)d_in[9];
    const float* Wf    = (const float*)d_in[10];
    const float* bf    = (const float*)d_in[11];
    float* out = (float*)d_out;

    cudaFuncSetAttribute(k_cgemm,  cudaFuncAttributeMaxDynamicSharedMemorySize, TG_TOTAL);
    cudaFuncSetAttribute(k_tginit, cudaFuncAttributeMaxDynamicSharedMemorySize, TG_TOTAL);
    cudaFuncSetAttribute(k_tgnode, cudaFuncAttributeMaxDynamicSharedMemorySize, TG_TOTAL);

    dim3 gT(3, NEDGES / 128);
    dim3 gN(3, (NNODES + 127) / 128);
    int ssB = (NNODES * 75 + 255) / 256;

    k_pre<<<1440, 256>>>(Wc, Wi, We);                   // 1
    k_hist<<<NEDGES / 256, 256>>>(coli);                // 2
    k_tginit<<<gT, 256, TG_TOTAL>>>(rowi, bi, x, ea);   // 3: h0 + A fp16
    k_cgemm<<<gT, 256, TG_TOTAL>>>(0, 1);               // 4: t0  <- profiled
    k_scan<<<1, 1024>>>();                              // 5
    k_scatter<<<NEDGES / 256, 256>>>(coli);             // 6

    k_seghm<<<ssB, 256>>>(1, bc);                       // u0 (regs) + A = h1 fp16
    k_cgemm<<<gT, 256, TG_TOTAL>>>(1, 2);               // t1
    k_seghm<<<ssB, 256>>>(2, bc + HIDN);                // u1 (regs) + A = h2 fp16
    k_cgemm<<<gT, 256, TG_TOTAL>>>(2, 1);               // t2
    k_segsum<<<ssB, 256>>>(1);                          // u2 -> g_a
    k_segsum_h3<<<ssB, 256>>>(1, bc + 2 * HIDN, rowi);  // s (fused h3+segsum)

    k_tgnode<<<gN, 256, TG_TOTAL>>>(batch, be, x);      // node GEMM + pool
    k_ffn<<<NGRAPH, 32>>>(Wf, bf, out);
}

// round 16
// speedup vs baseline: 2.0709x; 1.2187x over previous
#include <cuda_runtime.h>
#include <cuda_bf16.h>
#include <cuda_fp16.h>
#include <cstdint>

#define NNODES 20000
#define NEDGES 320000
#define FNODE  64
#define FEDGE  16
#define HIDN   300
#define NGRAPH 128

typedef unsigned long long ull;

// ---------------- scratch (device globals) ----------------
__device__ __half g_h0f[NEDGES * 320];         // h0 fp16, stride 320 (pad 0) = layer-0 A
__device__ __half g_tA [NEDGES * HIDN];        // t ping (fp16)
__device__ __half g_tB [NEDGES * HIDN];        // t pong (fp16)
__device__ __half g_Af [NEDGES * 320];         // A operand fp16 (layers 1,2)
__device__ float g_a [NNODES * HIDN];          // u2 (fp32)
__device__ float g_s [NNODES * HIDN];          // final node message (fp32)
__device__ float g_pool[NGRAPH * HIDN];
__device__ __half g_W [3 * 384 * 320];         // conv W^T fp16 [l][n][k]
__device__ __half g_WI[384 * 320];             // init W^T fp16
__device__ __half g_WN[384 * 384];             // e2n W^T fp16 [n][k]
__device__ int g_cnt [NNODES];
__device__ int g_ptr [NNODES + 1];
__device__ int g_fill[NNODES];
__device__ int g_eid [NEDGES];

__device__ __forceinline__ __half* tbuf(int s) { return s ? g_tB : g_tA; }

// ---------------- helpers ----------------
__device__ __forceinline__ float4 ld4(const float* p) { return *reinterpret_cast<const float4*>(p); }
__device__ __forceinline__ void   st4(float* p, float4 v) { *reinterpret_cast<float4*>(p) = v; }
__device__ __forceinline__ float  frelu(float x) { return x > 0.f ? x : 0.f; }

__device__ __forceinline__ float4 ld4h(const __half* p) {
    uint2 w = *reinterpret_cast<const uint2*>(p);
    __half2 a = *reinterpret_cast<__half2*>(&w.x);
    __half2 b = *reinterpret_cast<__half2*>(&w.y);
    float2 fa = __half22float2(a), fb = __half22float2(b);
    return make_float4(fa.x, fa.y, fb.x, fb.y);
}
__device__ __forceinline__ uint2 pack4h(float4 v) {
    __half2 a = __floats2half2_rn(v.x, v.y);
    __half2 b = __floats2half2_rn(v.z, v.w);
    return make_uint2(*reinterpret_cast<uint32_t*>(&a), *reinterpret_cast<uint32_t*>(&b));
}

__device__ __forceinline__ uint32_t smem_u32(const void* p) {
    uint32_t a;
    asm("{ .reg .u64 t; cvta.to.shared.u64 t, %1; cvt.u32.u64 %0, t; }" : "=r"(a) : "l"(p));
    return a;
}
__device__ __forceinline__ uint32_t sw128(uint32_t o) { return o ^ ((o >> 3) & 0x70); }

__device__ __forceinline__ void ldsm4(uint32_t* r, uint32_t a) {
    asm volatile("ldmatrix.sync.aligned.m8n8.x4.shared.b16 {%0,%1,%2,%3}, [%4];"
                 : "=r"(r[0]), "=r"(r[1]), "=r"(r[2]), "=r"(r[3]) : "r"(a));
}
__device__ __forceinline__ void mma_f16(float* d, const uint32_t* a, const uint32_t* b) {
    asm volatile("mma.sync.aligned.m16n8k16.row.col.f32.f16.f16.f32 "
                 "{%0,%1,%2,%3}, {%4,%5,%6,%7}, {%8,%9}, {%0,%1,%2,%3};"
                 : "+f"(d[0]), "+f"(d[1]), "+f"(d[2]), "+f"(d[3])
                 : "r"(a[0]), "r"(a[1]), "r"(a[2]), "r"(a[3]), "r"(b[0]), "r"(b[1]));
}
#define CPA16(dst, src) asm volatile("cp.async.cg.shared.global [%0], [%1], 16;" :: "r"(dst), "l"(src))
#define CPA_COMMIT()    asm volatile("cp.async.commit_group;" ::: "memory")
#define CPA_WAIT0()     asm volatile("cp.async.wait_group 0;" ::: "memory")

// ---------------- preprocessing ----------------
__global__ void k_pre(const float* __restrict__ Wc, const float* __restrict__ Wi,
                      const float* __restrict__ We) {
    int t = blockIdx.x * blockDim.x + threadIdx.x;
    int nth = gridDim.x * blockDim.x;
    if (t < NNODES) g_cnt[t] = 0;
    if (t < NGRAPH * HIDN) g_pool[t] = 0.f;
    if (t < 122880) {
        int n = t / 320, k = t % 320;
        float v = (n < HIDN && k < 80) ? Wi[k * HIDN + n] : 0.f;
        g_WI[t] = __float2half(v);
    }
    if (t < 3 * 122880) {
        int l = t / 122880, r2 = t % 122880;
        int n = r2 / 320, k = r2 % 320;
        float v = (n < HIDN && k < HIDN) ? Wc[l * HIDN * HIDN + k * HIDN + n] : 0.f;
        g_W[t] = __float2half(v);
    }
    if (t < 384 * 384) {
        int n = t / 384, k = t % 384;
        float v = (n < HIDN && k < FNODE + HIDN) ? We[k * HIDN + n] : 0.f;
        g_WN[t] = __float2half(v);
    }
    // zero pad columns (300..319) of g_Af: 5 uint2 (4 halves) per edge
    for (int j = t; j < NEDGES * 5; j += nth) {
        int e = j / 5, q = j - e * 5;
        *reinterpret_cast<uint2*>(g_Af + (size_t)e * 320 + 300 + q * 4) = make_uint2(0u, 0u);
    }
}

__global__ void k_hist(const int* __restrict__ coli) {
    int e = blockIdx.x * blockDim.x + threadIdx.x;
    if (e < NEDGES) atomicAdd(&g_cnt[coli[e]], 1);
}

// fast single-block scan: 1024 threads x 20 elems, shuffle-based
__global__ void k_scan() {
    __shared__ int wsum[32];
    int tid = threadIdx.x;
    int lane = tid & 31, wid = tid >> 5;
    const int PER = 20;
    int base = tid * PER;
    int v[PER];
    int s = 0;
#pragma unroll
    for (int i = 0; i < PER; ++i) {
        int idx = base + i;
        v[i] = (idx < NNODES) ? g_cnt[idx] : 0;
        s += v[i];
    }
    int ws = s;
#pragma unroll
    for (int off = 1; off < 32; off <<= 1) {
        int t = __shfl_up_sync(0xffffffffu, ws, off);
        if (lane >= off) ws += t;
    }
    if (lane == 31) wsum[wid] = ws;
    __syncthreads();
    if (wid == 0) {
        int w = wsum[lane];
#pragma unroll
        for (int off = 1; off < 32; off <<= 1) {
            int t = __shfl_up_sync(0xffffffffu, w, off);
            if (lane >= off) w += t;
        }
        wsum[lane] = w;
    }
    __syncthreads();
    int warp_off = (wid > 0) ? wsum[wid - 1] : 0;
    int run = warp_off + ws - s;
#pragma unroll
    for (int i = 0; i < PER; ++i) {
        int idx = base + i;
        if (idx < NNODES) { g_ptr[idx] = run; g_fill[idx] = run; }
        run += v[i];
    }
    if (tid == 0) g_ptr[NNODES] = wsum[31];
}

__global__ void k_scatter(const int* __restrict__ coli) {
    int e = blockIdx.x * blockDim.x + threadIdx.x;
    if (e < NEDGES) {
        int pos = atomicAdd(&g_fill[coli[e]], 1);
        g_eid[pos] = e;
    }
}

// ---------------- segment sum: g_a[n] = sum t[e] (u2 only) ----------------
__global__ void k_segsum(int src_sel) {
    const __half* h = tbuf(src_sel);
    int t = blockIdx.x * blockDim.x + threadIdx.x;
    if (t >= NNODES * 75) return;
    int n = t / 75;
    int c = (t - n * 75) * 4;
    int beg = g_ptr[n], end = g_ptr[n + 1];
    float4 acc = make_float4(0.f, 0.f, 0.f, 0.f);
#pragma unroll 2
    for (int i = beg; i < end; ++i) {
        int e = g_eid[i];
        float4 vv = ld4h(h + (size_t)e * HIDN + c);
        acc.x += vv.x; acc.y += vv.y; acc.z += vv.z; acc.w += vv.w;
    }
    st4(g_a + n * HIDN + c, acc);
}

// ------ fused segsum + next-h materialize (paired-edge identity) --------
__global__ void k_seghm(int t_sel, const float* __restrict__ bc) {
    const __half* tp = tbuf(t_sel);
    int t = blockIdx.x * blockDim.x + threadIdx.x;
    if (t >= NNODES * 75) return;
    int n = t / 75;
    int c = (t - n * 75) * 4;
    float4 bv = ld4(bc + c);
    int beg = g_ptr[n], end = g_ptr[n + 1];
    float4 u = make_float4(0.f, 0.f, 0.f, 0.f);
#pragma unroll 2
    for (int i = beg; i < end; ++i) {
        int e = g_eid[i];
        float4 vv = ld4h(tp + (size_t)e * HIDN + c);
        u.x += vv.x; u.y += vv.y; u.z += vv.z; u.w += vv.w;
    }
#pragma unroll 2
    for (int i = beg; i < end; ++i) {
        int e = g_eid[i];
        int er = e ^ 1;
        float4 tv  = ld4h(tp + (size_t)e * HIDN + c);
        float4 h0v = ld4h(g_h0f + (size_t)er * 320 + c);
        float4 v;
        v.x = frelu(h0v.x + bv.x + u.x - tv.x);
        v.y = frelu(h0v.y + bv.y + u.y - tv.y);
        v.z = frelu(h0v.z + bv.z + u.z - tv.z);
        v.w = frelu(h0v.w + bv.w + u.w - tv.w);
        *reinterpret_cast<uint2*>(g_Af + (size_t)er * 320 + c) = pack4h(v);
    }
}

// --------- fused final: g_s[n] = sum_e relu(h0[e]+bc2+u2[row[e]]-rev(t2)) ----
__global__ void k_segsum_h3(int t2_sel, const float* __restrict__ bc2,
                            const int* __restrict__ rowi) {
    const __half* t2 = tbuf(t2_sel);
    int t = blockIdx.x * blockDim.x + threadIdx.x;
    if (t >= NNODES * 75) return;
    int n = t / 75;
    int c = (t - n * 75) * 4;
    float4 bv = ld4(bc2 + c);
    int beg = g_ptr[n], end = g_ptr[n + 1];
    float4 acc = make_float4(0.f, 0.f, 0.f, 0.f);
#pragma unroll 2
    for (int i = beg; i < end; ++i) {
        int e = g_eid[i];
        float4 h0v = ld4h(g_h0f + (size_t)e * 320 + c);
        float4 uv  = ld4(g_a + rowi[e] * HIDN + c);
        float4 tv  = ld4h(t2 + (size_t)(e ^ 1) * HIDN + c);
        acc.x += frelu(h0v.x + bv.x + uv.x - tv.x);
        acc.y += frelu(h0v.y + bv.y + uv.y - tv.y);
        acc.z += frelu(h0v.z + bv.z + uv.z - tv.z);
        acc.w += frelu(h0v.w + bv.w + uv.w - tv.w);
    }
    st4(g_s + n * HIDN + c, acc);
}

// =====================================================================
// Conv GEMM (fp16 single-pass): t_out = A @ W, fp16 in/out, fp32 acc.
// CTA 128m x 128n, 8 warps (4m x 2n), K=320 in 5 chunks of 64, SW128,
// cp.async commit+wait0, 2 CTAs/SM. smem: A 16K + B 16K = 32K.
// =====================================================================
#define TG_A   0
#define TG_B   16384
#define TG_TOTAL 32768

__global__ void __launch_bounds__(256, 2) k_cgemm(int layer, int a_sel, int out_sel) {
    extern __shared__ char smem[];
    uint32_t sb = smem_u32(smem);
    int tid = threadIdx.x;
    int lane = tid & 31;
    int wid = tid >> 5;
    int m0 = blockIdx.y * 128;
    int n0 = blockIdx.x * 128;

    const __half* W = g_W + layer * 122880;
    const __half* Ain = a_sel ? g_Af : g_h0f;
    __half* tout = tbuf(out_sel);

    int wm = wid >> 1, wn = wid & 1;
    int mat = lane >> 3, l7 = lane & 7;
    int a_row = wm * 32 + (mat & 1) * 8 + l7;
    int a_kof = (mat >> 1) * 8;
    int b_base = wn * 64 + (mat >> 1) * 8 + l7;
    int b_kof = (mat & 1) * 8;
    bool nact = (n0 + wn * 64) < HIDN;

    uint32_t a_soff[2][4], b_soff[4][4];
#pragma unroll
    for (int mt = 0; mt < 2; ++mt)
#pragma unroll
        for (int ks = 0; ks < 4; ++ks)
            a_soff[mt][ks] = sw128((uint32_t)(((a_row + mt * 16) << 7) +
                                              ((ks * 16 + a_kof) << 1)));
#pragma unroll
    for (int np = 0; np < 4; ++np)
#pragma unroll
        for (int ks = 0; ks < 4; ++ks)
            b_soff[np][ks] = sw128((uint32_t)(((b_base + np * 16) << 7) +
                                              ((ks * 16 + b_kof) << 1)));

    float acc[2][8][4];
#pragma unroll
    for (int i = 0; i < 2; i++)
#pragma unroll
        for (int j = 0; j < 8; j++)
#pragma unroll
            for (int q = 0; q < 4; q++) acc[i][j][q] = 0.f;

    for (int kc = 0; kc < 5; ++kc) {
        int k0 = kc * 64;
        if (kc) __syncthreads();
#pragma unroll
        for (int s = 0; s < 4; s++) {
            int j = tid + s * 256;
            int r2 = j >> 3, i = j & 7;
            uint32_t off = sw128((uint32_t)(r2 * 128 + i * 16));
            CPA16(sb + TG_A + off, Ain + (size_t)(m0 + r2) * 320 + k0 + i * 8);
            CPA16(sb + TG_B + off, W + (size_t)(n0 + r2) * 320 + k0 + i * 8);
        }
        CPA_COMMIT();
        CPA_WAIT0();
        __syncthreads();

#pragma unroll
        for (int ks = 0; ks < 4; ++ks) {
            uint32_t af[2][4];
#pragma unroll
            for (int mt = 0; mt < 2; ++mt)
                ldsm4(af[mt], sb + TG_A + a_soff[mt][ks]);
            if (nact) {
#pragma unroll
                for (int np = 0; np < 4; ++np) {
                    uint32_t bf4[4];
                    ldsm4(bf4, sb + TG_B + b_soff[np][ks]);
#pragma unroll
                    for (int mt = 0; mt < 2; ++mt)
#pragma unroll
                        for (int h = 0; h < 2; ++h)
                            mma_f16(acc[mt][np * 2 + h], af[mt], bf4 + h * 2);
                }
            }
        }
    }

    int orow = m0 + wm * 32 + (lane >> 2);
    int oc0  = n0 + wn * 64 + (lane & 3) * 2;
#pragma unroll
    for (int mt = 0; mt < 2; ++mt)
#pragma unroll
        for (int nt = 0; nt < 8; ++nt) {
            int col = oc0 + nt * 8;
            if (col >= HIDN) continue;
#pragma unroll
            for (int h = 0; h < 2; ++h) {
                int row = orow + mt * 16 + h * 8;
                __half2 p = __floats2half2_rn(acc[mt][nt][h * 2], acc[mt][nt][h * 2 + 1]);
                *reinterpret_cast<__half2*>(tout + (size_t)row * HIDN + col) = p;
            }
        }
}

// =====================================================================
// Init GEMM: A = [x[row]|ea], K=80 -> 2 chunks. Epilogue -> g_h0f fp16.
// =====================================================================
__global__ void __launch_bounds__(256, 2) k_tginit(
    const int* __restrict__ rowi, const float* __restrict__ bvec,
    const float* __restrict__ x, const float* __restrict__ ea)
{
    extern __shared__ char smem[];
    uint32_t sb = smem_u32(smem);
    int tid = threadIdx.x;
    int lane = tid & 31;
    int wid = tid >> 5;
    int m0 = blockIdx.y * 128;
    int n0 = blockIdx.x * 128;

    int r = tid >> 1;
    int e = m0 + r;
    int cc0 = (tid & 1) * 32;
    int rv = rowi[e];

    int wm = wid >> 1, wn = wid & 1;
    int mat = lane >> 3, l7 = lane & 7;
    int a_row = wm * 32 + (mat & 1) * 8 + l7;
    int a_kof = (mat >> 1) * 8;
    int b_base = wn * 64 + (mat >> 1) * 8 + l7;
    int b_kof = (mat & 1) * 8;
    bool nact = (n0 + wn * 64) < HIDN;

    float acc[2][8][4];
#pragma unroll
    for (int i = 0; i < 2; i++)
#pragma unroll
        for (int j = 0; j < 8; j++)
#pragma unroll
            for (int q = 0; q < 4; q++) acc[i][j][q] = 0.f;

    for (int kc = 0; kc < 2; ++kc) {
        int k0 = kc * 64;
        if (kc) __syncthreads();
#pragma unroll
        for (int s = 0; s < 4; s++) {
            int j = tid + s * 256;
            int n = j >> 3, i = j & 7;
            uint32_t off = sw128((uint32_t)(n * 128 + i * 16));
            CPA16(sb + TG_B + off, g_WI + (n0 + n) * 320 + k0 + i * 8);
        }
        CPA_COMMIT();
#pragma unroll
        for (int i = 0; i < 8; i++) {
            int cc = cc0 + i * 4;
            int k = k0 + cc;
            float4 v = make_float4(0.f, 0.f, 0.f, 0.f);
            if (k < FNODE)    v = ld4(x + rv * FNODE + k);
            else if (k < 80)  v = ld4(ea + e * FEDGE + (k - FNODE));
            uint32_t off = sw128((uint32_t)(r * 128 + cc * 2));
            *reinterpret_cast<uint2*>(smem + TG_A + off) = pack4h(v);
        }
        CPA_WAIT0();
        __syncthreads();
#pragma unroll
        for (int ks = 0; ks < 4; ++ks) {
            uint32_t af[2][4];
#pragma unroll
            for (int mt = 0; mt < 2; ++mt) {
                uint32_t off = sw128((uint32_t)(((a_row + mt * 16) << 7) +
                                                ((ks * 16 + a_kof) << 1)));
                ldsm4(af[mt], sb + TG_A + off);
            }
            if (nact) {
#pragma unroll
                for (int np = 0; np < 4; ++np) {
                    uint32_t boff = sw128((uint32_t)(((b_base + np * 16) << 7) +
                                                     ((ks * 16 + b_kof) << 1)));
                    uint32_t bf4[4];
                    ldsm4(bf4, sb + TG_B + boff);
#pragma unroll
                    for (int mt = 0; mt < 2; ++mt)
#pragma unroll
                        for (int h = 0; h < 2; ++h)
                            mma_f16(acc[mt][np * 2 + h], af[mt], bf4 + h * 2);
                }
            }
        }
    }

    int orow = m0 + wm * 32 + (lane >> 2);
    int oc0  = n0 + wn * 64 + (lane & 3) * 2;
#pragma unroll
    for (int mt = 0; mt < 2; ++mt)
#pragma unroll
        for (int nt = 0; nt < 8; ++nt) {
            int col = oc0 + nt * 8;
            if (col >= 320) continue;
            bool live = col < HIDN;
            float b0 = live ? bvec[col] : 0.f;
            float b1 = live ? bvec[col + 1] : 0.f;
#pragma unroll
            for (int h = 0; h < 2; ++h) {
                int row = orow + mt * 16 + h * 8;
                float v0 = live ? frelu(acc[mt][nt][h * 2] + b0) : 0.f;
                float v1 = live ? frelu(acc[mt][nt][h * 2 + 1] + b1) : 0.f;
                __half2 p = __floats2half2_rn(v0, v1);
                *reinterpret_cast<__half2*>(g_h0f + (size_t)row * 320 + col) = p;
            }
        }
}

// =====================================================================
// Node GEMM: hn = relu([x|s] @ W_e2n + be); pool += hn
// =====================================================================
__global__ void __launch_bounds__(256, 2) k_tgnode(
    const int* __restrict__ batch, const float* __restrict__ bvec,
    const float* __restrict__ x)
{
    extern __shared__ char smem[];
    uint32_t sb = smem_u32(smem);
    int tid = threadIdx.x;
    int lane = tid & 31;
    int wid = tid >> 5;
    int m0 = blockIdx.y * 128;
    int n0 = blockIdx.x * 128;

    int r = tid >> 1;
    int e = m0 + r;
    bool eok = (e < NNODES);
    int es = eok ? e : 0;
    int cc0 = (tid & 1) * 32;

    int wm = wid >> 1, wn = wid & 1;
    int mat = lane >> 3, l7 = lane & 7;
    int a_row = wm * 32 + (mat & 1) * 8 + l7;
    int a_kof = (mat >> 1) * 8;
    int b_base = wn * 64 + (mat >> 1) * 8 + l7;
    int b_kof = (mat & 1) * 8;
    bool nact = (n0 + wn * 64) < HIDN;

    const int KTOT = FNODE + HIDN;  // 364

    float acc[2][8][4];
#pragma unroll
    for (int i = 0; i < 2; i++)
#pragma unroll
        for (int j = 0; j < 8; j++)
#pragma unroll
            for (int q = 0; q < 4; q++) acc[i][j][q] = 0.f;

    for (int kc = 0; kc < 6; ++kc) {
        int k0 = kc * 64;
        if (kc) __syncthreads();
#pragma unroll
        for (int s = 0; s < 4; s++) {
            int j = tid + s * 256;
            int n = j >> 3, i = j & 7;
            uint32_t off = sw128((uint32_t)(n * 128 + i * 16));
            CPA16(sb + TG_B + off, g_WN + (n0 + n) * 384 + k0 + i * 8);
        }
        CPA_COMMIT();
#pragma unroll
        for (int i = 0; i < 8; i++) {
            int cc = cc0 + i * 4;
            int k = k0 + cc;
            float4 v = make_float4(0.f, 0.f, 0.f, 0.f);
            if (eok && k < KTOT)
                v = (k < FNODE) ? ld4(x + es * FNODE + k)
                                : ld4(g_s + es * HIDN + (k - FNODE));
            uint32_t off = sw128((uint32_t)(r * 128 + cc * 2));
            *reinterpret_cast<uint2*>(smem + TG_A + off) = pack4h(v);
        }
        CPA_WAIT0();
        __syncthreads();
#pragma unroll
        for (int ks = 0; ks < 4; ++ks) {
            uint32_t af[2][4];
#pragma unroll
            for (int mt = 0; mt < 2; ++mt) {
                uint32_t off = sw128((uint32_t)(((a_row + mt * 16) << 7) +
                                                ((ks * 16 + a_kof) << 1)));
                ldsm4(af[mt], sb + TG_A + off);
            }
            if (nact) {
#pragma unroll
                for (int np = 0; np < 4; ++np) {
                    uint32_t boff = sw128((uint32_t)(((b_base + np * 16) << 7) +
                                                     ((ks * 16 + b_kof) << 1)));
                    uint32_t bf4[4];
                    ldsm4(bf4, sb + TG_B + boff);
#pragma unroll
                    for (int mt = 0; mt < 2; ++mt)
#pragma unroll
                        for (int h = 0; h < 2; ++h)
                            mma_f16(acc[mt][np * 2 + h], af[mt], bf4 + h * 2);
                }
            }
        }
    }

    int orow = m0 + wm * 32 + (lane >> 2);
    int oc0  = n0 + wn * 64 + (lane & 3) * 2;
#pragma unroll
    for (int mt = 0; mt < 2; ++mt)
#pragma unroll
        for (int nt = 0; nt < 8; ++nt) {
            int col = oc0 + nt * 8;
            if (col >= HIDN) continue;
            float b0 = bvec[col], b1 = bvec[col + 1];
#pragma unroll
            for (int h = 0; h < 2; ++h) {
                int row = orow + mt * 16 + h * 8;
                if (row >= NNODES) continue;
                float* p = g_pool + batch[row] * HIDN + col;
                atomicAdd(p + 0, frelu(acc[mt][nt][h * 2] + b0));
                atomicAdd(p + 1, frelu(acc[mt][nt][h * 2 + 1] + b1));
            }
        }
}

// ---------------- FFN ----------------
__global__ void k_ffn(const float* __restrict__ Wf, const float* __restrict__ bf,
                      float* __restrict__ out) {
    int g = blockIdx.x;
    int lane = threadIdx.x;
    float s = 0.f;
    for (int k = lane; k < HIDN; k += 32) s += g_pool[g * HIDN + k] * Wf[k];
#pragma unroll
    for (int o = 16; o; o >>= 1) s += __shfl_xor_sync(0xffffffffu, s, o);
    if (lane == 0) out[g] = s + bf[0];
}

// ---------------- entry ----------------
extern "C" void kernel_launch(void* const* d_in, const int* in_sizes, int n_in,
                              void* d_out, int out_size) {
    const float* x     = (const float*)d_in[0];
    const float* ea    = (const float*)d_in[1];
    const int*   ei    = (const int*)d_in[2];
    const int*   rowi  = ei;
    const int*   coli  = ei + NEDGES;
    const int*   batch = (const int*)d_in[3];
    const float* Wi    = (const float*)d_in[4];
    const float* bi    = (const float*)d_in[5];
    const float* Wc    = (const float*)d_in[6];
    const float* bc    = (const float*)d_in[7];
    const float* We    = (const float*)d_in[8];
    const float* be    = (const float*)d_in[9];
    const float* Wf    = (const float*)d_in[10];
    const float* bf    = (const float*)d_in[11];
    float* out = (float*)d_out;

    cudaFuncSetAttribute(k_cgemm,  cudaFuncAttributeMaxDynamicSharedMemorySize, TG_TOTAL);
    cudaFuncSetAttribute(k_tginit, cudaFuncAttributeMaxDynamicSharedMemorySize, TG_TOTAL);
    cudaFuncSetAttribute(k_tgnode, cudaFuncAttributeMaxDynamicSharedMemorySize, TG_TOTAL);

    dim3 gT(3, NEDGES / 128);
    dim3 gN(3, (NNODES + 127) / 128);
    int ssB = (NNODES * 75 + 255) / 256;

    k_pre<<<1440, 256>>>(Wc, Wi, We);                    // 1
    k_hist<<<NEDGES / 256, 256>>>(coli);                 // 2
    k_tginit<<<gT, 256, TG_TOTAL>>>(rowi, bi, x, ea);    // 3: h0 fp16 (= layer-0 A)
    k_cgemm<<<gT, 256, TG_TOTAL>>>(0, 0, 0);             // 4: t0 -> tA  <- profiled
    k_scan<<<1, 1024>>>();                               // 5
    k_scatter<<<NEDGES / 256, 256>>>(coli);              // 6

    k_seghm<<<ssB, 256>>>(0, bc);                        // u0 (regs) + A = h1 fp16
    k_cgemm<<<gT, 256, TG_TOTAL>>>(1, 1, 1);             // t1 -> tB
    k_seghm<<<ssB, 256>>>(1, bc + HIDN);                 // u1 (regs) + A = h2 fp16
    k_cgemm<<<gT, 256, TG_TOTAL>>>(2, 1, 0);             // t2 -> tA
    k_segsum<<<ssB, 256>>>(0);                           // u2 -> g_a
    k_segsum_h3<<<ssB, 256>>>(0, bc + 2 * HIDN, rowi);   // s (fused h3+segsum)

    k_tgnode<<<gN, 256, TG_TOTAL>>>(batch, be, x);       // node GEMM + pool
    k_ffn<<<NGRAPH, 32>>>(Wf, bf, out);
}

// round 17
// speedup vs baseline: 2.1386x; 1.0327x over previous
#include <cuda_runtime.h>
#include <cuda_bf16.h>
#include <cuda_fp16.h>
#include <cstdint>

#define NNODES 20000
#define NEDGES 320000
#define FNODE  64
#define FEDGE  16
#define HIDN   300
#define NGRAPH 128

typedef unsigned long long ull;

// ---------------- scratch (device globals) ----------------
__device__ __half g_h0f[NEDGES * 320];         // h0 fp16, stride 320 (pad 0) = layer-0 A
__device__ __half g_tA [NEDGES * HIDN];        // t ping (fp16)
__device__ __half g_tB [NEDGES * HIDN];        // t pong (fp16)
__device__ __half g_Af [NEDGES * 320];         // A operand fp16 (layers 1,2)
__device__ float g_a [NNODES * HIDN];          // u2 (fp32)
__device__ float g_s [NNODES * HIDN];          // final node message (fp32)
__device__ float g_pool[NGRAPH * HIDN];
__device__ __half g_W [3 * 384 * 320];         // conv W^T fp16 [l][n][k]
__device__ __half g_WI[384 * 320];             // init W^T fp16
__device__ __half g_WN[384 * 384];             // e2n W^T fp16 [n][k]
__device__ int g_cnt [NNODES];
__device__ int g_ptr [NNODES + 1];
__device__ int g_fill[NNODES];
__device__ int g_eid [NEDGES];

__device__ __forceinline__ __half* tbuf(int s) { return s ? g_tB : g_tA; }

// ---------------- helpers ----------------
__device__ __forceinline__ float4 ld4(const float* p) { return *reinterpret_cast<const float4*>(p); }
__device__ __forceinline__ void   st4(float* p, float4 v) { *reinterpret_cast<float4*>(p) = v; }
__device__ __forceinline__ float  frelu(float x) { return x > 0.f ? x : 0.f; }

__device__ __forceinline__ float4 ld4h(const __half* p) {
    uint2 w = *reinterpret_cast<const uint2*>(p);
    __half2 a = *reinterpret_cast<__half2*>(&w.x);
    __half2 b = *reinterpret_cast<__half2*>(&w.y);
    float2 fa = __half22float2(a), fb = __half22float2(b);
    return make_float4(fa.x, fa.y, fb.x, fb.y);
}
__device__ __forceinline__ uint2 pack4h(float4 v) {
    __half2 a = __floats2half2_rn(v.x, v.y);
    __half2 b = __floats2half2_rn(v.z, v.w);
    return make_uint2(*reinterpret_cast<uint32_t*>(&a), *reinterpret_cast<uint32_t*>(&b));
}

__device__ __forceinline__ uint32_t smem_u32(const void* p) {
    uint32_t a;
    asm("{ .reg .u64 t; cvta.to.shared.u64 t, %1; cvt.u32.u64 %0, t; }" : "=r"(a) : "l"(p));
    return a;
}
__device__ __forceinline__ uint32_t sw128(uint32_t o) { return o ^ ((o >> 3) & 0x70); }

__device__ __forceinline__ void ldsm4(uint32_t* r, uint32_t a) {
    asm volatile("ldmatrix.sync.aligned.m8n8.x4.shared.b16 {%0,%1,%2,%3}, [%4];"
                 : "=r"(r[0]), "=r"(r[1]), "=r"(r[2]), "=r"(r[3]) : "r"(a));
}
__device__ __forceinline__ void mma_f16(float* d, const uint32_t* a, const uint32_t* b) {
    asm volatile("mma.sync.aligned.m16n8k16.row.col.f32.f16.f16.f32 "
                 "{%0,%1,%2,%3}, {%4,%5,%6,%7}, {%8,%9}, {%0,%1,%2,%3};"
                 : "+f"(d[0]), "+f"(d[1]), "+f"(d[2]), "+f"(d[3])
                 : "r"(a[0]), "r"(a[1]), "r"(a[2]), "r"(a[3]), "r"(b[0]), "r"(b[1]));
}
#define CPA16(dst, src) asm volatile("cp.async.cg.shared.global [%0], [%1], 16;" :: "r"(dst), "l"(src))
#define CPA_COMMIT()    asm volatile("cp.async.commit_group;" ::: "memory")
#define CPA_WAIT0()     asm volatile("cp.async.wait_group 0;" ::: "memory")

// ---------------- preprocessing ----------------
__global__ void k_pre(const float* __restrict__ Wc, const float* __restrict__ Wi,
                      const float* __restrict__ We) {
    int t = blockIdx.x * blockDim.x + threadIdx.x;
    int nth = gridDim.x * blockDim.x;
    if (t < NNODES) g_cnt[t] = 0;
    if (t < NGRAPH * HIDN) g_pool[t] = 0.f;
    if (t < 122880) {
        int n = t / 320, k = t % 320;
        float v = (n < HIDN && k < 80) ? Wi[k * HIDN + n] : 0.f;
        g_WI[t] = __float2half(v);
    }
    if (t < 3 * 122880) {
        int l = t / 122880, r2 = t % 122880;
        int n = r2 / 320, k = r2 % 320;
        float v = (n < HIDN && k < HIDN) ? Wc[l * HIDN * HIDN + k * HIDN + n] : 0.f;
        g_W[t] = __float2half(v);
    }
    if (t < 384 * 384) {
        int n = t / 384, k = t % 384;
        float v = (n < HIDN && k < FNODE + HIDN) ? We[k * HIDN + n] : 0.f;
        g_WN[t] = __float2half(v);
    }
    // zero pad columns (300..319) of g_Af: 5 uint2 (4 halves) per edge
    for (int j = t; j < NEDGES * 5; j += nth) {
        int e = j / 5, q = j - e * 5;
        *reinterpret_cast<uint2*>(g_Af + (size_t)e * 320 + 300 + q * 4) = make_uint2(0u, 0u);
    }
}

__global__ void k_hist(const int* __restrict__ coli) {
    int e = blockIdx.x * blockDim.x + threadIdx.x;
    if (e < NEDGES) atomicAdd(&g_cnt[coli[e]], 1);
}

// fast single-block scan: 1024 threads x 20 elems, shuffle-based
__global__ void k_scan() {
    __shared__ int wsum[32];
    int tid = threadIdx.x;
    int lane = tid & 31, wid = tid >> 5;
    const int PER = 20;
    int base = tid * PER;
    int v[PER];
    int s = 0;
#pragma unroll
    for (int i = 0; i < PER; ++i) {
        int idx = base + i;
        v[i] = (idx < NNODES) ? g_cnt[idx] : 0;
        s += v[i];
    }
    int ws = s;
#pragma unroll
    for (int off = 1; off < 32; off <<= 1) {
        int t = __shfl_up_sync(0xffffffffu, ws, off);
        if (lane >= off) ws += t;
    }
    if (lane == 31) wsum[wid] = ws;
    __syncthreads();
    if (wid == 0) {
        int w = wsum[lane];
#pragma unroll
        for (int off = 1; off < 32; off <<= 1) {
            int t = __shfl_up_sync(0xffffffffu, w, off);
            if (lane >= off) w += t;
        }
        wsum[lane] = w;
    }
    __syncthreads();
    int warp_off = (wid > 0) ? wsum[wid - 1] : 0;
    int run = warp_off + ws - s;
#pragma unroll
    for (int i = 0; i < PER; ++i) {
        int idx = base + i;
        if (idx < NNODES) { g_ptr[idx] = run; g_fill[idx] = run; }
        run += v[i];
    }
    if (tid == 0) g_ptr[NNODES] = wsum[31];
}

__global__ void k_scatter(const int* __restrict__ coli) {
    int e = blockIdx.x * blockDim.x + threadIdx.x;
    if (e < NEDGES) {
        int pos = atomicAdd(&g_fill[coli[e]], 1);
        g_eid[pos] = e;
    }
}

// ---------------- segment sum: g_a[n] = sum t[e] (u2 only) ----------------
__global__ void k_segsum(int src_sel) {
    const __half* h = tbuf(src_sel);
    int t = blockIdx.x * blockDim.x + threadIdx.x;
    if (t >= NNODES * 75) return;
    int n = t / 75;
    int c = (t - n * 75) * 4;
    int beg = g_ptr[n], end = g_ptr[n + 1];
    float4 acc = make_float4(0.f, 0.f, 0.f, 0.f);
#pragma unroll 2
    for (int i = beg; i < end; ++i) {
        int e = g_eid[i];
        float4 vv = ld4h(h + (size_t)e * HIDN + c);
        acc.x += vv.x; acc.y += vv.y; acc.z += vv.z; acc.w += vv.w;
    }
    st4(g_a + n * HIDN + c, acc);
}

// ------ fused segsum + next-h materialize (paired-edge identity) --------
__global__ void k_seghm(int t_sel, const float* __restrict__ bc) {
    const __half* tp = tbuf(t_sel);
    int t = blockIdx.x * blockDim.x + threadIdx.x;
    if (t >= NNODES * 75) return;
    int n = t / 75;
    int c = (t - n * 75) * 4;
    float4 bv = ld4(bc + c);
    int beg = g_ptr[n], end = g_ptr[n + 1];
    float4 u = make_float4(0.f, 0.f, 0.f, 0.f);
#pragma unroll 2
    for (int i = beg; i < end; ++i) {
        int e = g_eid[i];
        float4 vv = ld4h(tp + (size_t)e * HIDN + c);
        u.x += vv.x; u.y += vv.y; u.z += vv.z; u.w += vv.w;
    }
#pragma unroll 2
    for (int i = beg; i < end; ++i) {
        int e = g_eid[i];
        int er = e ^ 1;
        float4 tv  = ld4h(tp + (size_t)e * HIDN + c);
        float4 h0v = ld4h(g_h0f + (size_t)er * 320 + c);
        float4 v;
        v.x = frelu(h0v.x + bv.x + u.x - tv.x);
        v.y = frelu(h0v.y + bv.y + u.y - tv.y);
        v.z = frelu(h0v.z + bv.z + u.z - tv.z);
        v.w = frelu(h0v.w + bv.w + u.w - tv.w);
        *reinterpret_cast<uint2*>(g_Af + (size_t)er * 320 + c) = pack4h(v);
    }
}

// --------- fused final: g_s[n] = sum_e relu(h0[e]+bc2+u2[row[e]]-rev(t2)) ----
__global__ void k_segsum_h3(int t2_sel, const float* __restrict__ bc2,
                            const int* __restrict__ rowi) {
    const __half* t2 = tbuf(t2_sel);
    int t = blockIdx.x * blockDim.x + threadIdx.x;
    if (t >= NNODES * 75) return;
    int n = t / 75;
    int c = (t - n * 75) * 4;
    float4 bv = ld4(bc2 + c);
    int beg = g_ptr[n], end = g_ptr[n + 1];
    float4 acc = make_float4(0.f, 0.f, 0.f, 0.f);
#pragma unroll 2
    for (int i = beg; i < end; ++i) {
        int e = g_eid[i];
        float4 h0v = ld4h(g_h0f + (size_t)e * 320 + c);
        float4 uv  = ld4(g_a + rowi[e] * HIDN + c);
        float4 tv  = ld4h(t2 + (size_t)(e ^ 1) * HIDN + c);
        acc.x += frelu(h0v.x + bv.x + uv.x - tv.x);
        acc.y += frelu(h0v.y + bv.y + uv.y - tv.y);
        acc.z += frelu(h0v.z + bv.z + uv.z - tv.z);
        acc.w += frelu(h0v.w + bv.w + uv.w - tv.w);
    }
    st4(g_s + n * HIDN + c, acc);
}

// =====================================================================
// Conv GEMM (fp16 single-pass, K-chunks of 128 as 2x64-col panels):
// t_out = A @ W. CTA 128m x 128n, 8 warps (4m x 2n), K=320 in 3 chunks
// {128,128,64}, SW128 per panel, cp.async commit+wait0, 2 CTAs/SM.
// smem: A 2x16K panels + B 2x16K panels = 64K.
// =====================================================================
#define TG_A   0
#define TG_B   32768
#define TG_TOTAL 65536

__global__ void __launch_bounds__(256, 2) k_cgemm(int layer, int a_sel, int out_sel) {
    extern __shared__ char smem[];
    uint32_t sb = smem_u32(smem);
    int tid = threadIdx.x;
    int lane = tid & 31;
    int wid = tid >> 5;
    int m0 = blockIdx.y * 128;
    int n0 = blockIdx.x * 128;

    const __half* W = g_W + layer * 122880;
    const __half* Ain = a_sel ? g_Af : g_h0f;
    __half* tout = tbuf(out_sel);

    int wm = wid >> 1, wn = wid & 1;
    int mat = lane >> 3, l7 = lane & 7;
    int a_row = wm * 32 + (mat & 1) * 8 + l7;
    int a_kof = (mat >> 1) * 8;
    int b_base = wn * 64 + (mat >> 1) * 8 + l7;
    int b_kof = (mat & 1) * 8;
    bool nact = (n0 + wn * 64) < HIDN;

    uint32_t a_soff[2][4], b_soff[4][4];
#pragma unroll
    for (int mt = 0; mt < 2; ++mt)
#pragma unroll
        for (int ks = 0; ks < 4; ++ks)
            a_soff[mt][ks] = sw128((uint32_t)(((a_row + mt * 16) << 7) +
                                              ((ks * 16 + a_kof) << 1)));
#pragma unroll
    for (int np = 0; np < 4; ++np)
#pragma unroll
        for (int ks = 0; ks < 4; ++ks)
            b_soff[np][ks] = sw128((uint32_t)(((b_base + np * 16) << 7) +
                                              ((ks * 16 + b_kof) << 1)));

    float acc[2][8][4];
#pragma unroll
    for (int i = 0; i < 2; i++)
#pragma unroll
        for (int j = 0; j < 8; j++)
#pragma unroll
            for (int q = 0; q < 4; q++) acc[i][j][q] = 0.f;

    for (int kc = 0; kc < 3; ++kc) {
        int k0 = kc * 128;
        int npan = (kc == 2) ? 1 : 2;     // chunk widths 128,128,64
        if (kc) __syncthreads();
        // loads: per panel 1024 x 16B split over 256 threads (4 iters)
        for (int s = 0; s < npan * 4; s++) {
            int j = tid + s * 256;
            int p  = j >> 10;             // panel
            int r2 = (j >> 3) & 127;
            int i  = j & 7;
            uint32_t off = (uint32_t)p * 16384 + sw128((uint32_t)(r2 * 128 + i * 16));
            int kg = k0 + p * 64 + i * 8;
            CPA16(sb + TG_A + off, Ain + (size_t)(m0 + r2) * 320 + kg);
            CPA16(sb + TG_B + off, W + (size_t)(n0 + r2) * 320 + kg);
        }
        CPA_COMMIT();
        CPA_WAIT0();
        __syncthreads();

        for (int ks8 = 0; ks8 < npan * 4; ++ks8) {
            uint32_t po = (uint32_t)(ks8 >> 2) * 16384;
            int ks = ks8 & 3;
            uint32_t af[2][4];
#pragma unroll
            for (int mt = 0; mt < 2; ++mt)
                ldsm4(af[mt], sb + TG_A + po + a_soff[mt][ks]);
            if (nact) {
#pragma unroll
                for (int np = 0; np < 4; ++np) {
                    uint32_t bf4[4];
                    ldsm4(bf4, sb + TG_B + po + b_soff[np][ks]);
#pragma unroll
                    for (int mt = 0; mt < 2; ++mt)
#pragma unroll
                        for (int h = 0; h < 2; ++h)
                            mma_f16(acc[mt][np * 2 + h], af[mt], bf4 + h * 2);
                }
            }
        }
    }

    int orow = m0 + wm * 32 + (lane >> 2);
    int oc0  = n0 + wn * 64 + (lane & 3) * 2;
#pragma unroll
    for (int mt = 0; mt < 2; ++mt)
#pragma unroll
        for (int nt = 0; nt < 8; ++nt) {
            int col = oc0 + nt * 8;
            if (col >= HIDN) continue;
#pragma unroll
            for (int h = 0; h < 2; ++h) {
                int row = orow + mt * 16 + h * 8;
                __half2 p = __floats2half2_rn(acc[mt][nt][h * 2], acc[mt][nt][h * 2 + 1]);
                *reinterpret_cast<__half2*>(tout + (size_t)row * HIDN + col) = p;
            }
        }
}

// =====================================================================
// Init GEMM: A = [x[row]|ea], K=80 -> 2 chunks of 64. -> g_h0f fp16.
// =====================================================================
__global__ void __launch_bounds__(256, 2) k_tginit(
    const int* __restrict__ rowi, const float* __restrict__ bvec,
    const float* __restrict__ x, const float* __restrict__ ea)
{
    extern __shared__ char smem[];
    uint32_t sb = smem_u32(smem);
    int tid = threadIdx.x;
    int lane = tid & 31;
    int wid = tid >> 5;
    int m0 = blockIdx.y * 128;
    int n0 = blockIdx.x * 128;

    int r = tid >> 1;
    int e = m0 + r;
    int cc0 = (tid & 1) * 32;
    int rv = rowi[e];

    int wm = wid >> 1, wn = wid & 1;
    int mat = lane >> 3, l7 = lane & 7;
    int a_row = wm * 32 + (mat & 1) * 8 + l7;
    int a_kof = (mat >> 1) * 8;
    int b_base = wn * 64 + (mat >> 1) * 8 + l7;
    int b_kof = (mat & 1) * 8;
    bool nact = (n0 + wn * 64) < HIDN;

    float acc[2][8][4];
#pragma unroll
    for (int i = 0; i < 2; i++)
#pragma unroll
        for (int j = 0; j < 8; j++)
#pragma unroll
            for (int q = 0; q < 4; q++) acc[i][j][q] = 0.f;

    for (int kc = 0; kc < 2; ++kc) {
        int k0 = kc * 64;
        if (kc) __syncthreads();
#pragma unroll
        for (int s = 0; s < 4; s++) {
            int j = tid + s * 256;
            int n = j >> 3, i = j & 7;
            uint32_t off = sw128((uint32_t)(n * 128 + i * 16));
            CPA16(sb + TG_B + off, g_WI + (n0 + n) * 320 + k0 + i * 8);
        }
        CPA_COMMIT();
#pragma unroll
        for (int i = 0; i < 8; i++) {
            int cc = cc0 + i * 4;
            int k = k0 + cc;
            float4 v = make_float4(0.f, 0.f, 0.f, 0.f);
            if (k < FNODE)    v = ld4(x + rv * FNODE + k);
            else if (k < 80)  v = ld4(ea + e * FEDGE + (k - FNODE));
            uint32_t off = sw128((uint32_t)(r * 128 + cc * 2));
            *reinterpret_cast<uint2*>(smem + TG_A + off) = pack4h(v);
        }
        CPA_WAIT0();
        __syncthreads();
#pragma unroll
        for (int ks = 0; ks < 4; ++ks) {
            uint32_t af[2][4];
#pragma unroll
            for (int mt = 0; mt < 2; ++mt) {
                uint32_t off = sw128((uint32_t)(((a_row + mt * 16) << 7) +
                                                ((ks * 16 + a_kof) << 1)));
                ldsm4(af[mt], sb + TG_A + off);
            }
            if (nact) {
#pragma unroll
                for (int np = 0; np < 4; ++np) {
                    uint32_t boff = sw128((uint32_t)(((b_base + np * 16) << 7) +
                                                     ((ks * 16 + b_kof) << 1)));
                    uint32_t bf4[4];
                    ldsm4(bf4, sb + TG_B + boff);
#pragma unroll
                    for (int mt = 0; mt < 2; ++mt)
#pragma unroll
                        for (int h = 0; h < 2; ++h)
                            mma_f16(acc[mt][np * 2 + h], af[mt], bf4 + h * 2);
                }
            }
        }
    }

    int orow = m0 + wm * 32 + (lane >> 2);
    int oc0  = n0 + wn * 64 + (lane & 3) * 2;
#pragma unroll
    for (int mt = 0; mt < 2; ++mt)
#pragma unroll
        for (int nt = 0; nt < 8; ++nt) {
            int col = oc0 + nt * 8;
            if (col >= 320) continue;
            bool live = col < HIDN;
            float b0 = live ? bvec[col] : 0.f;
            float b1 = live ? bvec[col + 1] : 0.f;
#pragma unroll
            for (int h = 0; h < 2; ++h) {
                int row = orow + mt * 16 + h * 8;
                float v0 = live ? frelu(acc[mt][nt][h * 2] + b0) : 0.f;
                float v1 = live ? frelu(acc[mt][nt][h * 2 + 1] + b1) : 0.f;
                __half2 p = __floats2half2_rn(v0, v1);
                *reinterpret_cast<__half2*>(g_h0f + (size_t)row * 320 + col) = p;
            }
        }
}

// =====================================================================
// Node GEMM: hn = relu([x|s] @ W_e2n + be); pool += hn
// =====================================================================
__global__ void __launch_bounds__(256, 2) k_tgnode(
    const int* __restrict__ batch, const float* __restrict__ bvec,
    const float* __restrict__ x)
{
    extern __shared__ char smem[];
    uint32_t sb = smem_u32(smem);
    int tid = threadIdx.x;
    int lane = tid & 31;
    int wid = tid >> 5;
    int m0 = blockIdx.y * 128;
    int n0 = blockIdx.x * 128;

    int r = tid >> 1;
    int e = m0 + r;
    bool eok = (e < NNODES);
    int es = eok ? e : 0;
    int cc0 = (tid & 1) * 32;

    int wm = wid >> 1, wn = wid & 1;
    int mat = lane >> 3, l7 = lane & 7;
    int a_row = wm * 32 + (mat & 1) * 8 + l7;
    int a_kof = (mat >> 1) * 8;
    int b_base = wn * 64 + (mat >> 1) * 8 + l7;
    int b_kof = (mat & 1) * 8;
    bool nact = (n0 + wn * 64) < HIDN;

    const int KTOT = FNODE + HIDN;  // 364

    float acc[2][8][4];
#pragma unroll
    for (int i = 0; i < 2; i++)
#pragma unroll
        for (int j = 0; j < 8; j++)
#pragma unroll
            for (int q = 0; q < 4; q++) acc[i][j][q] = 0.f;

    for (int kc = 0; kc < 6; ++kc) {
        int k0 = kc * 64;
        if (kc) __syncthreads();
#pragma unroll
        for (int s = 0; s < 4; s++) {
            int j = tid + s * 256;
            int n = j >> 3, i = j & 7;
            uint32_t off = sw128((uint32_t)(n * 128 + i * 16));
            CPA16(sb + TG_B + off, g_WN + (n0 + n) * 384 + k0 + i * 8);
        }
        CPA_COMMIT();
#pragma unroll
        for (int i = 0; i < 8; i++) {
            int cc = cc0 + i * 4;
            int k = k0 + cc;
            float4 v = make_float4(0.f, 0.f, 0.f, 0.f);
            if (eok && k < KTOT)
                v = (k < FNODE) ? ld4(x + es * FNODE + k)
                                : ld4(g_s + es * HIDN + (k - FNODE));
            uint32_t off = sw128((uint32_t)(r * 128 + cc * 2));
            *reinterpret_cast<uint2*>(smem + TG_A + off) = pack4h(v);
        }
        CPA_WAIT0();
        __syncthreads();
#pragma unroll
        for (int ks = 0; ks < 4; ++ks) {
            uint32_t af[2][4];
#pragma unroll
            for (int mt = 0; mt < 2; ++mt) {
                uint32_t off = sw128((uint32_t)(((a_row + mt * 16) << 7) +
                                                ((ks * 16 + a_kof) << 1)));
                ldsm4(af[mt], sb + TG_A + off);
            }
            if (nact) {
#pragma unroll
                for (int np = 0; np < 4; ++np) {
                    uint32_t boff = sw128((uint32_t)(((b_base + np * 16) << 7) +
                                                     ((ks * 16 + b_kof) << 1)));
                    uint32_t bf4[4];
                    ldsm4(bf4, sb + TG_B + boff);
#pragma unroll
                    for (int mt = 0; mt < 2; ++mt)
#pragma unroll
                        for (int h = 0; h < 2; ++h)
                            mma_f16(acc[mt][np * 2 + h], af[mt], bf4 + h * 2);
                }
            }
        }
    }

    int orow = m0 + wm * 32 + (lane >> 2);
    int oc0  = n0 + wn * 64 + (lane & 3) * 2;
#pragma unroll
    for (int mt = 0; mt < 2; ++mt)
#pragma unroll
        for (int nt = 0; nt < 8; ++nt) {
            int col = oc0 + nt * 8;
            if (col >= HIDN) continue;
            float b0 = bvec[col], b1 = bvec[col + 1];
#pragma unroll
            for (int h = 0; h < 2; ++h) {
                int row = orow + mt * 16 + h * 8;
                if (row >= NNODES) continue;
                float* p = g_pool + batch[row] * HIDN + col;
                atomicAdd(p + 0, frelu(acc[mt][nt][h * 2] + b0));
                atomicAdd(p + 1, frelu(acc[mt][nt][h * 2 + 1] + b1));
            }
        }
}

// ---------------- FFN ----------------
__global__ void k_ffn(const float* __restrict__ Wf, const float* __restrict__ bf,
                      float* __restrict__ out) {
    int g = blockIdx.x;
    int lane = threadIdx.x;
    float s = 0.f;
    for (int k = lane; k < HIDN; k += 32) s += g_pool[g * HIDN + k] * Wf[k];
#pragma unroll
    for (int o = 16; o; o >>= 1) s += __shfl_xor_sync(0xffffffffu, s, o);
    if (lane == 0) out[g] = s + bf[0];
}

// ---------------- entry ----------------
extern "C" void kernel_launch(void* const* d_in, const int* in_sizes, int n_in,
                              void* d_out, int out_size) {
    const float* x     = (const float*)d_in[0];
    const float* ea    = (const float*)d_in[1];
    const int*   ei    = (const int*)d_in[2];
    const int*   rowi  = ei;
    const int*   coli  = ei + NEDGES;
    const int*   batch = (const int*)d_in[3];
    const float* Wi    = (const float*)d_in[4];
    const float* bi    = (const float*)d_in[5];
    const float* Wc    = (const float*)d_in[6];
    const float* bc    = (const float*)d_in[7];
    const float* We    = (const float*)d_in[8];
    const float* be    = (const float*)d_in[9];
    const float* Wf    = (const float*)d_in[10];
    const float* bf    = (const float*)d_in[11];
    float* out = (float*)d_out;

    cudaFuncSetAttribute(k_cgemm,  cudaFuncAttributeMaxDynamicSharedMemorySize, TG_TOTAL);
    cudaFuncSetAttribute(k_tginit, cudaFuncAttributeMaxDynamicSharedMemorySize, TG_TOTAL);
    cudaFuncSetAttribute(k_tgnode, cudaFuncAttributeMaxDynamicSharedMemorySize, TG_TOTAL);

    dim3 gT(3, NEDGES / 128);
    dim3 gN(3, (NNODES + 127) / 128);
    int ssB = (NNODES * 75 + 255) / 256;

    k_pre<<<1440, 256>>>(Wc, Wi, We);                    // 1
    k_hist<<<NEDGES / 256, 256>>>(coli);                 // 2
    k_tginit<<<gT, 256, TG_TOTAL>>>(rowi, bi, x, ea);    // 3: h0 fp16 (= layer-0 A)
    k_cgemm<<<gT, 256, TG_TOTAL>>>(0, 0, 0);             // 4: t0 -> tA  <- profiled
    k_scan<<<1, 1024>>>();                               // 5
    k_scatter<<<NEDGES / 256, 256>>>(coli);              // 6

    k_seghm<<<ssB, 256>>>(0, bc);                        // u0 (regs) + A = h1 fp16
    k_cgemm<<<gT, 256, TG_TOTAL>>>(1, 1, 1);             // t1 -> tB
    k_seghm<<<ssB, 256>>>(1, bc + HIDN);                 // u1 (regs) + A = h2 fp16
    k_cgemm<<<gT, 256, TG_TOTAL>>>(2, 1, 0);             // t2 -> tA
    k_segsum<<<ssB, 256>>>(0);                           // u2 -> g_a
    k_segsum_h3<<<ssB, 256>>>(0, bc + 2 * HIDN, rowi);   // s (fused h3+segsum)

    k_tgnode<<<gN, 256, TG_TOTAL>>>(batch, be, x);       // node GEMM + pool
    k_ffn<<<NGRAPH, 32>>>(Wf, bf, out);
}